// round 2
// baseline (speedup 1.0000x reference)
#include <cuda_runtime.h>
#include <cuda_bf16.h>
#include <math.h>

// Problem constants
#define BB 4
#define SS 1024
#define EE 512
#define HH 512
#define VV 32000
#define MM (BB*SS)      // 4096
#define NH 8
#define DH 64

// ---------------- scratch (static device memory; no allocations) ----------------
__device__ float g_h[MM*HH];          // activations
__device__ float g_I[MM*HH];          // liquid input currents
__device__ float g_s[MM*HH];          // scan output (tanh'd)
__device__ float g_qkv[MM*3*HH];      // qkv projections
__device__ float g_att[MM*HH];        // attention output (pre out-proj)
__device__ float g_h2[MM*HH];         // post out-proj
__device__ float g_scores[32*1024*1024]; // [bh][q][k] fp32 (134 MB)

// ---------------- embed + positional encoding ----------------
__global__ void embed_pe_kernel(const int* __restrict__ x, const float* __restrict__ emb,
                                float* __restrict__ out) {
    int idx = blockIdx.x * blockDim.x + threadIdx.x;
    if (idx >= MM*EE) return;
    int m = idx >> 9;           // row (b*S + s)
    int e = idx & 511;          // feature
    int s = m & (SS - 1);
    int tok = x[m];
    int i2 = e & ~1;
    // div = exp(-(2i) * ln(10000)/512)
    float freq = expf((float)i2 * (-9.210340371976184f / 512.0f));
    float ang = (float)s * freq;
    float pe = (e & 1) ? cosf(ang) : sinf(ang);
    out[idx] = emb[(size_t)tok * EE + e] + pe;
}

// ---------------- generic SGEMM: C[M,N] = A[M,K] @ B[N,K]^T + bias[N] ----------------
// BM=BN=128, BK=8, 256 threads, 8x8 per thread. All dims divisible (M=4096, K=512,
// N in {512,1536,32000}).
__global__ __launch_bounds__(256) void sgemm_nt(const float* __restrict__ A,
                                                const float* __restrict__ B,
                                                const float* __restrict__ bias,
                                                float* __restrict__ C,
                                                int M, int N, int K) {
    __shared__ float As[8][128];
    __shared__ float Bs[8][128];
    const int tid = threadIdx.x;
    const int bm = blockIdx.y * 128;
    const int bn = blockIdx.x * 128;
    const int tx = tid & 15;     // 16 col-groups of 8
    const int ty = tid >> 4;     // 16 row-groups of 8

    float acc[8][8];
    #pragma unroll
    for (int i = 0; i < 8; i++)
        #pragma unroll
        for (int j = 0; j < 8; j++) acc[i][j] = 0.f;

    const int lrow = tid >> 1;          // 0..127
    const int lcol = (tid & 1) * 4;     // 0 or 4
    const float* Ab = A + (size_t)(bm + lrow) * K + lcol;
    const float* Bb = B + (size_t)(bn + lrow) * K + lcol;

    for (int k0 = 0; k0 < K; k0 += 8) {
        float4 av = *(const float4*)(Ab + k0);
        float4 bv = *(const float4*)(Bb + k0);
        As[lcol+0][lrow] = av.x; As[lcol+1][lrow] = av.y;
        As[lcol+2][lrow] = av.z; As[lcol+3][lrow] = av.w;
        Bs[lcol+0][lrow] = bv.x; Bs[lcol+1][lrow] = bv.y;
        Bs[lcol+2][lrow] = bv.z; Bs[lcol+3][lrow] = bv.w;
        __syncthreads();
        #pragma unroll
        for (int k = 0; k < 8; k++) {
            float4 a0 = *(const float4*)&As[k][ty*8];
            float4 a1 = *(const float4*)&As[k][ty*8+4];
            float4 b0 = *(const float4*)&Bs[k][tx*8];
            float4 b1 = *(const float4*)&Bs[k][tx*8+4];
            float ra[8] = {a0.x,a0.y,a0.z,a0.w,a1.x,a1.y,a1.z,a1.w};
            float rb[8] = {b0.x,b0.y,b0.z,b0.w,b1.x,b1.y,b1.z,b1.w};
            #pragma unroll
            for (int i = 0; i < 8; i++)
                #pragma unroll
                for (int j = 0; j < 8; j++)
                    acc[i][j] += ra[i] * rb[j];
        }
        __syncthreads();
    }

    // epilogue with bias
    float bi[8];
    #pragma unroll
    for (int j = 0; j < 8; j++) bi[j] = bias[bn + tx*8 + j];
    #pragma unroll
    for (int i = 0; i < 8; i++) {
        int row = bm + ty*8 + i;
        float* Crow = C + (size_t)row * N + bn + tx*8;
        float4 v0 = make_float4(acc[i][0]+bi[0], acc[i][1]+bi[1], acc[i][2]+bi[2], acc[i][3]+bi[3]);
        float4 v1 = make_float4(acc[i][4]+bi[4], acc[i][5]+bi[5], acc[i][6]+bi[6], acc[i][7]+bi[7]);
        *(float4*)(Crow)     = v0;
        *(float4*)(Crow + 4) = v1;
    }
}

// ---------------- liquid sequential scan (per (b,o) lane) ----------------
__global__ void liquid_scan_kernel(const float* __restrict__ I, const float* __restrict__ tau,
                                   const float* __restrict__ log_dt, float* __restrict__ out) {
    int b = blockIdx.x;          // 0..3
    int o = threadIdx.x;         // 0..511
    float dt = expf(log_dt[0]);
    float r = dt / tau[o];
    float u = 0.f, s = 0.f;
    const float* Ib = I + (size_t)b * SS * HH + o;
    float* Ob = out + (size_t)b * SS * HH + o;
    float nextI = Ib[0];
    for (int t = 0; t < SS; t++) {
        float It = nextI;
        if (t + 1 < SS) nextI = Ib[(size_t)(t+1) * HH];
        float sn = s + r * (u - s);   // uses OLD u
        u = u + r * (It - u);
        s = sn;
        Ob[(size_t)t * HH] = tanhf(s);
    }
}

// ---------------- layernorm over H=512 ----------------
__global__ void layernorm_kernel(const float* __restrict__ in, const float* __restrict__ g,
                                 const float* __restrict__ be, float* __restrict__ out) {
    int row = blockIdx.x;
    int tid = threadIdx.x;   // 256
    const float* p = in + (size_t)row * HH;
    float a = p[tid], b = p[tid + 256];
    float sum = a + b, sq = a*a + b*b;
    __shared__ float s1[8], s2[8];
    #pragma unroll
    for (int o = 16; o; o >>= 1) {
        sum += __shfl_xor_sync(0xffffffffu, sum, o);
        sq  += __shfl_xor_sync(0xffffffffu, sq,  o);
    }
    if ((tid & 31) == 0) { s1[tid>>5] = sum; s2[tid>>5] = sq; }
    __syncthreads();
    sum = 0.f; sq = 0.f;
    #pragma unroll
    for (int i = 0; i < 8; i++) { sum += s1[i]; sq += s2[i]; }
    float mean = sum * (1.f/512.f);
    float var  = sq * (1.f/512.f) - mean*mean;
    float inv = rsqrtf(var + 1e-5f);
    float* q = out + (size_t)row * HH;
    q[tid]       = (a - mean) * inv * g[tid]       + be[tid];
    q[tid + 256] = (b - mean) * inv * g[tid + 256] + be[tid + 256];
}

// ---------------- attention scores: scores[bh][q][k] = Q.K/8 ----------------
__global__ __launch_bounds__(256) void attn_scores_kernel(const float* __restrict__ qkv,
                                                           float* __restrict__ scores) {
    int bh = blockIdx.z; int b = bh >> 3, h = bh & 7;
    int q0 = blockIdx.y * 64, k0 = blockIdx.x * 64;
    __shared__ float Qs[64][65];   // [d][q]
    __shared__ float Ks[64][65];   // [d][k]
    int tid = threadIdx.x;
    int tx = tid & 15, ty = tid >> 4;

    #pragma unroll
    for (int l = 0; l < 4; l++) {
        int r  = (tid >> 4) + l * 16;   // 0..63
        int c4 = (tid & 15) * 4;        // 0..60
        float4 qv = *(const float4*)(qkv + (size_t)(b*SS + q0 + r)*1536 + h*DH + c4);
        Qs[c4+0][r]=qv.x; Qs[c4+1][r]=qv.y; Qs[c4+2][r]=qv.z; Qs[c4+3][r]=qv.w;
        float4 kv = *(const float4*)(qkv + (size_t)(b*SS + k0 + r)*1536 + 512 + h*DH + c4);
        Ks[c4+0][r]=kv.x; Ks[c4+1][r]=kv.y; Ks[c4+2][r]=kv.z; Ks[c4+3][r]=kv.w;
    }
    __syncthreads();

    float acc[4][4];
    #pragma unroll
    for (int i=0;i<4;i++)
        #pragma unroll
        for (int j=0;j<4;j++) acc[i][j]=0.f;

    #pragma unroll
    for (int d = 0; d < 64; d++) {
        float ra[4], rb[4];
        #pragma unroll
        for (int i=0;i<4;i++) ra[i] = Qs[d][ty*4+i];
        #pragma unroll
        for (int j=0;j<4;j++) rb[j] = Ks[d][tx*4+j];
        #pragma unroll
        for (int i=0;i<4;i++)
            #pragma unroll
            for (int j=0;j<4;j++) acc[i][j] += ra[i]*rb[j];
    }

    size_t base = ((size_t)bh << 20);
    #pragma unroll
    for (int i = 0; i < 4; i++) {
        float4 v = make_float4(acc[i][0]*0.125f, acc[i][1]*0.125f,
                               acc[i][2]*0.125f, acc[i][3]*0.125f);
        *(float4*)(scores + base + (size_t)(q0 + ty*4 + i)*1024 + k0 + tx*4) = v;
    }
}

// ---------------- softmax over rows of 1024 ----------------
__global__ void softmax_kernel(float* __restrict__ scores) {
    size_t row = blockIdx.x;
    float* p = scores + row * 1024;
    int tid = threadIdx.x;   // 256
    float4 v = ((float4*)p)[tid];
    float m = fmaxf(fmaxf(v.x, v.y), fmaxf(v.z, v.w));
    __shared__ float red[8];
    #pragma unroll
    for (int o = 16; o; o >>= 1) m = fmaxf(m, __shfl_xor_sync(0xffffffffu, m, o));
    if ((tid & 31) == 0) red[tid>>5] = m;
    __syncthreads();
    m = red[0];
    #pragma unroll
    for (int i = 1; i < 8; i++) m = fmaxf(m, red[i]);
    v.x = __expf(v.x - m); v.y = __expf(v.y - m);
    v.z = __expf(v.z - m); v.w = __expf(v.w - m);
    float s = v.x + v.y + v.z + v.w;
    #pragma unroll
    for (int o = 16; o; o >>= 1) s += __shfl_xor_sync(0xffffffffu, s, o);
    __syncthreads();
    if ((tid & 31) == 0) red[tid>>5] = s;
    __syncthreads();
    s = 0.f;
    #pragma unroll
    for (int i = 0; i < 8; i++) s += red[i];
    float inv = 1.f / s;
    v.x *= inv; v.y *= inv; v.z *= inv; v.w *= inv;
    ((float4*)p)[tid] = v;
}

// ---------------- attention AV: out[bh][q][d] = P @ V ----------------
__global__ __launch_bounds__(256) void attn_av_kernel(const float* __restrict__ scores,
                                                       const float* __restrict__ qkv,
                                                       float* __restrict__ out) {
    int bh = blockIdx.y; int b = bh >> 3, h = bh & 7;
    int q0 = blockIdx.x * 64;
    __shared__ float Ps[64][65];   // [k][q]
    __shared__ float Vs[64][64];   // [k][d]
    int tid = threadIdx.x;
    int tx = tid & 15, ty = tid >> 4;

    float acc[4][4];
    #pragma unroll
    for (int i=0;i<4;i++)
        #pragma unroll
        for (int j=0;j<4;j++) acc[i][j]=0.f;

    size_t sbase = ((size_t)bh << 20);
    for (int k0 = 0; k0 < 1024; k0 += 64) {
        #pragma unroll
        for (int l = 0; l < 4; l++) {
            int r  = (tid >> 4) + l * 16;  // 0..63
            int c4 = (tid & 15) * 4;
            float4 pv = *(const float4*)(scores + sbase + (size_t)(q0 + r)*1024 + k0 + c4);
            Ps[c4+0][r]=pv.x; Ps[c4+1][r]=pv.y; Ps[c4+2][r]=pv.z; Ps[c4+3][r]=pv.w;
            float4 vv = *(const float4*)(qkv + (size_t)(b*SS + k0 + r)*1536 + 1024 + h*DH + c4);
            *(float4*)&Vs[r][c4] = vv;
        }
        __syncthreads();
        #pragma unroll
        for (int k = 0; k < 64; k++) {
            float ra[4], rb[4];
            #pragma unroll
            for (int i=0;i<4;i++) ra[i] = Ps[k][ty*4+i];
            #pragma unroll
            for (int j=0;j<4;j++) rb[j] = Vs[k][tx*4+j];
            #pragma unroll
            for (int i=0;i<4;i++)
                #pragma unroll
                for (int j=0;j<4;j++) acc[i][j] += ra[i]*rb[j];
        }
        __syncthreads();
    }

    #pragma unroll
    for (int i = 0; i < 4; i++) {
        float4 v = make_float4(acc[i][0], acc[i][1], acc[i][2], acc[i][3]);
        *(float4*)(out + (size_t)(b*SS + q0 + ty*4 + i)*HH + h*DH + tx*4) = v;
    }
}

// ---------------- host orchestration ----------------
static void sgemm(const float* A, const float* B, const float* bias, float* C,
                  int M, int N, int K) {
    dim3 grid(N / 128, M / 128);
    sgemm_nt<<<grid, 256>>>(A, B, bias, C, M, N, K);
}

extern "C" void kernel_launch(void* const* d_in, const int* in_sizes, int n_in,
                              void* d_out, int out_size) {
    const int*   x          = (const int*)  d_in[0];
    const float* emb        = (const float*)d_in[1];
    const float* W0         = (const float*)d_in[2];
    const float* b0         = (const float*)d_in[3];
    const float* tau0       = (const float*)d_in[4];
    const float* g0         = (const float*)d_in[5];
    const float* be0        = (const float*)d_in[6];
    const float* W1         = (const float*)d_in[7];
    const float* b1         = (const float*)d_in[8];
    const float* tau1       = (const float*)d_in[9];
    const float* g1         = (const float*)d_in[10];
    const float* be1        = (const float*)d_in[11];
    const float* attn_in_w  = (const float*)d_in[12];
    const float* attn_in_b  = (const float*)d_in[13];
    const float* attn_out_w = (const float*)d_in[14];
    const float* attn_out_b = (const float*)d_in[15];
    const float* out_w      = (const float*)d_in[16];
    const float* out_b      = (const float*)d_in[17];
    const float* log_dt     = (const float*)d_in[18];
    float* out = (float*)d_out;

    float *h, *I, *sbuf, *qkv, *att, *h2, *scores;
    cudaGetSymbolAddress((void**)&h,      g_h);
    cudaGetSymbolAddress((void**)&I,      g_I);
    cudaGetSymbolAddress((void**)&sbuf,   g_s);
    cudaGetSymbolAddress((void**)&qkv,    g_qkv);
    cudaGetSymbolAddress((void**)&att,    g_att);
    cudaGetSymbolAddress((void**)&h2,     g_h2);
    cudaGetSymbolAddress((void**)&scores, g_scores);

    // 1. embedding + positional encoding -> h [4096,512]
    embed_pe_kernel<<<(MM*EE)/256, 256>>>(x, emb, h);

    // 2. liquid layer 0
    sgemm(h, W0, b0, I, MM, HH, EE);
    liquid_scan_kernel<<<BB, HH>>>(I, tau0, log_dt, sbuf);
    layernorm_kernel<<<MM, 256>>>(sbuf, g0, be0, h);

    // 3. liquid layer 1
    sgemm(h, W1, b1, I, MM, HH, HH);
    liquid_scan_kernel<<<BB, HH>>>(I, tau1, log_dt, sbuf);
    layernorm_kernel<<<MM, 256>>>(sbuf, g1, be1, h);

    // 4. MHA
    sgemm(h, attn_in_w, attn_in_b, qkv, MM, 3*HH, HH);
    attn_scores_kernel<<<dim3(16, 16, 32), 256>>>(qkv, scores);
    softmax_kernel<<<32*1024, 256>>>(scores);
    attn_av_kernel<<<dim3(16, 32), 256>>>(scores, qkv, att);
    sgemm(att, attn_out_w, attn_out_b, h2, MM, HH, HH);

    // 5. vocab projection -> out [4096, 32000]
    sgemm(h2, out_w, out_b, out, MM, VV, HH);
}

// round 4
// speedup vs baseline: 1.7546x; 1.7546x over previous
#include <cuda_runtime.h>
#include <cuda_bf16.h>
#include <cstdint>
#include <math.h>

// Problem constants
#define BB 4
#define SS 1024
#define EE 512
#define HH 512
#define VV 32000
#define MM (BB*SS)      // 4096
#define NH 8
#define DH 64

// ---------------- scratch (static device memory; no allocations) ----------------
__device__ float g_h[MM*HH];
__device__ float g_I[MM*HH];
__device__ float g_s[MM*HH];
__device__ float g_qkv[MM*3*HH];
__device__ float g_att[MM*HH];
__device__ float g_h2[MM*HH];
__device__ float g_scores[32*1024*1024];
// bf16 split buffers for tensor-core vocab GEMM
__device__ __nv_bfloat16 g_Ahi[MM*HH];
__device__ __nv_bfloat16 g_Alo[MM*HH];
__device__ __nv_bfloat16 g_Bhi[(size_t)VV*HH];
__device__ __nv_bfloat16 g_Blo[(size_t)VV*HH];

__device__ __forceinline__ uint32_t smem_u32(const void* p) {
    uint32_t a;
    asm("{ .reg .u64 t; cvta.to.shared.u64 t, %1; cvt.u32.u64 %0, t; }" : "=r"(a) : "l"(p));
    return a;
}
__device__ __forceinline__ void cp_async16(uint32_t dst, const void* src) {
    asm volatile("cp.async.cg.shared.global [%0], [%1], 16;" :: "r"(dst), "l"(src));
}
__device__ __forceinline__ void ldsm_x4(uint32_t& r0, uint32_t& r1, uint32_t& r2, uint32_t& r3,
                                        uint32_t addr) {
    asm volatile("ldmatrix.sync.aligned.m8n8.x4.shared.b16 {%0,%1,%2,%3}, [%4];"
                 : "=r"(r0), "=r"(r1), "=r"(r2), "=r"(r3) : "r"(addr));
}
__device__ __forceinline__ void mma16816(float* c, const uint32_t* a, const uint32_t* b) {
    asm volatile("mma.sync.aligned.m16n8k16.row.col.f32.bf16.bf16.f32 "
                 "{%0,%1,%2,%3}, {%4,%5,%6,%7}, {%8,%9}, {%0,%1,%2,%3};"
                 : "+f"(c[0]), "+f"(c[1]), "+f"(c[2]), "+f"(c[3])
                 : "r"(a[0]), "r"(a[1]), "r"(a[2]), "r"(a[3]), "r"(b[0]), "r"(b[1]));
}

// ---------------- embed + positional encoding ----------------
__global__ void embed_pe_kernel(const int* __restrict__ x, const float* __restrict__ emb,
                                float* __restrict__ out) {
    int idx = blockIdx.x * blockDim.x + threadIdx.x;
    if (idx >= MM*EE) return;
    int m = idx >> 9;
    int e = idx & 511;
    int s = m & (SS - 1);
    int tok = x[m];
    int i2 = e & ~1;
    float freq = expf((float)i2 * (-9.210340371976184f / 512.0f));
    float ang = (float)s * freq;
    float pe = (e & 1) ? cosf(ang) : sinf(ang);
    out[idx] = emb[(size_t)tok * EE + e] + pe;
}

// ---------------- fp32 SGEMM (small GEMMs) ----------------
__global__ __launch_bounds__(256) void sgemm_nt(const float* __restrict__ A,
                                                const float* __restrict__ B,
                                                const float* __restrict__ bias,
                                                float* __restrict__ C,
                                                int M, int N, int K) {
    __shared__ float As[8][128];
    __shared__ float Bs[8][128];
    const int tid = threadIdx.x;
    const int bm = blockIdx.y * 128;
    const int bn = blockIdx.x * 128;
    const int tx = tid & 15;
    const int ty = tid >> 4;

    float acc[8][8];
    #pragma unroll
    for (int i = 0; i < 8; i++)
        #pragma unroll
        for (int j = 0; j < 8; j++) acc[i][j] = 0.f;

    const int lrow = tid >> 1;
    const int lcol = (tid & 1) * 4;
    const float* Ab = A + (size_t)(bm + lrow) * K + lcol;
    const float* Bb = B + (size_t)(bn + lrow) * K + lcol;

    for (int k0 = 0; k0 < K; k0 += 8) {
        float4 av = *(const float4*)(Ab + k0);
        float4 bv = *(const float4*)(Bb + k0);
        As[lcol+0][lrow] = av.x; As[lcol+1][lrow] = av.y;
        As[lcol+2][lrow] = av.z; As[lcol+3][lrow] = av.w;
        Bs[lcol+0][lrow] = bv.x; Bs[lcol+1][lrow] = bv.y;
        Bs[lcol+2][lrow] = bv.z; Bs[lcol+3][lrow] = bv.w;
        __syncthreads();
        #pragma unroll
        for (int k = 0; k < 8; k++) {
            float4 a0 = *(const float4*)&As[k][ty*8];
            float4 a1 = *(const float4*)&As[k][ty*8+4];
            float4 b0 = *(const float4*)&Bs[k][tx*8];
            float4 b1 = *(const float4*)&Bs[k][tx*8+4];
            float ra[8] = {a0.x,a0.y,a0.z,a0.w,a1.x,a1.y,a1.z,a1.w};
            float rb[8] = {b0.x,b0.y,b0.z,b0.w,b1.x,b1.y,b1.z,b1.w};
            #pragma unroll
            for (int i = 0; i < 8; i++)
                #pragma unroll
                for (int j = 0; j < 8; j++)
                    acc[i][j] += ra[i] * rb[j];
        }
        __syncthreads();
    }

    float bi[8];
    #pragma unroll
    for (int j = 0; j < 8; j++) bi[j] = bias[bn + tx*8 + j];
    #pragma unroll
    for (int i = 0; i < 8; i++) {
        int row = bm + ty*8 + i;
        float* Crow = C + (size_t)row * N + bn + tx*8;
        float4 v0 = make_float4(acc[i][0]+bi[0], acc[i][1]+bi[1], acc[i][2]+bi[2], acc[i][3]+bi[3]);
        float4 v1 = make_float4(acc[i][4]+bi[4], acc[i][5]+bi[5], acc[i][6]+bi[6], acc[i][7]+bi[7]);
        *(float4*)(Crow)     = v0;
        *(float4*)(Crow + 4) = v1;
    }
}

// ---------------- bf16 hi/lo split ----------------
__global__ void split_bf16_kernel(const float* __restrict__ in, __nv_bfloat16* __restrict__ hi,
                                  __nv_bfloat16* __restrict__ lo, int n) {
    int i = blockIdx.x * blockDim.x + threadIdx.x;
    if (i >= n) return;
    float x = in[i];
    __nv_bfloat16 h = __float2bfloat16(x);
    hi[i] = h;
    lo[i] = __float2bfloat16(x - __bfloat162float(h));
}

// ============== vocab GEMM via mma.sync bf16 split-precision ==============
// C[M,N] = A[M,512] @ B[N,512]^T + bias, via Ahi*Bhi + Ahi*Blo + Alo*Bhi.
// Effective K = 1536, BK=32 per stage, 48 stages, cp.async double buffer.
// 256 threads = 8 warps as 2(m) x 4(n); warp tile 64x32; 16x m16n8k16 per k16.
#define SPAD 40   // 32 + 8 bf16 padding

__global__ __launch_bounds__(256, 2) void gemm_vocab_mma(
    const __nv_bfloat16* __restrict__ Ahi, const __nv_bfloat16* __restrict__ Alo,
    const __nv_bfloat16* __restrict__ Bhi, const __nv_bfloat16* __restrict__ Blo,
    const float* __restrict__ bias, float* __restrict__ C)
{
    __shared__ __nv_bfloat16 As[2][128*SPAD];
    __shared__ __nv_bfloat16 Bs[2][128*SPAD];

    const int tid = threadIdx.x;
    const int lane = tid & 31;
    const int wid = tid >> 5;
    const int warp_m = wid >> 2;      // 0..1
    const int warp_n = wid & 3;       // 0..3
    const int bm = blockIdx.y * 128;
    const int bn = blockIdx.x * 128;

    const __nv_bfloat16* segA[3] = { Ahi, Ahi, Alo };
    const __nv_bfloat16* segB[3] = { Bhi, Blo, Bhi };

    const uint32_t sA = smem_u32(As);
    const uint32_t sB = smem_u32(Bs);

    float acc[4][4][4];
    #pragma unroll
    for (int i = 0; i < 4; i++)
        #pragma unroll
        for (int j = 0; j < 4; j++)
            #pragma unroll
            for (int r = 0; r < 4; r++) acc[i][j][r] = 0.f;

    const int lrow = tid >> 2;          // 0..63
    const int lcol = (tid & 3) * 8;     // 0,8,16,24

    // prefetch stage s into buffer s&1
    auto prefetch = [&](int s) {
        int gk = s * 32;
        int seg = gk >> 9;
        int kk = gk & 511;
        const __nv_bfloat16* Ap = segA[seg] + (size_t)bm * 512 + kk + lcol;
        const __nv_bfloat16* Bp = segB[seg] + (size_t)bn * 512 + kk + lcol;
        int buf = s & 1;
        #pragma unroll
        for (int c = 0; c < 2; c++) {
            int row = lrow + c * 64;
            cp_async16(sA + (uint32_t)(buf * (128*SPAD) + row * SPAD + lcol) * 2,
                       Ap + (size_t)row * 512);
            cp_async16(sB + (uint32_t)(buf * (128*SPAD) + row * SPAD + lcol) * 2,
                       Bp + (size_t)row * 512);
        }
    };

    prefetch(0);
    asm volatile("cp.async.commit_group;");

    for (int s = 0; s < 48; s++) {
        if (s < 47) {
            prefetch(s + 1);
            asm volatile("cp.async.commit_group;");
            asm volatile("cp.async.wait_group 1;");
        } else {
            asm volatile("cp.async.wait_group 0;");
        }
        __syncthreads();

        const uint32_t bufA = sA + (uint32_t)((s & 1) * (128*SPAD)) * 2;
        const uint32_t bufB = sB + (uint32_t)((s & 1) * (128*SPAD)) * 2;
        const int q  = lane >> 3;      // 0..3
        const int rr = lane & 7;       // 0..7

        #pragma unroll
        for (int ko = 0; ko < 32; ko += 16) {
            uint32_t a[4][4];
            #pragma unroll
            for (int i = 0; i < 4; i++) {
                int m0 = warp_m * 64 + i * 16;
                int row = m0 + (q & 1) * 8 + rr;
                int col = ko + (q >> 1) * 8;
                ldsm_x4(a[i][0], a[i][1], a[i][2], a[i][3],
                        bufA + (uint32_t)(row * SPAD + col) * 2);
            }
            uint32_t b[4][2];
            #pragma unroll
            for (int j = 0; j < 2; j++) {
                int n0 = warp_n * 32 + j * 16;
                int row = n0 + (q >> 1) * 8 + rr;
                int col = ko + (q & 1) * 8;
                ldsm_x4(b[2*j][0], b[2*j][1], b[2*j+1][0], b[2*j+1][1],
                        bufB + (uint32_t)(row * SPAD + col) * 2);
            }
            #pragma unroll
            for (int i = 0; i < 4; i++)
                #pragma unroll
                for (int j = 0; j < 4; j++)
                    mma16816(acc[i][j], a[i], b[j]);
        }
        __syncthreads();
    }

    // epilogue: direct global stores (float2) + bias
    const int gr = lane >> 2;          // 0..7
    const int gc = (lane & 3) * 2;     // 0,2,4,6
    #pragma unroll
    for (int j = 0; j < 4; j++) {
        int col = bn + warp_n * 32 + j * 8 + gc;
        float2 bv = *(const float2*)(bias + col);
        #pragma unroll
        for (int i = 0; i < 4; i++) {
            int row0 = bm + warp_m * 64 + i * 16 + gr;
            float2 v0 = make_float2(acc[i][j][0] + bv.x, acc[i][j][1] + bv.y);
            float2 v1 = make_float2(acc[i][j][2] + bv.x, acc[i][j][3] + bv.y);
            *(float2*)(C + (size_t)row0 * VV + col)       = v0;
            *(float2*)(C + (size_t)(row0 + 8) * VV + col) = v1;
        }
    }
}

// ---------------- liquid sequential scan ----------------
__global__ void liquid_scan_kernel(const float* __restrict__ I, const float* __restrict__ tau,
                                   const float* __restrict__ log_dt, float* __restrict__ out) {
    int b = blockIdx.x;
    int o = threadIdx.x;
    float dt = expf(log_dt[0]);
    float r = dt / tau[o];
    float u = 0.f, s = 0.f;
    const float* Ib = I + (size_t)b * SS * HH + o;
    float* Ob = out + (size_t)b * SS * HH + o;
    float nextI = Ib[0];
    for (int t = 0; t < SS; t++) {
        float It = nextI;
        if (t + 1 < SS) nextI = Ib[(size_t)(t+1) * HH];
        float sn = s + r * (u - s);
        u = u + r * (It - u);
        s = sn;
        Ob[(size_t)t * HH] = tanhf(s);
    }
}

// ---------------- layernorm over H=512 ----------------
__global__ void layernorm_kernel(const float* __restrict__ in, const float* __restrict__ g,
                                 const float* __restrict__ be, float* __restrict__ out) {
    int row = blockIdx.x;
    int tid = threadIdx.x;
    const float* p = in + (size_t)row * HH;
    float a = p[tid], b = p[tid + 256];
    float sum = a + b, sq = a*a + b*b;
    __shared__ float s1[8], s2[8];
    #pragma unroll
    for (int o = 16; o; o >>= 1) {
        sum += __shfl_xor_sync(0xffffffffu, sum, o);
        sq  += __shfl_xor_sync(0xffffffffu, sq,  o);
    }
    if ((tid & 31) == 0) { s1[tid>>5] = sum; s2[tid>>5] = sq; }
    __syncthreads();
    sum = 0.f; sq = 0.f;
    #pragma unroll
    for (int i = 0; i < 8; i++) { sum += s1[i]; sq += s2[i]; }
    float mean = sum * (1.f/512.f);
    float var  = sq * (1.f/512.f) - mean*mean;
    float inv = rsqrtf(var + 1e-5f);
    float* q = out + (size_t)row * HH;
    q[tid]       = (a - mean) * inv * g[tid]       + be[tid];
    q[tid + 256] = (b - mean) * inv * g[tid + 256] + be[tid + 256];
}

// ---------------- attention scores ----------------
__global__ __launch_bounds__(256) void attn_scores_kernel(const float* __restrict__ qkv,
                                                           float* __restrict__ scores) {
    int bh = blockIdx.z; int b = bh >> 3, h = bh & 7;
    int q0 = blockIdx.y * 64, k0 = blockIdx.x * 64;
    __shared__ float Qs[64][65];
    __shared__ float Ks[64][65];
    int tid = threadIdx.x;
    int tx = tid & 15, ty = tid >> 4;

    #pragma unroll
    for (int l = 0; l < 4; l++) {
        int r  = (tid >> 4) + l * 16;
        int c4 = (tid & 15) * 4;
        float4 qv = *(const float4*)(qkv + (size_t)(b*SS + q0 + r)*1536 + h*DH + c4);
        Qs[c4+0][r]=qv.x; Qs[c4+1][r]=qv.y; Qs[c4+2][r]=qv.z; Qs[c4+3][r]=qv.w;
        float4 kv = *(const float4*)(qkv + (size_t)(b*SS + k0 + r)*1536 + 512 + h*DH + c4);
        Ks[c4+0][r]=kv.x; Ks[c4+1][r]=kv.y; Ks[c4+2][r]=kv.z; Ks[c4+3][r]=kv.w;
    }
    __syncthreads();

    float acc[4][4];
    #pragma unroll
    for (int i=0;i<4;i++)
        #pragma unroll
        for (int j=0;j<4;j++) acc[i][j]=0.f;

    #pragma unroll
    for (int d = 0; d < 64; d++) {
        float ra[4], rb[4];
        #pragma unroll
        for (int i=0;i<4;i++) ra[i] = Qs[d][ty*4+i];
        #pragma unroll
        for (int j=0;j<4;j++) rb[j] = Ks[d][tx*4+j];
        #pragma unroll
        for (int i=0;i<4;i++)
            #pragma unroll
            for (int j=0;j<4;j++) acc[i][j] += ra[i]*rb[j];
    }

    size_t base = ((size_t)bh << 20);
    #pragma unroll
    for (int i = 0; i < 4; i++) {
        float4 v = make_float4(acc[i][0]*0.125f, acc[i][1]*0.125f,
                               acc[i][2]*0.125f, acc[i][3]*0.125f);
        *(float4*)(scores + base + (size_t)(q0 + ty*4 + i)*1024 + k0 + tx*4) = v;
    }
}

// ---------------- softmax ----------------
__global__ void softmax_kernel(float* __restrict__ scores) {
    size_t row = blockIdx.x;
    float* p = scores + row * 1024;
    int tid = threadIdx.x;
    float4 v = ((float4*)p)[tid];
    float m = fmaxf(fmaxf(v.x, v.y), fmaxf(v.z, v.w));
    __shared__ float red[8];
    #pragma unroll
    for (int o = 16; o; o >>= 1) m = fmaxf(m, __shfl_xor_sync(0xffffffffu, m, o));
    if ((tid & 31) == 0) red[tid>>5] = m;
    __syncthreads();
    m = red[0];
    #pragma unroll
    for (int i = 1; i < 8; i++) m = fmaxf(m, red[i]);
    v.x = __expf(v.x - m); v.y = __expf(v.y - m);
    v.z = __expf(v.z - m); v.w = __expf(v.w - m);
    float s = v.x + v.y + v.z + v.w;
    #pragma unroll
    for (int o = 16; o; o >>= 1) s += __shfl_xor_sync(0xffffffffu, s, o);
    __syncthreads();
    if ((tid & 31) == 0) red[tid>>5] = s;
    __syncthreads();
    s = 0.f;
    #pragma unroll
    for (int i = 0; i < 8; i++) s += red[i];
    float inv = 1.f / s;
    v.x *= inv; v.y *= inv; v.z *= inv; v.w *= inv;
    ((float4*)p)[tid] = v;
}

// ---------------- attention AV ----------------
__global__ __launch_bounds__(256) void attn_av_kernel(const float* __restrict__ scores,
                                                       const float* __restrict__ qkv,
                                                       float* __restrict__ out) {
    int bh = blockIdx.y; int b = bh >> 3, h = bh & 7;
    int q0 = blockIdx.x * 64;
    __shared__ float Ps[64][65];
    __shared__ float Vs[64][64];
    int tid = threadIdx.x;
    int tx = tid & 15, ty = tid >> 4;

    float acc[4][4];
    #pragma unroll
    for (int i=0;i<4;i++)
        #pragma unroll
        for (int j=0;j<4;j++) acc[i][j]=0.f;

    size_t sbase = ((size_t)bh << 20);
    for (int k0 = 0; k0 < 1024; k0 += 64) {
        #pragma unroll
        for (int l = 0; l < 4; l++) {
            int r  = (tid >> 4) + l * 16;
            int c4 = (tid & 15) * 4;
            float4 pv = *(const float4*)(scores + sbase + (size_t)(q0 + r)*1024 + k0 + c4);
            Ps[c4+0][r]=pv.x; Ps[c4+1][r]=pv.y; Ps[c4+2][r]=pv.z; Ps[c4+3][r]=pv.w;
            float4 vv = *(const float4*)(qkv + (size_t)(b*SS + k0 + r)*1536 + 1024 + h*DH + c4);
            *(float4*)&Vs[r][c4] = vv;
        }
        __syncthreads();
        #pragma unroll
        for (int k = 0; k < 64; k++) {
            float ra[4], rb[4];
            #pragma unroll
            for (int i=0;i<4;i++) ra[i] = Ps[k][ty*4+i];
            #pragma unroll
            for (int j=0;j<4;j++) rb[j] = Vs[k][tx*4+j];
            #pragma unroll
            for (int i=0;i<4;i++)
                #pragma unroll
                for (int j=0;j<4;j++) acc[i][j] += ra[i]*rb[j];
        }
        __syncthreads();
    }

    #pragma unroll
    for (int i = 0; i < 4; i++) {
        float4 v = make_float4(acc[i][0], acc[i][1], acc[i][2], acc[i][3]);
        *(float4*)(out + (size_t)(b*SS + q0 + ty*4 + i)*HH + h*DH + tx*4) = v;
    }
}

// ---------------- host orchestration ----------------
static void sgemm(const float* A, const float* B, const float* bias, float* C,
                  int M, int N, int K) {
    dim3 grid(N / 128, M / 128);
    sgemm_nt<<<grid, 256>>>(A, B, bias, C, M, N, K);
}

extern "C" void kernel_launch(void* const* d_in, const int* in_sizes, int n_in,
                              void* d_out, int out_size) {
    const int*   x          = (const int*)  d_in[0];
    const float* emb        = (const float*)d_in[1];
    const float* W0         = (const float*)d_in[2];
    const float* b0         = (const float*)d_in[3];
    const float* tau0       = (const float*)d_in[4];
    const float* g0         = (const float*)d_in[5];
    const float* be0        = (const float*)d_in[6];
    const float* W1         = (const float*)d_in[7];
    const float* b1         = (const float*)d_in[8];
    const float* tau1       = (const float*)d_in[9];
    const float* g1         = (const float*)d_in[10];
    const float* be1        = (const float*)d_in[11];
    const float* attn_in_w  = (const float*)d_in[12];
    const float* attn_in_b  = (const float*)d_in[13];
    const float* attn_out_w = (const float*)d_in[14];
    const float* attn_out_b = (const float*)d_in[15];
    const float* out_w      = (const float*)d_in[16];
    const float* out_b      = (const float*)d_in[17];
    const float* log_dt     = (const float*)d_in[18];
    float* out = (float*)d_out;

    float *h, *I, *sbuf, *qkv, *att, *h2, *scores;
    __nv_bfloat16 *Ahi, *Alo, *Bhi, *Blo;
    cudaGetSymbolAddress((void**)&h,      g_h);
    cudaGetSymbolAddress((void**)&I,      g_I);
    cudaGetSymbolAddress((void**)&sbuf,   g_s);
    cudaGetSymbolAddress((void**)&qkv,    g_qkv);
    cudaGetSymbolAddress((void**)&att,    g_att);
    cudaGetSymbolAddress((void**)&h2,     g_h2);
    cudaGetSymbolAddress((void**)&scores, g_scores);
    cudaGetSymbolAddress((void**)&Ahi,    g_Ahi);
    cudaGetSymbolAddress((void**)&Alo,    g_Alo);
    cudaGetSymbolAddress((void**)&Bhi,    g_Bhi);
    cudaGetSymbolAddress((void**)&Blo,    g_Blo);

    // bf16 split of vocab weights (independent of everything else; runs early)
    split_bf16_kernel<<<(VV*HH + 255)/256, 256>>>(out_w, Bhi, Blo, VV*HH);

    // 1. embedding + positional encoding
    embed_pe_kernel<<<(MM*EE)/256, 256>>>(x, emb, h);

    // 2. liquid layer 0
    sgemm(h, W0, b0, I, MM, HH, EE);
    liquid_scan_kernel<<<BB, HH>>>(I, tau0, log_dt, sbuf);
    layernorm_kernel<<<MM, 256>>>(sbuf, g0, be0, h);

    // 3. liquid layer 1
    sgemm(h, W1, b1, I, MM, HH, HH);
    liquid_scan_kernel<<<BB, HH>>>(I, tau1, log_dt, sbuf);
    layernorm_kernel<<<MM, 256>>>(sbuf, g1, be1, h);

    // 4. MHA
    sgemm(h, attn_in_w, attn_in_b, qkv, MM, 3*HH, HH);
    attn_scores_kernel<<<dim3(16, 16, 32), 256>>>(qkv, scores);
    softmax_kernel<<<32*1024, 256>>>(scores);
    attn_av_kernel<<<dim3(16, 32), 256>>>(scores, qkv, att);
    sgemm(att, attn_out_w, attn_out_b, h2, MM, HH, HH);

    // 5. vocab projection via mma.sync split-bf16
    split_bf16_kernel<<<(MM*HH + 255)/256, 256>>>(h2, Ahi, Alo, MM*HH);
    gemm_vocab_mma<<<dim3(VV/128, MM/128), 256>>>(Ahi, Alo, Bhi, Blo, out_b, out);
}

// round 5
// speedup vs baseline: 2.3617x; 1.3460x over previous
#include <cuda_runtime.h>
#include <cuda_bf16.h>
#include <cstdint>
#include <math.h>

#define BB 4
#define SS 1024
#define EE 512
#define HH 512
#define VV 32000
#define MM (BB*SS)      // 4096
#define NH 8
#define DH 64

// ---------------- scratch (static device memory; no allocations) ----------------
__device__ float g_I[MM*HH];
__device__ float g_s[MM*HH];
__device__ float g_qkv[MM*3*HH];
__device__ float g_att[MM*HH];
__device__ float g_h2[MM*HH];
__device__ float g_scores[32*1024*1024];          // [bh][q][k] fp32
// activation split buffers (reused across stages, all sequential)
__device__ __nv_bfloat16 g_Ahi[MM*HH];
__device__ __nv_bfloat16 g_Alo[MM*HH];
// weight splits
__device__ __nv_bfloat16 g_W0hi[HH*EE],  g_W0lo[HH*EE];
__device__ __nv_bfloat16 g_W1hi[HH*HH],  g_W1lo[HH*HH];
__device__ __nv_bfloat16 g_Wqhi[3*HH*HH], g_Wqlo[3*HH*HH];
__device__ __nv_bfloat16 g_Wohi[HH*HH],  g_Wolo[HH*HH];
__device__ __nv_bfloat16 g_Bhi[(size_t)VV*HH], g_Blo[(size_t)VV*HH];
// attention operand splits
__device__ __nv_bfloat16 g_Qhi[32*1024*64], g_Qlo[32*1024*64];
__device__ __nv_bfloat16 g_Khi[32*1024*64], g_Klo[32*1024*64];
__device__ __nv_bfloat16 g_Vthi[32*128*1024], g_Vtlo[32*128*1024];  // [bh][d(pad128)][k]; pad rows stay 0
__device__ __nv_bfloat16 g_Phi[(size_t)32*1024*1024], g_Plo[(size_t)32*1024*1024];

__device__ __forceinline__ uint32_t smem_u32(const void* p) {
    uint32_t a;
    asm("{ .reg .u64 t; cvta.to.shared.u64 t, %1; cvt.u32.u64 %0, t; }" : "=r"(a) : "l"(p));
    return a;
}
__device__ __forceinline__ void cp_async16(uint32_t dst, const void* src) {
    asm volatile("cp.async.cg.shared.global [%0], [%1], 16;" :: "r"(dst), "l"(src));
}
__device__ __forceinline__ void ldsm_x4(uint32_t& r0, uint32_t& r1, uint32_t& r2, uint32_t& r3,
                                        uint32_t addr) {
    asm volatile("ldmatrix.sync.aligned.m8n8.x4.shared.b16 {%0,%1,%2,%3}, [%4];"
                 : "=r"(r0), "=r"(r1), "=r"(r2), "=r"(r3) : "r"(addr));
}
__device__ __forceinline__ void mma16816(float* c, const uint32_t* a, const uint32_t* b) {
    asm volatile("mma.sync.aligned.m16n8k16.row.col.f32.bf16.bf16.f32 "
                 "{%0,%1,%2,%3}, {%4,%5,%6,%7}, {%8,%9}, {%0,%1,%2,%3};"
                 : "+f"(c[0]), "+f"(c[1]), "+f"(c[2]), "+f"(c[3])
                 : "r"(a[0]), "r"(a[1]), "r"(a[2]), "r"(a[3]), "r"(b[0]), "r"(b[1]));
}

// ---------------- embed + positional encoding -> bf16 hi/lo ----------------
__global__ void embed_pe_split(const int* __restrict__ x, const float* __restrict__ emb,
                               __nv_bfloat16* __restrict__ hi, __nv_bfloat16* __restrict__ lo) {
    int idx = blockIdx.x * blockDim.x + threadIdx.x;
    if (idx >= MM*EE) return;
    int m = idx >> 9;
    int e = idx & 511;
    int s = m & (SS - 1);
    int tok = x[m];
    int i2 = e & ~1;
    float freq = expf((float)i2 * (-9.210340371976184f / 512.0f));
    float ang = (float)s * freq;
    float pe = (e & 1) ? cosf(ang) : sinf(ang);
    float v = emb[(size_t)tok * EE + e] + pe;
    __nv_bfloat16 h = __float2bfloat16(v);
    hi[idx] = h;
    lo[idx] = __float2bfloat16(v - __bfloat162float(h));
}

// ---------------- bf16 hi/lo split ----------------
__global__ void split_bf16_kernel(const float* __restrict__ in, __nv_bfloat16* __restrict__ hi,
                                  __nv_bfloat16* __restrict__ lo, int n) {
    int i = blockIdx.x * blockDim.x + threadIdx.x;
    if (i >= n) return;
    float x = in[i];
    __nv_bfloat16 h = __float2bfloat16(x);
    hi[i] = h;
    lo[i] = __float2bfloat16(x - __bfloat162float(h));
}

// ============== generic batched NT GEMM via mma.sync bf16 split ==============
// C[M,N] = scale * (A[M,K] @ B[N,K]^T) + bias, via Ahi*Bhi + Ahi*Blo + Alo*Bhi.
// Block 128x128, BK=32 per stage, cp.async double buffer, 8 warps 2(m)x4(n).
#define SPAD 40

__global__ __launch_bounds__(256, 2) void gemm_nt_mma(
    const __nv_bfloat16* __restrict__ Ahi_, const __nv_bfloat16* __restrict__ Alo_,
    const __nv_bfloat16* __restrict__ Bhi_, const __nv_bfloat16* __restrict__ Blo_,
    const float* __restrict__ bias, float* __restrict__ C_,
    int K, int lda, int ldb, int ldc, int nValid, float scale,
    int zmod, long long sA1, long long sA2, long long sB1, long long sB2,
    long long sC1, long long sC2)
{
    __shared__ __nv_bfloat16 As[2][128*SPAD];
    __shared__ __nv_bfloat16 Bs[2][128*SPAD];

    const int tid = threadIdx.x;
    const int lane = tid & 31;
    const int wid = tid >> 5;
    const int warp_m = wid >> 2;
    const int warp_n = wid & 3;
    const int bm = blockIdx.y * 128;
    const int bn = blockIdx.x * 128;

    const int z = blockIdx.z;
    const int z1 = z % zmod, z2 = z / zmod;
    const long long offA = (long long)z1 * sA1 + (long long)z2 * sA2;
    const long long offB = (long long)z1 * sB1 + (long long)z2 * sB2;
    const __nv_bfloat16* segA[3] = { Ahi_ + offA, Ahi_ + offA, Alo_ + offA };
    const __nv_bfloat16* segB[3] = { Bhi_ + offB, Blo_ + offB, Bhi_ + offB };
    float* C = C_ + (long long)z1 * sC1 + (long long)z2 * sC2;

    const uint32_t sA = smem_u32(As);
    const uint32_t sB = smem_u32(Bs);

    float acc[4][4][4];
    #pragma unroll
    for (int i = 0; i < 4; i++)
        #pragma unroll
        for (int j = 0; j < 4; j++)
            #pragma unroll
            for (int r = 0; r < 4; r++) acc[i][j][r] = 0.f;

    const int lrow = tid >> 2;          // 0..63
    const int lcol = (tid & 3) * 8;     // 0,8,16,24
    const int nstages = (3 * K) >> 5;

    auto prefetch = [&](int s) {
        int gk = s * 32;
        int seg = gk / K;
        int kk = gk - seg * K;
        const __nv_bfloat16* Ap = segA[seg] + (size_t)bm * lda + kk + lcol;
        const __nv_bfloat16* Bp = segB[seg] + (size_t)bn * ldb + kk + lcol;
        int buf = s & 1;
        #pragma unroll
        for (int c = 0; c < 2; c++) {
            int row = lrow + c * 64;
            cp_async16(sA + (uint32_t)(buf * (128*SPAD) + row * SPAD + lcol) * 2,
                       Ap + (size_t)row * lda);
            cp_async16(sB + (uint32_t)(buf * (128*SPAD) + row * SPAD + lcol) * 2,
                       Bp + (size_t)row * ldb);
        }
    };

    prefetch(0);
    asm volatile("cp.async.commit_group;");

    for (int s = 0; s < nstages; s++) {
        if (s < nstages - 1) {
            prefetch(s + 1);
            asm volatile("cp.async.commit_group;");
            asm volatile("cp.async.wait_group 1;");
        } else {
            asm volatile("cp.async.wait_group 0;");
        }
        __syncthreads();

        const uint32_t bufA = sA + (uint32_t)((s & 1) * (128*SPAD)) * 2;
        const uint32_t bufB = sB + (uint32_t)((s & 1) * (128*SPAD)) * 2;
        const int q  = lane >> 3;
        const int rr = lane & 7;

        #pragma unroll
        for (int ko = 0; ko < 32; ko += 16) {
            uint32_t a[4][4];
            #pragma unroll
            for (int i = 0; i < 4; i++) {
                int m0 = warp_m * 64 + i * 16;
                int row = m0 + (q & 1) * 8 + rr;
                int col = ko + (q >> 1) * 8;
                ldsm_x4(a[i][0], a[i][1], a[i][2], a[i][3],
                        bufA + (uint32_t)(row * SPAD + col) * 2);
            }
            uint32_t b[4][2];
            #pragma unroll
            for (int j = 0; j < 2; j++) {
                int n0 = warp_n * 32 + j * 16;
                int row = n0 + (q >> 1) * 8 + rr;
                int col = ko + (q & 1) * 8;
                ldsm_x4(b[2*j][0], b[2*j][1], b[2*j+1][0], b[2*j+1][1],
                        bufB + (uint32_t)(row * SPAD + col) * 2);
            }
            #pragma unroll
            for (int i = 0; i < 4; i++)
                #pragma unroll
                for (int j = 0; j < 4; j++)
                    mma16816(acc[i][j], a[i], b[j]);
        }
        __syncthreads();
    }

    // epilogue
    const int gr = lane >> 2;
    const int gc = (lane & 3) * 2;
    #pragma unroll
    for (int j = 0; j < 4; j++) {
        int col = bn + warp_n * 32 + j * 8 + gc;
        if (col >= nValid) continue;
        float2 bv = make_float2(0.f, 0.f);
        if (bias) bv = *(const float2*)(bias + col);
        #pragma unroll
        for (int i = 0; i < 4; i++) {
            int row0 = bm + warp_m * 64 + i * 16 + gr;
            float2 v0 = make_float2(acc[i][j][0]*scale + bv.x, acc[i][j][1]*scale + bv.y);
            float2 v1 = make_float2(acc[i][j][2]*scale + bv.x, acc[i][j][3]*scale + bv.y);
            *(float2*)(C + (size_t)row0 * ldc + col)       = v0;
            *(float2*)(C + (size_t)(row0 + 8) * ldc + col) = v1;
        }
    }
}

// ---------------- parallel liquid scan (exact affine chunk decomposition) ----------------
// x_{t+1} = A x_t + r*I_t*e_u, A = [[a,0],[r,a]], a=1-r.  A^t=[[a^t,0],[t r a^{t-1}, a^t]].
__global__ __launch_bounds__(512) void liquid_scan_par(
    const float* __restrict__ I, const float* __restrict__ tau,
    const float* __restrict__ log_dt, float* __restrict__ out) {
    const int b = blockIdx.x;            // 0..3
    const int lg = blockIdx.y;           // 0..31
    const int lane16 = threadIdx.x & 15;
    const int chunk  = threadIdx.x >> 4; // 0..31
    const int o = lg * 16 + lane16;
    const float dt = expf(log_dt[0]);
    const float r = dt / tau[o];
    const float a = 1.f - r;
    const float* Ib = I + (size_t)b * SS * HH + o;
    const int t0 = chunk * 32;

    float Iv[32];
    #pragma unroll
    for (int i = 0; i < 32; i++) Iv[i] = Ib[(size_t)(t0 + i) * HH];

    // phase 1: local scan with zero init
    float u = 0.f, s = 0.f;
    #pragma unroll
    for (int i = 0; i < 32; i++) {
        float sn = s + r * (u - s);
        u = u + r * (Iv[i] - u);
        s = sn;
    }
    __shared__ float2 dloc[32][16];
    __shared__ float2 st[32][16];
    dloc[chunk][lane16] = make_float2(u, s);
    __syncthreads();

    // phase 2: inter-chunk affine combine (16 threads)
    if (chunk == 0) {
        float a2 = a*a, a4 = a2*a2, a8 = a4*a4, a16 = a8*a8;
        float a32v = a16*a16;
        float a31 = a16*a8*a4*a2*a;
        float c32 = 32.f * r * a31;
        float2 x = make_float2(0.f, 0.f);
        #pragma unroll
        for (int c = 0; c < 32; c++) {
            st[c][lane16] = x;
            float2 d = dloc[c][lane16];
            float nu = a32v * x.x + d.x;
            float ns = c32 * x.x + a32v * x.y + d.y;
            x = make_float2(nu, ns);
        }
    }
    __syncthreads();

    // phase 3: exact replay from correct start state
    float2 x0 = st[chunk][lane16];
    u = x0.x; s = x0.y;
    float* Ob = out + (size_t)b * SS * HH + o;
    #pragma unroll
    for (int i = 0; i < 32; i++) {
        float sn = s + r * (u - s);
        u = u + r * (Iv[i] - u);
        s = sn;
        Ob[(size_t)(t0 + i) * HH] = tanhf(s);
    }
}

// ---------------- layernorm -> bf16 hi/lo ----------------
__global__ void layernorm_split(const float* __restrict__ in, const float* __restrict__ g,
                                const float* __restrict__ be,
                                __nv_bfloat16* __restrict__ hi, __nv_bfloat16* __restrict__ lo) {
    int row = blockIdx.x;
    int tid = threadIdx.x;   // 256
    const float* p = in + (size_t)row * HH;
    float a = p[tid], b = p[tid + 256];
    float sum = a + b, sq = a*a + b*b;
    __shared__ float s1[8], s2[8];
    #pragma unroll
    for (int o = 16; o; o >>= 1) {
        sum += __shfl_xor_sync(0xffffffffu, sum, o);
        sq  += __shfl_xor_sync(0xffffffffu, sq,  o);
    }
    if ((tid & 31) == 0) { s1[tid>>5] = sum; s2[tid>>5] = sq; }
    __syncthreads();
    sum = 0.f; sq = 0.f;
    #pragma unroll
    for (int i = 0; i < 8; i++) { sum += s1[i]; sq += s2[i]; }
    float mean = sum * (1.f/512.f);
    float var  = sq * (1.f/512.f) - mean*mean;
    float inv = rsqrtf(var + 1e-5f);
    float y0 = (a - mean) * inv * g[tid]       + be[tid];
    float y1 = (b - mean) * inv * g[tid + 256] + be[tid + 256];
    size_t base = (size_t)row * HH;
    __nv_bfloat16 h0 = __float2bfloat16(y0);
    __nv_bfloat16 h1 = __float2bfloat16(y1);
    hi[base + tid]       = h0;
    hi[base + tid + 256] = h1;
    lo[base + tid]       = __float2bfloat16(y0 - __bfloat162float(h0));
    lo[base + tid + 256] = __float2bfloat16(y1 - __bfloat162float(h1));
}

// ---------------- qkv split: Q/K -> [bh][s][d], V -> transposed [bh][d][k] ----------------
__global__ void qkv_split_kernel(const float* __restrict__ qkv) {
    int idx = blockIdx.x * blockDim.x + threadIdx.x;
    if (idx >= MM * 1536) return;
    int row = idx / 1536;          // b*1024 + s
    int col = idx - row * 1536;
    int b = row >> 10, s = row & 1023;
    float v = qkv[idx];
    __nv_bfloat16 h = __float2bfloat16(v);
    __nv_bfloat16 l = __float2bfloat16(v - __bfloat162float(h));
    if (col < 512) {
        int hd = col >> 6, d = col & 63;
        size_t o = ((size_t)(b*8 + hd) * 1024 + s) * 64 + d;
        g_Qhi[o] = h; g_Qlo[o] = l;
    } else if (col < 1024) {
        int c = col - 512;
        int hd = c >> 6, d = c & 63;
        size_t o = ((size_t)(b*8 + hd) * 1024 + s) * 64 + d;
        g_Khi[o] = h; g_Klo[o] = l;
    } else {
        int c = col - 1024;
        int hd = c >> 6, d = c & 63;
        size_t o = (size_t)(b*8 + hd) * 131072 + (size_t)d * 1024 + s;
        g_Vthi[o] = h; g_Vtlo[o] = l;
    }
}

// ---------------- softmax over rows of 1024, fused P split ----------------
__global__ void softmax_split_kernel(const float* __restrict__ scores,
                                     __nv_bfloat16* __restrict__ Phi,
                                     __nv_bfloat16* __restrict__ Plo) {
    size_t row = blockIdx.x;
    const float* p = scores + row * 1024;
    int tid = threadIdx.x;   // 256
    float4 v = ((const float4*)p)[tid];
    float m = fmaxf(fmaxf(v.x, v.y), fmaxf(v.z, v.w));
    __shared__ float red[8];
    #pragma unroll
    for (int o = 16; o; o >>= 1) m = fmaxf(m, __shfl_xor_sync(0xffffffffu, m, o));
    if ((tid & 31) == 0) red[tid>>5] = m;
    __syncthreads();
    m = red[0];
    #pragma unroll
    for (int i = 1; i < 8; i++) m = fmaxf(m, red[i]);
    v.x = __expf(v.x - m); v.y = __expf(v.y - m);
    v.z = __expf(v.z - m); v.w = __expf(v.w - m);
    float sum = v.x + v.y + v.z + v.w;
    #pragma unroll
    for (int o = 16; o; o >>= 1) sum += __shfl_xor_sync(0xffffffffu, sum, o);
    __syncthreads();
    if ((tid & 31) == 0) red[tid>>5] = sum;
    __syncthreads();
    sum = 0.f;
    #pragma unroll
    for (int i = 0; i < 8; i++) sum += red[i];
    float inv = 1.f / sum;
    float pv[4] = { v.x*inv, v.y*inv, v.z*inv, v.w*inv };
    __nv_bfloat16 hb[4], lb[4];
    #pragma unroll
    for (int i = 0; i < 4; i++) {
        hb[i] = __float2bfloat16(pv[i]);
        lb[i] = __float2bfloat16(pv[i] - __bfloat162float(hb[i]));
    }
    *(uint2*)(Phi + row*1024 + tid*4) = *(uint2*)hb;
    *(uint2*)(Plo + row*1024 + tid*4) = *(uint2*)lb;
}

// ---------------- host orchestration ----------------
static void gemm_plain(const __nv_bfloat16* Ahi, const __nv_bfloat16* Alo,
                       const __nv_bfloat16* Bhi, const __nv_bfloat16* Blo,
                       const float* bias, float* C, int M, int N, int K, int ldc) {
    dim3 grid((N + 127) / 128, M / 128, 1);
    gemm_nt_mma<<<grid, 256>>>(Ahi, Alo, Bhi, Blo, bias, C,
                               K, K, K, ldc, N, 1.0f,
                               1, 0, 0, 0, 0, 0, 0);
}

extern "C" void kernel_launch(void* const* d_in, const int* in_sizes, int n_in,
                              void* d_out, int out_size) {
    const int*   x          = (const int*)  d_in[0];
    const float* emb        = (const float*)d_in[1];
    const float* W0         = (const float*)d_in[2];
    const float* b0         = (const float*)d_in[3];
    const float* tau0       = (const float*)d_in[4];
    const float* g0         = (const float*)d_in[5];
    const float* be0        = (const float*)d_in[6];
    const float* W1         = (const float*)d_in[7];
    const float* b1         = (const float*)d_in[8];
    const float* tau1       = (const float*)d_in[9];
    const float* g1         = (const float*)d_in[10];
    const float* be1        = (const float*)d_in[11];
    const float* attn_in_w  = (const float*)d_in[12];
    const float* attn_in_b  = (const float*)d_in[13];
    const float* attn_out_w = (const float*)d_in[14];
    const float* attn_out_b = (const float*)d_in[15];
    const float* out_w      = (const float*)d_in[16];
    const float* out_b      = (const float*)d_in[17];
    const float* log_dt     = (const float*)d_in[18];
    float* out = (float*)d_out;

    float *I, *sbuf, *qkv, *att, *h2, *scores;
    __nv_bfloat16 *Ahi, *Alo, *Bhi, *Blo;
    __nv_bfloat16 *W0hi, *W0lo, *W1hi, *W1lo, *Wqhi, *Wqlo, *Wohi, *Wolo;
    __nv_bfloat16 *Qhi, *Qlo, *Khi, *Klo, *Vthi, *Vtlo, *Phi, *Plo;
    cudaGetSymbolAddress((void**)&I,      g_I);
    cudaGetSymbolAddress((void**)&sbuf,   g_s);
    cudaGetSymbolAddress((void**)&qkv,    g_qkv);
    cudaGetSymbolAddress((void**)&att,    g_att);
    cudaGetSymbolAddress((void**)&h2,     g_h2);
    cudaGetSymbolAddress((void**)&scores, g_scores);
    cudaGetSymbolAddress((void**)&Ahi,    g_Ahi);
    cudaGetSymbolAddress((void**)&Alo,    g_Alo);
    cudaGetSymbolAddress((void**)&Bhi,    g_Bhi);
    cudaGetSymbolAddress((void**)&Blo,    g_Blo);
    cudaGetSymbolAddress((void**)&W0hi,   g_W0hi);
    cudaGetSymbolAddress((void**)&W0lo,   g_W0lo);
    cudaGetSymbolAddress((void**)&W1hi,   g_W1hi);
    cudaGetSymbolAddress((void**)&W1lo,   g_W1lo);
    cudaGetSymbolAddress((void**)&Wqhi,   g_Wqhi);
    cudaGetSymbolAddress((void**)&Wqlo,   g_Wqlo);
    cudaGetSymbolAddress((void**)&Wohi,   g_Wohi);
    cudaGetSymbolAddress((void**)&Wolo,   g_Wolo);
    cudaGetSymbolAddress((void**)&Qhi,    g_Qhi);
    cudaGetSymbolAddress((void**)&Qlo,    g_Qlo);
    cudaGetSymbolAddress((void**)&Khi,    g_Khi);
    cudaGetSymbolAddress((void**)&Klo,    g_Klo);
    cudaGetSymbolAddress((void**)&Vthi,   g_Vthi);
    cudaGetSymbolAddress((void**)&Vtlo,   g_Vtlo);
    cudaGetSymbolAddress((void**)&Phi,    g_Phi);
    cudaGetSymbolAddress((void**)&Plo,    g_Plo);

    // ---- weight splits (input-only dependencies) ----
    split_bf16_kernel<<<(VV*HH + 255)/256, 256>>>(out_w, Bhi, Blo, VV*HH);
    split_bf16_kernel<<<(HH*EE + 255)/256, 256>>>(W0, W0hi, W0lo, HH*EE);
    split_bf16_kernel<<<(HH*HH + 255)/256, 256>>>(W1, W1hi, W1lo, HH*HH);
    split_bf16_kernel<<<(3*HH*HH + 255)/256, 256>>>(attn_in_w, Wqhi, Wqlo, 3*HH*HH);
    split_bf16_kernel<<<(HH*HH + 255)/256, 256>>>(attn_out_w, Wohi, Wolo, HH*HH);

    // 1. embedding + positional encoding -> bf16 split
    embed_pe_split<<<(MM*EE)/256, 256>>>(x, emb, Ahi, Alo);

    // 2. liquid layer 0
    gemm_plain(Ahi, Alo, W0hi, W0lo, b0, I, MM, HH, EE, HH);
    liquid_scan_par<<<dim3(BB, 32), 512>>>(I, tau0, log_dt, sbuf);
    layernorm_split<<<MM, 256>>>(sbuf, g0, be0, Ahi, Alo);

    // 3. liquid layer 1
    gemm_plain(Ahi, Alo, W1hi, W1lo, b1, I, MM, HH, HH, HH);
    liquid_scan_par<<<dim3(BB, 32), 512>>>(I, tau1, log_dt, sbuf);
    layernorm_split<<<MM, 256>>>(sbuf, g1, be1, Ahi, Alo);

    // 4. MHA
    gemm_plain(Ahi, Alo, Wqhi, Wqlo, attn_in_b, qkv, MM, 3*HH, HH, 3*HH);
    qkv_split_kernel<<<(MM*1536 + 255)/256, 256>>>(qkv);

    // scores[bh] = Q[bh] @ K[bh]^T / 8     (batched, zmod=32)
    gemm_nt_mma<<<dim3(8, 8, 32), 256>>>(Qhi, Qlo, Khi, Klo, nullptr, scores,
                                         64, 64, 64, 1024, 1024, 0.125f,
                                         32, 65536LL, 0, 65536LL, 0, 1LL<<20, 0);
    softmax_split_kernel<<<32*1024, 256>>>(scores, Phi, Plo);

    // att[b*1024+q][h*64+d] = P[bh] @ Vt[bh]^T    (zmod=8: z1=h, z2=b)
    gemm_nt_mma<<<dim3(1, 8, 32), 256>>>(Phi, Plo, Vthi, Vtlo, nullptr, att,
                                         1024, 1024, 1024, 512, 64, 1.0f,
                                         8, 1LL<<20, 8LL<<20, 131072LL, 8LL*131072,
                                         64LL, 524288LL);

    split_bf16_kernel<<<(MM*HH + 255)/256, 256>>>(att, Ahi, Alo, MM*HH);
    gemm_plain(Ahi, Alo, Wohi, Wolo, attn_out_b, h2, MM, HH, HH, HH);

    // 5. vocab projection
    split_bf16_kernel<<<(MM*HH + 255)/256, 256>>>(h2, Ahi, Alo, MM*HH);
    gemm_plain(Ahi, Alo, Bhi, Blo, out_b, out, MM, VV, HH, VV);
}

// round 6
// speedup vs baseline: 2.8343x; 1.2001x over previous
#include <cuda_runtime.h>
#include <cuda_bf16.h>
#include <cstdint>
#include <math.h>

#define BB 4
#define SS 1024
#define EE 512
#define HH 512
#define VV 32000
#define MM (BB*SS)      // 4096
#define NH 8
#define DH 64

// ---------------- scratch (static device memory; no allocations) ----------------
__device__ float g_I[MM*HH];
__device__ float g_s[MM*HH];
__device__ float g_qkv[MM*3*HH];
__device__ float g_scores[32*1024*1024];          // [bh][q][k] fp32
__device__ __nv_bfloat16 g_Ahi[MM*HH],  g_Alo[MM*HH];
__device__ __nv_bfloat16 g_A2hi[MM*HH], g_A2lo[MM*HH];
__device__ __nv_bfloat16 g_W0hi[HH*EE],  g_W0lo[HH*EE];
__device__ __nv_bfloat16 g_W1hi[HH*HH],  g_W1lo[HH*HH];
__device__ __nv_bfloat16 g_Wqhi[3*HH*HH], g_Wqlo[3*HH*HH];
__device__ __nv_bfloat16 g_Wohi[HH*HH],  g_Wolo[HH*HH];
__device__ __nv_bfloat16 g_Bhi[(size_t)VV*HH], g_Blo[(size_t)VV*HH];
__device__ __nv_bfloat16 g_Qhi[32*1024*64], g_Qlo[32*1024*64];
__device__ __nv_bfloat16 g_Khi[32*1024*64], g_Klo[32*1024*64];
__device__ __nv_bfloat16 g_Vthi[32*128*1024], g_Vtlo[32*128*1024];  // [bh][d pad128][k]
__device__ __nv_bfloat16 g_Phi[(size_t)32*1024*1024], g_Plo[(size_t)32*1024*1024];

__device__ __forceinline__ uint32_t smem_u32(const void* p) {
    uint32_t a;
    asm("{ .reg .u64 t; cvta.to.shared.u64 t, %1; cvt.u32.u64 %0, t; }" : "=r"(a) : "l"(p));
    return a;
}
__device__ __forceinline__ void cp_async16(uint32_t dst, const void* src) {
    asm volatile("cp.async.cg.shared.global [%0], [%1], 16;" :: "r"(dst), "l"(src));
}
__device__ __forceinline__ void ldsm_x4(uint32_t& r0, uint32_t& r1, uint32_t& r2, uint32_t& r3,
                                        uint32_t addr) {
    asm volatile("ldmatrix.sync.aligned.m8n8.x4.shared.b16 {%0,%1,%2,%3}, [%4];"
                 : "=r"(r0), "=r"(r1), "=r"(r2), "=r"(r3) : "r"(addr));
}
__device__ __forceinline__ void mma16816(float* c, const uint32_t* a, const uint32_t* b) {
    asm volatile("mma.sync.aligned.m16n8k16.row.col.f32.bf16.bf16.f32 "
                 "{%0,%1,%2,%3}, {%4,%5,%6,%7}, {%8,%9}, {%0,%1,%2,%3};"
                 : "+f"(c[0]), "+f"(c[1]), "+f"(c[2]), "+f"(c[3])
                 : "r"(a[0]), "r"(a[1]), "r"(a[2]), "r"(a[3]), "r"(b[0]), "r"(b[1]));
}

// ---------------- embed + positional encoding -> bf16 hi/lo ----------------
__global__ void embed_pe_split(const int* __restrict__ x, const float* __restrict__ emb,
                               __nv_bfloat16* __restrict__ hi, __nv_bfloat16* __restrict__ lo) {
    int idx = blockIdx.x * blockDim.x + threadIdx.x;
    if (idx >= MM*EE) return;
    int m = idx >> 9;
    int e = idx & 511;
    int s = m & (SS - 1);
    int tok = x[m];
    int i2 = e & ~1;
    float freq = expf((float)i2 * (-9.210340371976184f / 512.0f));
    float ang = (float)s * freq;
    float pe = (e & 1) ? cosf(ang) : sinf(ang);
    float v = emb[(size_t)tok * EE + e] + pe;
    __nv_bfloat16 h = __float2bfloat16(v);
    hi[idx] = h;
    lo[idx] = __float2bfloat16(v - __bfloat162float(h));
}

__global__ void split_bf16_kernel(const float* __restrict__ in, __nv_bfloat16* __restrict__ hi,
                                  __nv_bfloat16* __restrict__ lo, int n) {
    int i = blockIdx.x * blockDim.x + threadIdx.x;
    if (i >= n) return;
    float x = in[i];
    __nv_bfloat16 h = __float2bfloat16(x);
    hi[i] = h;
    lo[i] = __float2bfloat16(x - __bfloat162float(h));
}

// ============== paired-operand split-precision NT GEMM (mma.sync bf16) ==============
// C = scale*(Ahi@Bhi^T + Ahi@Blo^T + Alo@Bhi^T) + bias
// Per k-stage loads 4 tiles (Ahi,Alo,Bhi,Blo) and issues all 3 products.
#define SPAD 40
#define TILE_E (128*SPAD)
#define GP_SMEM (2*4*TILE_E*2)    // 81920 bytes

__global__ __launch_bounds__(256, 2) void gemm_pair_mma(
    const __nv_bfloat16* __restrict__ Ahi_, const __nv_bfloat16* __restrict__ Alo_,
    const __nv_bfloat16* __restrict__ Bhi_, const __nv_bfloat16* __restrict__ Blo_,
    const float* __restrict__ bias, float* __restrict__ C_,
    __nv_bfloat16* __restrict__ Chi_, __nv_bfloat16* __restrict__ Clo_,
    int K, int lda, int ldb, int ldc, int nValid, float scale,
    int zmod, long long sA1, long long sA2, long long sB1, long long sB2,
    long long sC1, long long sC2)
{
    extern __shared__ __align__(16) __nv_bfloat16 sm[];
    const uint32_t smb = smem_u32(sm);

    const int tid = threadIdx.x;
    const int lane = tid & 31;
    const int wid = tid >> 5;
    const int warp_m = wid >> 2;      // 0..1
    const int warp_n = wid & 3;       // 0..3
    const int bm = blockIdx.y * 128;
    const int bn = blockIdx.x * 128;

    const int z = blockIdx.z;
    const int z1 = z % zmod, z2 = z / zmod;
    const long long offA = (long long)z1 * sA1 + (long long)z2 * sA2;
    const long long offB = (long long)z1 * sB1 + (long long)z2 * sB2;
    const long long offC = (long long)z1 * sC1 + (long long)z2 * sC2;

    const __nv_bfloat16* pA[2] = { Ahi_ + offA + (size_t)bm * lda,
                                   Alo_ + offA + (size_t)bm * lda };
    const __nv_bfloat16* pB[2] = { Bhi_ + offB + (size_t)bn * ldb,
                                   Blo_ + offB + (size_t)bn * ldb };

    float acc[4][4][4];
    #pragma unroll
    for (int i = 0; i < 4; i++)
        #pragma unroll
        for (int j = 0; j < 4; j++)
            #pragma unroll
            for (int r = 0; r < 4; r++) acc[i][j][r] = 0.f;

    const int lrow = tid >> 2;          // 0..63
    const int lcol = (tid & 3) * 8;     // 0,8,16,24
    const int nstages = K >> 5;

    auto prefetch = [&](int s) {
        const int gk = s * 32;
        const uint32_t base = smb + (uint32_t)((s & 1) * 4 * TILE_E) * 2;
        #pragma unroll
        for (int t = 0; t < 4; t++) {
            const __nv_bfloat16* src = (t < 2 ? pA[t] : pB[t-2]) + gk + lcol;
            const int ld = (t < 2) ? lda : ldb;
            #pragma unroll
            for (int c = 0; c < 2; c++) {
                int row = lrow + c * 64;
                cp_async16(base + (uint32_t)(t * TILE_E + row * SPAD + lcol) * 2,
                           src + (size_t)row * ld);
            }
        }
    };

    prefetch(0);
    asm volatile("cp.async.commit_group;");

    for (int s = 0; s < nstages; s++) {
        if (s < nstages - 1) {
            prefetch(s + 1);
            asm volatile("cp.async.commit_group;");
            asm volatile("cp.async.wait_group 1;");
        } else {
            asm volatile("cp.async.wait_group 0;");
        }
        __syncthreads();

        const uint32_t stg = smb + (uint32_t)((s & 1) * 4 * TILE_E) * 2;
        const uint32_t tAhi = stg;
        const uint32_t tAlo = stg + TILE_E * 2;
        const uint32_t tBhi = stg + 2 * TILE_E * 2;
        const uint32_t tBlo = stg + 3 * TILE_E * 2;
        const int q  = lane >> 3;
        const int rr = lane & 7;

        #pragma unroll
        for (int ko = 0; ko < 32; ko += 16) {
            const int arow = warp_m * 64 + (q & 1) * 8 + rr;
            const int acol = ko + (q >> 1) * 8;
            const int brow = warp_n * 32 + (q >> 1) * 8 + rr;
            const int bcol = ko + (q & 1) * 8;

            uint32_t aH[4][4];
            #pragma unroll
            for (int i = 0; i < 4; i++)
                ldsm_x4(aH[i][0], aH[i][1], aH[i][2], aH[i][3],
                        tAhi + (uint32_t)((arow + i * 16) * SPAD + acol) * 2);
            uint32_t bH[4][2], bL[4][2];
            #pragma unroll
            for (int j = 0; j < 2; j++) {
                ldsm_x4(bH[2*j][0], bH[2*j][1], bH[2*j+1][0], bH[2*j+1][1],
                        tBhi + (uint32_t)((brow + j * 16) * SPAD + bcol) * 2);
                ldsm_x4(bL[2*j][0], bL[2*j][1], bL[2*j+1][0], bL[2*j+1][1],
                        tBlo + (uint32_t)((brow + j * 16) * SPAD + bcol) * 2);
            }
            #pragma unroll
            for (int i = 0; i < 4; i++)
                #pragma unroll
                for (int j = 0; j < 4; j++)
                    mma16816(acc[i][j], aH[i], bH[j]);
            #pragma unroll
            for (int i = 0; i < 4; i++)
                #pragma unroll
                for (int j = 0; j < 4; j++)
                    mma16816(acc[i][j], aH[i], bL[j]);
            uint32_t aL[4][4];
            #pragma unroll
            for (int i = 0; i < 4; i++)
                ldsm_x4(aL[i][0], aL[i][1], aL[i][2], aL[i][3],
                        tAlo + (uint32_t)((arow + i * 16) * SPAD + acol) * 2);
            #pragma unroll
            for (int i = 0; i < 4; i++)
                #pragma unroll
                for (int j = 0; j < 4; j++)
                    mma16816(acc[i][j], aL[i], bH[j]);
        }
        __syncthreads();
    }

    // epilogue: fp32 or fused bf16 hi/lo split output
    const int gr = lane >> 2;
    const int gc = (lane & 3) * 2;
    float* C = C_ ? C_ + offC : nullptr;
    __nv_bfloat16* Chi = Chi_ ? Chi_ + offC : nullptr;
    __nv_bfloat16* Clo = Clo_ ? Clo_ + offC : nullptr;

    #pragma unroll
    for (int j = 0; j < 4; j++) {
        int col = bn + warp_n * 32 + j * 8 + gc;
        if (col >= nValid) continue;
        float2 bv = make_float2(0.f, 0.f);
        if (bias) bv = *(const float2*)(bias + col);
        #pragma unroll
        for (int i = 0; i < 4; i++) {
            int row0 = bm + warp_m * 64 + i * 16 + gr;
            float v00 = acc[i][j][0]*scale + bv.x, v01 = acc[i][j][1]*scale + bv.y;
            float v10 = acc[i][j][2]*scale + bv.x, v11 = acc[i][j][3]*scale + bv.y;
            if (Chi) {
                size_t o0 = (size_t)row0 * ldc + col;
                size_t o1 = (size_t)(row0 + 8) * ldc + col;
                __nv_bfloat16 h;
                h = __float2bfloat16(v00); Chi[o0]   = h; Clo[o0]   = __float2bfloat16(v00 - __bfloat162float(h));
                h = __float2bfloat16(v01); Chi[o0+1] = h; Clo[o0+1] = __float2bfloat16(v01 - __bfloat162float(h));
                h = __float2bfloat16(v10); Chi[o1]   = h; Clo[o1]   = __float2bfloat16(v10 - __bfloat162float(h));
                h = __float2bfloat16(v11); Chi[o1+1] = h; Clo[o1+1] = __float2bfloat16(v11 - __bfloat162float(h));
            } else {
                *(float2*)(C + (size_t)row0 * ldc + col)       = make_float2(v00, v01);
                *(float2*)(C + (size_t)(row0 + 8) * ldc + col) = make_float2(v10, v11);
            }
        }
    }
}

// ---------------- parallel liquid scan (exact affine chunk decomposition) ----------------
__global__ __launch_bounds__(512) void liquid_scan_par(
    const float* __restrict__ I, const float* __restrict__ tau,
    const float* __restrict__ log_dt, float* __restrict__ out) {
    const int b = blockIdx.x;
    const int lg = blockIdx.y;
    const int lane16 = threadIdx.x & 15;
    const int chunk  = threadIdx.x >> 4;
    const int o = lg * 16 + lane16;
    const float dt = expf(log_dt[0]);
    const float r = dt / tau[o];
    const float a = 1.f - r;
    const float* Ib = I + (size_t)b * SS * HH + o;
    const int t0 = chunk * 32;

    float Iv[32];
    #pragma unroll
    for (int i = 0; i < 32; i++) Iv[i] = Ib[(size_t)(t0 + i) * HH];

    float u = 0.f, s = 0.f;
    #pragma unroll
    for (int i = 0; i < 32; i++) {
        float sn = s + r * (u - s);
        u = u + r * (Iv[i] - u);
        s = sn;
    }
    __shared__ float2 dloc[32][16];
    __shared__ float2 st[32][16];
    dloc[chunk][lane16] = make_float2(u, s);
    __syncthreads();

    if (chunk == 0) {
        float a2 = a*a, a4 = a2*a2, a8 = a4*a4, a16 = a8*a8;
        float a32v = a16*a16;
        float a31 = a16*a8*a4*a2*a;
        float c32 = 32.f * r * a31;
        float2 x = make_float2(0.f, 0.f);
        #pragma unroll
        for (int c = 0; c < 32; c++) {
            st[c][lane16] = x;
            float2 d = dloc[c][lane16];
            float nu = a32v * x.x + d.x;
            float ns = c32 * x.x + a32v * x.y + d.y;
            x = make_float2(nu, ns);
        }
    }
    __syncthreads();

    float2 x0 = st[chunk][lane16];
    u = x0.x; s = x0.y;
    float* Ob = out + (size_t)b * SS * HH + o;
    #pragma unroll
    for (int i = 0; i < 32; i++) {
        float sn = s + r * (u - s);
        u = u + r * (Iv[i] - u);
        s = sn;
        Ob[(size_t)(t0 + i) * HH] = tanhf(s);
    }
}

// ---------------- layernorm -> bf16 hi/lo ----------------
__global__ void layernorm_split(const float* __restrict__ in, const float* __restrict__ g,
                                const float* __restrict__ be,
                                __nv_bfloat16* __restrict__ hi, __nv_bfloat16* __restrict__ lo) {
    int row = blockIdx.x;
    int tid = threadIdx.x;
    const float* p = in + (size_t)row * HH;
    float a = p[tid], b = p[tid + 256];
    float sum = a + b, sq = a*a + b*b;
    __shared__ float s1[8], s2[8];
    #pragma unroll
    for (int o = 16; o; o >>= 1) {
        sum += __shfl_xor_sync(0xffffffffu, sum, o);
        sq  += __shfl_xor_sync(0xffffffffu, sq,  o);
    }
    if ((tid & 31) == 0) { s1[tid>>5] = sum; s2[tid>>5] = sq; }
    __syncthreads();
    sum = 0.f; sq = 0.f;
    #pragma unroll
    for (int i = 0; i < 8; i++) { sum += s1[i]; sq += s2[i]; }
    float mean = sum * (1.f/512.f);
    float var  = sq * (1.f/512.f) - mean*mean;
    float inv = rsqrtf(var + 1e-5f);
    float y0 = (a - mean) * inv * g[tid]       + be[tid];
    float y1 = (b - mean) * inv * g[tid + 256] + be[tid + 256];
    size_t base = (size_t)row * HH;
    __nv_bfloat16 h0 = __float2bfloat16(y0);
    __nv_bfloat16 h1 = __float2bfloat16(y1);
    hi[base + tid]       = h0;
    hi[base + tid + 256] = h1;
    lo[base + tid]       = __float2bfloat16(y0 - __bfloat162float(h0));
    lo[base + tid + 256] = __float2bfloat16(y1 - __bfloat162float(h1));
}

// ---------------- qkv split: Q/K -> [bh][s][d], V -> transposed [bh][d][k] ----------------
__global__ void qkv_split_kernel(const float* __restrict__ qkv) {
    int idx = blockIdx.x * blockDim.x + threadIdx.x;
    if (idx >= MM * 1536) return;
    int row = idx / 1536;
    int col = idx - row * 1536;
    int b = row >> 10, s = row & 1023;
    float v = qkv[idx];
    __nv_bfloat16 h = __float2bfloat16(v);
    __nv_bfloat16 l = __float2bfloat16(v - __bfloat162float(h));
    if (col < 512) {
        int hd = col >> 6, d = col & 63;
        size_t o = ((size_t)(b*8 + hd) * 1024 + s) * 64 + d;
        g_Qhi[o] = h; g_Qlo[o] = l;
    } else if (col < 1024) {
        int c = col - 512;
        int hd = c >> 6, d = c & 63;
        size_t o = ((size_t)(b*8 + hd) * 1024 + s) * 64 + d;
        g_Khi[o] = h; g_Klo[o] = l;
    } else {
        int c = col - 1024;
        int hd = c >> 6, d = c & 63;
        size_t o = (size_t)(b*8 + hd) * 131072 + (size_t)d * 1024 + s;
        g_Vthi[o] = h; g_Vtlo[o] = l;
    }
}

// ---------------- softmax over rows of 1024, fused P split ----------------
__global__ void softmax_split_kernel(const float* __restrict__ scores,
                                     __nv_bfloat16* __restrict__ Phi,
                                     __nv_bfloat16* __restrict__ Plo) {
    size_t row = blockIdx.x;
    const float* p = scores + row * 1024;
    int tid = threadIdx.x;
    float4 v = ((const float4*)p)[tid];
    float m = fmaxf(fmaxf(v.x, v.y), fmaxf(v.z, v.w));
    __shared__ float red[8];
    #pragma unroll
    for (int o = 16; o; o >>= 1) m = fmaxf(m, __shfl_xor_sync(0xffffffffu, m, o));
    if ((tid & 31) == 0) red[tid>>5] = m;
    __syncthreads();
    m = red[0];
    #pragma unroll
    for (int i = 1; i < 8; i++) m = fmaxf(m, red[i]);
    v.x = __expf(v.x - m); v.y = __expf(v.y - m);
    v.z = __expf(v.z - m); v.w = __expf(v.w - m);
    float sum = v.x + v.y + v.z + v.w;
    #pragma unroll
    for (int o = 16; o; o >>= 1) sum += __shfl_xor_sync(0xffffffffu, sum, o);
    __syncthreads();
    if ((tid & 31) == 0) red[tid>>5] = sum;
    __syncthreads();
    sum = 0.f;
    #pragma unroll
    for (int i = 0; i < 8; i++) sum += red[i];
    float inv = 1.f / sum;
    float pv[4] = { v.x*inv, v.y*inv, v.z*inv, v.w*inv };
    __nv_bfloat16 hb[4], lb[4];
    #pragma unroll
    for (int i = 0; i < 4; i++) {
        hb[i] = __float2bfloat16(pv[i]);
        lb[i] = __float2bfloat16(pv[i] - __bfloat162float(hb[i]));
    }
    *(uint2*)(Phi + row*1024 + tid*4) = *(uint2*)hb;
    *(uint2*)(Plo + row*1024 + tid*4) = *(uint2*)lb;
}

// ---------------- host orchestration ----------------
static void gemm_pair(const __nv_bfloat16* Ahi, const __nv_bfloat16* Alo,
                      const __nv_bfloat16* Bhi, const __nv_bfloat16* Blo,
                      const float* bias, float* C,
                      __nv_bfloat16* Chi, __nv_bfloat16* Clo,
                      int M, int N, int K, int lda, int ldb, int ldc, int nValid, float scale,
                      int gz, int zmod,
                      long long sA1, long long sA2, long long sB1, long long sB2,
                      long long sC1, long long sC2) {
    dim3 grid((N + 127) / 128, M / 128, gz);
    gemm_pair_mma<<<grid, 256, GP_SMEM>>>(Ahi, Alo, Bhi, Blo, bias, C, Chi, Clo,
                                          K, lda, ldb, ldc, nValid, scale,
                                          zmod, sA1, sA2, sB1, sB2, sC1, sC2);
}

extern "C" void kernel_launch(void* const* d_in, const int* in_sizes, int n_in,
                              void* d_out, int out_size) {
    const int*   x          = (const int*)  d_in[0];
    const float* emb        = (const float*)d_in[1];
    const float* W0         = (const float*)d_in[2];
    const float* b0         = (const float*)d_in[3];
    const float* tau0       = (const float*)d_in[4];
    const float* g0         = (const float*)d_in[5];
    const float* be0        = (const float*)d_in[6];
    const float* W1         = (const float*)d_in[7];
    const float* b1         = (const float*)d_in[8];
    const float* tau1       = (const float*)d_in[9];
    const float* g1         = (const float*)d_in[10];
    const float* be1        = (const float*)d_in[11];
    const float* attn_in_w  = (const float*)d_in[12];
    const float* attn_in_b  = (const float*)d_in[13];
    const float* attn_out_w = (const float*)d_in[14];
    const float* attn_out_b = (const float*)d_in[15];
    const float* out_w      = (const float*)d_in[16];
    const float* out_b      = (const float*)d_in[17];
    const float* log_dt     = (const float*)d_in[18];
    float* out = (float*)d_out;

    float *I, *sbuf, *qkv, *scores;
    __nv_bfloat16 *Ahi, *Alo, *A2hi, *A2lo, *Bhi, *Blo;
    __nv_bfloat16 *W0hi, *W0lo, *W1hi, *W1lo, *Wqhi, *Wqlo, *Wohi, *Wolo;
    __nv_bfloat16 *Qhi, *Qlo, *Khi, *Klo, *Vthi, *Vtlo, *Phi, *Plo;
    cudaGetSymbolAddress((void**)&I,      g_I);
    cudaGetSymbolAddress((void**)&sbuf,   g_s);
    cudaGetSymbolAddress((void**)&qkv,    g_qkv);
    cudaGetSymbolAddress((void**)&scores, g_scores);
    cudaGetSymbolAddress((void**)&Ahi,    g_Ahi);
    cudaGetSymbolAddress((void**)&Alo,    g_Alo);
    cudaGetSymbolAddress((void**)&A2hi,   g_A2hi);
    cudaGetSymbolAddress((void**)&A2lo,   g_A2lo);
    cudaGetSymbolAddress((void**)&Bhi,    g_Bhi);
    cudaGetSymbolAddress((void**)&Blo,    g_Blo);
    cudaGetSymbolAddress((void**)&W0hi,   g_W0hi);
    cudaGetSymbolAddress((void**)&W0lo,   g_W0lo);
    cudaGetSymbolAddress((void**)&W1hi,   g_W1hi);
    cudaGetSymbolAddress((void**)&W1lo,   g_W1lo);
    cudaGetSymbolAddress((void**)&Wqhi,   g_Wqhi);
    cudaGetSymbolAddress((void**)&Wqlo,   g_Wqlo);
    cudaGetSymbolAddress((void**)&Wohi,   g_Wohi);
    cudaGetSymbolAddress((void**)&Wolo,   g_Wolo);
    cudaGetSymbolAddress((void**)&Qhi,    g_Qhi);
    cudaGetSymbolAddress((void**)&Qlo,    g_Qlo);
    cudaGetSymbolAddress((void**)&Khi,    g_Khi);
    cudaGetSymbolAddress((void**)&Klo,    g_Klo);
    cudaGetSymbolAddress((void**)&Vthi,   g_Vthi);
    cudaGetSymbolAddress((void**)&Vtlo,   g_Vtlo);
    cudaGetSymbolAddress((void**)&Phi,    g_Phi);
    cudaGetSymbolAddress((void**)&Plo,    g_Plo);

    cudaFuncSetAttribute(gemm_pair_mma,
                         cudaFuncAttributeMaxDynamicSharedMemorySize, GP_SMEM);

    // weight splits
    split_bf16_kernel<<<(VV*HH + 255)/256, 256>>>(out_w, Bhi, Blo, VV*HH);
    split_bf16_kernel<<<(HH*EE + 255)/256, 256>>>(W0, W0hi, W0lo, HH*EE);
    split_bf16_kernel<<<(HH*HH + 255)/256, 256>>>(W1, W1hi, W1lo, HH*HH);
    split_bf16_kernel<<<(3*HH*HH + 255)/256, 256>>>(attn_in_w, Wqhi, Wqlo, 3*HH*HH);
    split_bf16_kernel<<<(HH*HH + 255)/256, 256>>>(attn_out_w, Wohi, Wolo, HH*HH);

    // 1. embedding + pos-enc -> splits
    embed_pe_split<<<(MM*EE)/256, 256>>>(x, emb, Ahi, Alo);

    // 2. liquid layer 0
    gemm_pair(Ahi, Alo, W0hi, W0lo, b0, I, nullptr, nullptr,
              MM, HH, EE, EE, EE, HH, HH, 1.f, 1, 1, 0,0,0,0,0,0);
    liquid_scan_par<<<dim3(BB, 32), 512>>>(I, tau0, log_dt, sbuf);
    layernorm_split<<<MM, 256>>>(sbuf, g0, be0, Ahi, Alo);

    // 3. liquid layer 1
    gemm_pair(Ahi, Alo, W1hi, W1lo, b1, I, nullptr, nullptr,
              MM, HH, HH, HH, HH, HH, HH, 1.f, 1, 1, 0,0,0,0,0,0);
    liquid_scan_par<<<dim3(BB, 32), 512>>>(I, tau1, log_dt, sbuf);
    layernorm_split<<<MM, 256>>>(sbuf, g1, be1, Ahi, Alo);

    // 4. MHA
    gemm_pair(Ahi, Alo, Wqhi, Wqlo, attn_in_b, qkv, nullptr, nullptr,
              MM, 3*HH, HH, HH, HH, 3*HH, 3*HH, 1.f, 1, 1, 0,0,0,0,0,0);
    qkv_split_kernel<<<(MM*1536 + 255)/256, 256>>>(qkv);

    // scores[bh] = Q[bh] @ K[bh]^T / 8
    gemm_pair(Qhi, Qlo, Khi, Klo, nullptr, scores, nullptr, nullptr,
              1024, 1024, 64, 64, 64, 1024, 1024, 0.125f,
              32, 32, 65536LL, 0, 65536LL, 0, 1LL<<20, 0);
    softmax_split_kernel<<<32*1024, 256>>>(scores, Phi, Plo);

    // attention out = P @ Vt^T -> fused split into A2
    gemm_pair(Phi, Plo, Vthi, Vtlo, nullptr, nullptr, A2hi, A2lo,
              1024, 128, 1024, 1024, 1024, 512, 64, 1.f,
              32, 8, 1LL<<20, 8LL<<20, 131072LL, 8LL*131072, 64LL, 524288LL);

    // out-projection -> fused split into Ahi/Alo (h2)
    gemm_pair(A2hi, A2lo, Wohi, Wolo, attn_out_b, nullptr, Ahi, Alo,
              MM, HH, HH, HH, HH, HH, HH, 1.f, 1, 1, 0,0,0,0,0,0);

    // 5. vocab projection
    gemm_pair(Ahi, Alo, Bhi, Blo, out_b, out, nullptr, nullptr,
              MM, VV, HH, HH, HH, VV, VV, 1.f, 1, 1, 0,0,0,0,0,0);
}

// round 7
// speedup vs baseline: 3.5776x; 1.2622x over previous
#include <cuda_runtime.h>
#include <cuda_bf16.h>
#include <cuda_fp16.h>
#include <cstdint>
#include <math.h>

#define BB 4
#define SS 1024
#define EE 512
#define HH 512
#define VV 32000
#define MM (BB*SS)      // 4096
#define NH 8
#define DH 64

// ---------------- scratch (static device memory; no allocations) ----------------
__device__ float g_I[MM*HH];
__device__ float g_s[MM*HH];
__device__ float g_qkv[MM*3*HH];
__device__ float g_scores[32*1024*1024];          // [bh][q][k] fp32
__device__ __nv_bfloat16 g_Ahi[MM*HH],  g_Alo[MM*HH];
__device__ __nv_bfloat16 g_A2hi[MM*HH], g_A2lo[MM*HH];
__device__ __half        g_H2hi[MM*HH], g_H2lo[MM*HH];   // h2 fp16 split (vocab A)
__device__ __nv_bfloat16 g_W0hi[HH*EE],  g_W0lo[HH*EE];
__device__ __nv_bfloat16 g_W1hi[HH*HH],  g_W1lo[HH*HH];
__device__ __nv_bfloat16 g_Wqhi[3*HH*HH], g_Wqlo[3*HH*HH];
__device__ __nv_bfloat16 g_Wohi[HH*HH],  g_Wolo[HH*HH];
__device__ __half        g_Bh[(size_t)VV*HH];            // vocab weights fp16
__device__ __nv_bfloat16 g_Qhi[32*1024*64], g_Qlo[32*1024*64];
__device__ __nv_bfloat16 g_Khi[32*1024*64], g_Klo[32*1024*64];
__device__ __half        g_Vth[32*128*1024];             // [bh][d pad128][k] fp16
__device__ __half        g_Phi[(size_t)32*1024*1024], g_Plo[(size_t)32*1024*1024];

__device__ __forceinline__ uint32_t smem_u32(const void* p) {
    uint32_t a;
    asm("{ .reg .u64 t; cvta.to.shared.u64 t, %1; cvt.u32.u64 %0, t; }" : "=r"(a) : "l"(p));
    return a;
}
__device__ __forceinline__ void cp_async16(uint32_t dst, const void* src) {
    asm volatile("cp.async.cg.shared.global [%0], [%1], 16;" :: "r"(dst), "l"(src));
}
__device__ __forceinline__ void ldsm_x4(uint32_t& r0, uint32_t& r1, uint32_t& r2, uint32_t& r3,
                                        uint32_t addr) {
    asm volatile("ldmatrix.sync.aligned.m8n8.x4.shared.b16 {%0,%1,%2,%3}, [%4];"
                 : "=r"(r0), "=r"(r1), "=r"(r2), "=r"(r3) : "r"(addr));
}
__device__ __forceinline__ void mma_bf16(float* c, const uint32_t* a, const uint32_t* b) {
    asm volatile("mma.sync.aligned.m16n8k16.row.col.f32.bf16.bf16.f32 "
                 "{%0,%1,%2,%3}, {%4,%5,%6,%7}, {%8,%9}, {%0,%1,%2,%3};"
                 : "+f"(c[0]), "+f"(c[1]), "+f"(c[2]), "+f"(c[3])
                 : "r"(a[0]), "r"(a[1]), "r"(a[2]), "r"(a[3]), "r"(b[0]), "r"(b[1]));
}
__device__ __forceinline__ void mma_f16(float* c, const uint32_t* a, const uint32_t* b) {
    asm volatile("mma.sync.aligned.m16n8k16.row.col.f32.f16.f16.f32 "
                 "{%0,%1,%2,%3}, {%4,%5,%6,%7}, {%8,%9}, {%0,%1,%2,%3};"
                 : "+f"(c[0]), "+f"(c[1]), "+f"(c[2]), "+f"(c[3])
                 : "r"(a[0]), "r"(a[1]), "r"(a[2]), "r"(a[3]), "r"(b[0]), "r"(b[1]));
}

// ---------------- embed + positional encoding -> bf16 hi/lo ----------------
__global__ void embed_pe_split(const int* __restrict__ x, const float* __restrict__ emb,
                               __nv_bfloat16* __restrict__ hi, __nv_bfloat16* __restrict__ lo) {
    int idx = blockIdx.x * blockDim.x + threadIdx.x;
    if (idx >= MM*EE) return;
    int m = idx >> 9;
    int e = idx & 511;
    int s = m & (SS - 1);
    int tok = x[m];
    int i2 = e & ~1;
    float freq = expf((float)i2 * (-9.210340371976184f / 512.0f));
    float ang = (float)s * freq;
    float pe = (e & 1) ? cosf(ang) : sinf(ang);
    float v = emb[(size_t)tok * EE + e] + pe;
    __nv_bfloat16 h = __float2bfloat16(v);
    hi[idx] = h;
    lo[idx] = __float2bfloat16(v - __bfloat162float(h));
}

__global__ void split_bf16_kernel(const float* __restrict__ in, __nv_bfloat16* __restrict__ hi,
                                  __nv_bfloat16* __restrict__ lo, int n) {
    int i = blockIdx.x * blockDim.x + threadIdx.x;
    if (i >= n) return;
    float x = in[i];
    __nv_bfloat16 h = __float2bfloat16(x);
    hi[i] = h;
    lo[i] = __float2bfloat16(x - __bfloat162float(h));
}

__global__ void convert_f16_kernel(const float* __restrict__ in, __half* __restrict__ out, int n) {
    int i = blockIdx.x * blockDim.x + threadIdx.x;
    if (i < n) out[i] = __float2half(in[i]);
}

// ============== bf16 3-term paired-operand NT GEMM ==============
// C = scale*(Ahi@Bhi^T + Ahi@Blo^T + Alo@Bhi^T) + bias
#define SPAD 40
#define TILE_E (128*SPAD)
#define GP_SMEM (2*4*TILE_E*2)    // 81920 bytes

__global__ __launch_bounds__(256, 2) void gemm_pair_mma(
    const __nv_bfloat16* __restrict__ Ahi_, const __nv_bfloat16* __restrict__ Alo_,
    const __nv_bfloat16* __restrict__ Bhi_, const __nv_bfloat16* __restrict__ Blo_,
    const float* __restrict__ bias, float* __restrict__ C_,
    __half* __restrict__ Fhi_, __half* __restrict__ Flo_,
    int K, int lda, int ldb, int ldc, int nValid, float scale,
    int zmod, long long sA1, long long sA2, long long sB1, long long sB2,
    long long sC1, long long sC2)
{
    extern __shared__ __align__(16) __nv_bfloat16 sm[];
    const uint32_t smb = smem_u32(sm);

    const int tid = threadIdx.x;
    const int lane = tid & 31;
    const int wid = tid >> 5;
    const int warp_m = wid >> 2;
    const int warp_n = wid & 3;
    const int bm = blockIdx.y * 128;
    const int bn = blockIdx.x * 128;

    const int z = blockIdx.z;
    const int z1 = z % zmod, z2 = z / zmod;
    const long long offA = (long long)z1 * sA1 + (long long)z2 * sA2;
    const long long offB = (long long)z1 * sB1 + (long long)z2 * sB2;
    const long long offC = (long long)z1 * sC1 + (long long)z2 * sC2;

    const __nv_bfloat16* pA[2] = { Ahi_ + offA + (size_t)bm * lda,
                                   Alo_ + offA + (size_t)bm * lda };
    const __nv_bfloat16* pB[2] = { Bhi_ + offB + (size_t)bn * ldb,
                                   Blo_ + offB + (size_t)bn * ldb };

    float acc[4][4][4];
    #pragma unroll
    for (int i = 0; i < 4; i++)
        #pragma unroll
        for (int j = 0; j < 4; j++)
            #pragma unroll
            for (int r = 0; r < 4; r++) acc[i][j][r] = 0.f;

    const int lrow = tid >> 2;
    const int lcol = (tid & 3) * 8;
    const int nstages = K >> 5;

    auto prefetch = [&](int s) {
        const int gk = s * 32;
        const uint32_t base = smb + (uint32_t)((s & 1) * 4 * TILE_E) * 2;
        #pragma unroll
        for (int t = 0; t < 4; t++) {
            const __nv_bfloat16* src = (t < 2 ? pA[t] : pB[t-2]) + gk + lcol;
            const int ld = (t < 2) ? lda : ldb;
            #pragma unroll
            for (int c = 0; c < 2; c++) {
                int row = lrow + c * 64;
                cp_async16(base + (uint32_t)(t * TILE_E + row * SPAD + lcol) * 2,
                           src + (size_t)row * ld);
            }
        }
    };

    prefetch(0);
    asm volatile("cp.async.commit_group;");

    for (int s = 0; s < nstages; s++) {
        if (s < nstages - 1) {
            prefetch(s + 1);
            asm volatile("cp.async.commit_group;");
            asm volatile("cp.async.wait_group 1;");
        } else {
            asm volatile("cp.async.wait_group 0;");
        }
        __syncthreads();

        const uint32_t stg = smb + (uint32_t)((s & 1) * 4 * TILE_E) * 2;
        const uint32_t tAhi = stg;
        const uint32_t tAlo = stg + TILE_E * 2;
        const uint32_t tBhi = stg + 2 * TILE_E * 2;
        const uint32_t tBlo = stg + 3 * TILE_E * 2;
        const int q  = lane >> 3;
        const int rr = lane & 7;

        #pragma unroll
        for (int ko = 0; ko < 32; ko += 16) {
            const int arow = warp_m * 64 + (q & 1) * 8 + rr;
            const int acol = ko + (q >> 1) * 8;
            const int brow = warp_n * 32 + (q >> 1) * 8 + rr;
            const int bcol = ko + (q & 1) * 8;

            uint32_t aH[4][4];
            #pragma unroll
            for (int i = 0; i < 4; i++)
                ldsm_x4(aH[i][0], aH[i][1], aH[i][2], aH[i][3],
                        tAhi + (uint32_t)((arow + i * 16) * SPAD + acol) * 2);
            uint32_t bH[4][2], bL[4][2];
            #pragma unroll
            for (int j = 0; j < 2; j++) {
                ldsm_x4(bH[2*j][0], bH[2*j][1], bH[2*j+1][0], bH[2*j+1][1],
                        tBhi + (uint32_t)((brow + j * 16) * SPAD + bcol) * 2);
                ldsm_x4(bL[2*j][0], bL[2*j][1], bL[2*j+1][0], bL[2*j+1][1],
                        tBlo + (uint32_t)((brow + j * 16) * SPAD + bcol) * 2);
            }
            #pragma unroll
            for (int i = 0; i < 4; i++)
                #pragma unroll
                for (int j = 0; j < 4; j++)
                    mma_bf16(acc[i][j], aH[i], bH[j]);
            #pragma unroll
            for (int i = 0; i < 4; i++)
                #pragma unroll
                for (int j = 0; j < 4; j++)
                    mma_bf16(acc[i][j], aH[i], bL[j]);
            uint32_t aL[4][4];
            #pragma unroll
            for (int i = 0; i < 4; i++)
                ldsm_x4(aL[i][0], aL[i][1], aL[i][2], aL[i][3],
                        tAlo + (uint32_t)((arow + i * 16) * SPAD + acol) * 2);
            #pragma unroll
            for (int i = 0; i < 4; i++)
                #pragma unroll
                for (int j = 0; j < 4; j++)
                    mma_bf16(acc[i][j], aL[i], bH[j]);
        }
        __syncthreads();
    }

    // epilogue: fp32, or fused fp16 hi/lo split
    const int gr = lane >> 2;
    const int gc = (lane & 3) * 2;
    float* C = C_ ? C_ + offC : nullptr;
    __half* Fhi = Fhi_ ? Fhi_ + offC : nullptr;
    __half* Flo = Flo_ ? Flo_ + offC : nullptr;

    #pragma unroll
    for (int j = 0; j < 4; j++) {
        int col = bn + warp_n * 32 + j * 8 + gc;
        if (col >= nValid) continue;
        float2 bv = make_float2(0.f, 0.f);
        if (bias) bv = *(const float2*)(bias + col);
        #pragma unroll
        for (int i = 0; i < 4; i++) {
            int row0 = bm + warp_m * 64 + i * 16 + gr;
            float v00 = acc[i][j][0]*scale + bv.x, v01 = acc[i][j][1]*scale + bv.y;
            float v10 = acc[i][j][2]*scale + bv.x, v11 = acc[i][j][3]*scale + bv.y;
            size_t o0 = (size_t)row0 * ldc + col;
            size_t o1 = (size_t)(row0 + 8) * ldc + col;
            if (Fhi) {
                __half h;
                h = __float2half(v00); Fhi[o0]   = h; Flo[o0]   = __float2half(v00 - __half2float(h));
                h = __float2half(v01); Fhi[o0+1] = h; Flo[o0+1] = __float2half(v01 - __half2float(h));
                h = __float2half(v10); Fhi[o1]   = h; Flo[o1]   = __float2half(v10 - __half2float(h));
                h = __float2half(v11); Fhi[o1+1] = h; Flo[o1+1] = __float2half(v11 - __half2float(h));
            } else {
                *(float2*)(C + o0) = make_float2(v00, v01);
                *(float2*)(C + o1) = make_float2(v10, v11);
            }
        }
    }
}

// ============== fp16 2-term NT GEMM: C = scale*((Ahi+Alo)@B^T) + bias ==============
// 3 tiles per stage (Ahi, Alo, B), 2 mma products per (i,j,ko).
#define GF_SMEM (2*3*TILE_E*2)    // 61440 bytes

__global__ __launch_bounds__(256, 2) void gemm_f16_mma(
    const __half* __restrict__ Ahi_, const __half* __restrict__ Alo_,
    const __half* __restrict__ B_,
    const float* __restrict__ bias, float* __restrict__ C_,
    __nv_bfloat16* __restrict__ Chi_, __nv_bfloat16* __restrict__ Clo_,
    int K, int lda, int ldb, int ldc, int nValid, float scale,
    int zmod, long long sA1, long long sA2, long long sB1, long long sB2,
    long long sC1, long long sC2)
{
    extern __shared__ __align__(16) __half smh[];
    const uint32_t smb = smem_u32(smh);

    const int tid = threadIdx.x;
    const int lane = tid & 31;
    const int wid = tid >> 5;
    const int warp_m = wid >> 2;
    const int warp_n = wid & 3;
    const int bm = blockIdx.y * 128;
    const int bn = blockIdx.x * 128;

    const int z = blockIdx.z;
    const int z1 = z % zmod, z2 = z / zmod;
    const long long offA = (long long)z1 * sA1 + (long long)z2 * sA2;
    const long long offB = (long long)z1 * sB1 + (long long)z2 * sB2;
    const long long offC = (long long)z1 * sC1 + (long long)z2 * sC2;

    const __half* pT[3] = { Ahi_ + offA + (size_t)bm * lda,
                            Alo_ + offA + (size_t)bm * lda,
                            B_   + offB + (size_t)bn * ldb };

    float acc[4][4][4];
    #pragma unroll
    for (int i = 0; i < 4; i++)
        #pragma unroll
        for (int j = 0; j < 4; j++)
            #pragma unroll
            for (int r = 0; r < 4; r++) acc[i][j][r] = 0.f;

    const int lrow = tid >> 2;
    const int lcol = (tid & 3) * 8;
    const int nstages = K >> 5;

    auto prefetch = [&](int s) {
        const int gk = s * 32;
        const uint32_t base = smb + (uint32_t)((s & 1) * 3 * TILE_E) * 2;
        #pragma unroll
        for (int t = 0; t < 3; t++) {
            const __half* src = pT[t] + gk + lcol;
            const int ld = (t < 2) ? lda : ldb;
            #pragma unroll
            for (int c = 0; c < 2; c++) {
                int row = lrow + c * 64;
                cp_async16(base + (uint32_t)(t * TILE_E + row * SPAD + lcol) * 2,
                           src + (size_t)row * ld);
            }
        }
    };

    prefetch(0);
    asm volatile("cp.async.commit_group;");

    for (int s = 0; s < nstages; s++) {
        if (s < nstages - 1) {
            prefetch(s + 1);
            asm volatile("cp.async.commit_group;");
            asm volatile("cp.async.wait_group 1;");
        } else {
            asm volatile("cp.async.wait_group 0;");
        }
        __syncthreads();

        const uint32_t stg = smb + (uint32_t)((s & 1) * 3 * TILE_E) * 2;
        const uint32_t tAhi = stg;
        const uint32_t tAlo = stg + TILE_E * 2;
        const uint32_t tB   = stg + 2 * TILE_E * 2;
        const int q  = lane >> 3;
        const int rr = lane & 7;

        #pragma unroll
        for (int ko = 0; ko < 32; ko += 16) {
            const int arow = warp_m * 64 + (q & 1) * 8 + rr;
            const int acol = ko + (q >> 1) * 8;
            const int brow = warp_n * 32 + (q >> 1) * 8 + rr;
            const int bcol = ko + (q & 1) * 8;

            uint32_t b[4][2];
            #pragma unroll
            for (int j = 0; j < 2; j++)
                ldsm_x4(b[2*j][0], b[2*j][1], b[2*j+1][0], b[2*j+1][1],
                        tB + (uint32_t)((brow + j * 16) * SPAD + bcol) * 2);
            uint32_t aH[4][4];
            #pragma unroll
            for (int i = 0; i < 4; i++)
                ldsm_x4(aH[i][0], aH[i][1], aH[i][2], aH[i][3],
                        tAhi + (uint32_t)((arow + i * 16) * SPAD + acol) * 2);
            #pragma unroll
            for (int i = 0; i < 4; i++)
                #pragma unroll
                for (int j = 0; j < 4; j++)
                    mma_f16(acc[i][j], aH[i], b[j]);
            uint32_t aL[4][4];
            #pragma unroll
            for (int i = 0; i < 4; i++)
                ldsm_x4(aL[i][0], aL[i][1], aL[i][2], aL[i][3],
                        tAlo + (uint32_t)((arow + i * 16) * SPAD + acol) * 2);
            #pragma unroll
            for (int i = 0; i < 4; i++)
                #pragma unroll
                for (int j = 0; j < 4; j++)
                    mma_f16(acc[i][j], aL[i], b[j]);
        }
        __syncthreads();
    }

    const int gr = lane >> 2;
    const int gc = (lane & 3) * 2;
    float* C = C_ ? C_ + offC : nullptr;
    __nv_bfloat16* Chi = Chi_ ? Chi_ + offC : nullptr;
    __nv_bfloat16* Clo = Clo_ ? Clo_ + offC : nullptr;

    #pragma unroll
    for (int j = 0; j < 4; j++) {
        int col = bn + warp_n * 32 + j * 8 + gc;
        if (col >= nValid) continue;
        float2 bv = make_float2(0.f, 0.f);
        if (bias) bv = *(const float2*)(bias + col);
        #pragma unroll
        for (int i = 0; i < 4; i++) {
            int row0 = bm + warp_m * 64 + i * 16 + gr;
            float v00 = acc[i][j][0]*scale + bv.x, v01 = acc[i][j][1]*scale + bv.y;
            float v10 = acc[i][j][2]*scale + bv.x, v11 = acc[i][j][3]*scale + bv.y;
            size_t o0 = (size_t)row0 * ldc + col;
            size_t o1 = (size_t)(row0 + 8) * ldc + col;
            if (Chi) {
                __nv_bfloat16 h;
                h = __float2bfloat16(v00); Chi[o0]   = h; Clo[o0]   = __float2bfloat16(v00 - __bfloat162float(h));
                h = __float2bfloat16(v01); Chi[o0+1] = h; Clo[o0+1] = __float2bfloat16(v01 - __bfloat162float(h));
                h = __float2bfloat16(v10); Chi[o1]   = h; Clo[o1]   = __float2bfloat16(v10 - __bfloat162float(h));
                h = __float2bfloat16(v11); Chi[o1+1] = h; Clo[o1+1] = __float2bfloat16(v11 - __bfloat162float(h));
            } else {
                *(float2*)(C + o0) = make_float2(v00, v01);
                *(float2*)(C + o1) = make_float2(v10, v11);
            }
        }
    }
}

// ---------------- parallel liquid scan (exact affine chunk decomposition) ----------------
__global__ __launch_bounds__(512) void liquid_scan_par(
    const float* __restrict__ I, const float* __restrict__ tau,
    const float* __restrict__ log_dt, float* __restrict__ out) {
    const int b = blockIdx.x;
    const int lg = blockIdx.y;
    const int lane16 = threadIdx.x & 15;
    const int chunk  = threadIdx.x >> 4;
    const int o = lg * 16 + lane16;
    const float dt = expf(log_dt[0]);
    const float r = dt / tau[o];
    const float a = 1.f - r;
    const float* Ib = I + (size_t)b * SS * HH + o;
    const int t0 = chunk * 32;

    float Iv[32];
    #pragma unroll
    for (int i = 0; i < 32; i++) Iv[i] = Ib[(size_t)(t0 + i) * HH];

    float u = 0.f, s = 0.f;
    #pragma unroll
    for (int i = 0; i < 32; i++) {
        float sn = s + r * (u - s);
        u = u + r * (Iv[i] - u);
        s = sn;
    }
    __shared__ float2 dloc[32][16];
    __shared__ float2 st[32][16];
    dloc[chunk][lane16] = make_float2(u, s);
    __syncthreads();

    if (chunk == 0) {
        float a2 = a*a, a4 = a2*a2, a8 = a4*a4, a16 = a8*a8;
        float a32v = a16*a16;
        float a31 = a16*a8*a4*a2*a;
        float c32 = 32.f * r * a31;
        float2 x = make_float2(0.f, 0.f);
        #pragma unroll
        for (int c = 0; c < 32; c++) {
            st[c][lane16] = x;
            float2 d = dloc[c][lane16];
            float nu = a32v * x.x + d.x;
            float ns = c32 * x.x + a32v * x.y + d.y;
            x = make_float2(nu, ns);
        }
    }
    __syncthreads();

    float2 x0 = st[chunk][lane16];
    u = x0.x; s = x0.y;
    float* Ob = out + (size_t)b * SS * HH + o;
    #pragma unroll
    for (int i = 0; i < 32; i++) {
        float sn = s + r * (u - s);
        u = u + r * (Iv[i] - u);
        s = sn;
        Ob[(size_t)(t0 + i) * HH] = tanhf(s);
    }
}

// ---------------- layernorm -> bf16 hi/lo ----------------
__global__ void layernorm_split(const float* __restrict__ in, const float* __restrict__ g,
                                const float* __restrict__ be,
                                __nv_bfloat16* __restrict__ hi, __nv_bfloat16* __restrict__ lo) {
    int row = blockIdx.x;
    int tid = threadIdx.x;
    const float* p = in + (size_t)row * HH;
    float a = p[tid], b = p[tid + 256];
    float sum = a + b, sq = a*a + b*b;
    __shared__ float s1[8], s2[8];
    #pragma unroll
    for (int o = 16; o; o >>= 1) {
        sum += __shfl_xor_sync(0xffffffffu, sum, o);
        sq  += __shfl_xor_sync(0xffffffffu, sq,  o);
    }
    if ((tid & 31) == 0) { s1[tid>>5] = sum; s2[tid>>5] = sq; }
    __syncthreads();
    sum = 0.f; sq = 0.f;
    #pragma unroll
    for (int i = 0; i < 8; i++) { sum += s1[i]; sq += s2[i]; }
    float mean = sum * (1.f/512.f);
    float var  = sq * (1.f/512.f) - mean*mean;
    float inv = rsqrtf(var + 1e-5f);
    float y0 = (a - mean) * inv * g[tid]       + be[tid];
    float y1 = (b - mean) * inv * g[tid + 256] + be[tid + 256];
    size_t base = (size_t)row * HH;
    __nv_bfloat16 h0 = __float2bfloat16(y0);
    __nv_bfloat16 h1 = __float2bfloat16(y1);
    hi[base + tid]       = h0;
    hi[base + tid + 256] = h1;
    lo[base + tid]       = __float2bfloat16(y0 - __bfloat162float(h0));
    lo[base + tid + 256] = __float2bfloat16(y1 - __bfloat162float(h1));
}

// ---------------- qkv split: Q/K bf16 -> [bh][s][d], V fp16 transposed [bh][d][k] ----------------
__global__ void qkv_split_kernel(const float* __restrict__ qkv) {
    int idx = blockIdx.x * blockDim.x + threadIdx.x;
    if (idx >= MM * 1536) return;
    int row = idx / 1536;
    int col = idx - row * 1536;
    int b = row >> 10, s = row & 1023;
    float v = qkv[idx];
    if (col < 512) {
        int hd = col >> 6, d = col & 63;
        size_t o = ((size_t)(b*8 + hd) * 1024 + s) * 64 + d;
        __nv_bfloat16 h = __float2bfloat16(v);
        g_Qhi[o] = h; g_Qlo[o] = __float2bfloat16(v - __bfloat162float(h));
    } else if (col < 1024) {
        int c = col - 512;
        int hd = c >> 6, d = c & 63;
        size_t o = ((size_t)(b*8 + hd) * 1024 + s) * 64 + d;
        __nv_bfloat16 h = __float2bfloat16(v);
        g_Khi[o] = h; g_Klo[o] = __float2bfloat16(v - __bfloat162float(h));
    } else {
        int c = col - 1024;
        int hd = c >> 6, d = c & 63;
        size_t o = (size_t)(b*8 + hd) * 131072 + (size_t)d * 1024 + s;
        g_Vth[o] = __float2half(v);
    }
}

// ---------------- softmax over rows of 1024, fused fp16 P split ----------------
__global__ void softmax_split_kernel(const float* __restrict__ scores,
                                     __half* __restrict__ Phi,
                                     __half* __restrict__ Plo) {
    size_t row = blockIdx.x;
    const float* p = scores + row * 1024;
    int tid = threadIdx.x;
    float4 v = ((const float4*)p)[tid];
    float m = fmaxf(fmaxf(v.x, v.y), fmaxf(v.z, v.w));
    __shared__ float red[8];
    #pragma unroll
    for (int o = 16; o; o >>= 1) m = fmaxf(m, __shfl_xor_sync(0xffffffffu, m, o));
    if ((tid & 31) == 0) red[tid>>5] = m;
    __syncthreads();
    m = red[0];
    #pragma unroll
    for (int i = 1; i < 8; i++) m = fmaxf(m, red[i]);
    v.x = __expf(v.x - m); v.y = __expf(v.y - m);
    v.z = __expf(v.z - m); v.w = __expf(v.w - m);
    float sum = v.x + v.y + v.z + v.w;
    #pragma unroll
    for (int o = 16; o; o >>= 1) sum += __shfl_xor_sync(0xffffffffu, sum, o);
    __syncthreads();
    if ((tid & 31) == 0) red[tid>>5] = sum;
    __syncthreads();
    sum = 0.f;
    #pragma unroll
    for (int i = 0; i < 8; i++) sum += red[i];
    float inv = 1.f / sum;
    float pv[4] = { v.x*inv, v.y*inv, v.z*inv, v.w*inv };
    __half hb[4], lb[4];
    #pragma unroll
    for (int i = 0; i < 4; i++) {
        hb[i] = __float2half(pv[i]);
        lb[i] = __float2half(pv[i] - __half2float(hb[i]));
    }
    *(uint2*)(Phi + row*1024 + tid*4) = *(uint2*)hb;
    *(uint2*)(Plo + row*1024 + tid*4) = *(uint2*)lb;
}

// ---------------- host orchestration ----------------
extern "C" void kernel_launch(void* const* d_in, const int* in_sizes, int n_in,
                              void* d_out, int out_size) {
    const int*   x          = (const int*)  d_in[0];
    const float* emb        = (const float*)d_in[1];
    const float* W0         = (const float*)d_in[2];
    const float* b0         = (const float*)d_in[3];
    const float* tau0       = (const float*)d_in[4];
    const float* g0         = (const float*)d_in[5];
    const float* be0        = (const float*)d_in[6];
    const float* W1         = (const float*)d_in[7];
    const float* b1         = (const float*)d_in[8];
    const float* tau1       = (const float*)d_in[9];
    const float* g1         = (const float*)d_in[10];
    const float* be1        = (const float*)d_in[11];
    const float* attn_in_w  = (const float*)d_in[12];
    const float* attn_in_b  = (const float*)d_in[13];
    const float* attn_out_w = (const float*)d_in[14];
    const float* attn_out_b = (const float*)d_in[15];
    const float* out_w      = (const float*)d_in[16];
    const float* out_b      = (const float*)d_in[17];
    const float* log_dt     = (const float*)d_in[18];
    float* out = (float*)d_out;

    float *I, *sbuf, *qkv, *scores;
    __nv_bfloat16 *Ahi, *Alo, *A2hi, *A2lo;
    __nv_bfloat16 *W0hi, *W0lo, *W1hi, *W1lo, *Wqhi, *Wqlo, *Wohi, *Wolo;
    __nv_bfloat16 *Qhi, *Qlo, *Khi, *Klo;
    __half *H2hi, *H2lo, *Bh, *Vth, *Phi, *Plo;
    cudaGetSymbolAddress((void**)&I,      g_I);
    cudaGetSymbolAddress((void**)&sbuf,   g_s);
    cudaGetSymbolAddress((void**)&qkv,    g_qkv);
    cudaGetSymbolAddress((void**)&scores, g_scores);
    cudaGetSymbolAddress((void**)&Ahi,    g_Ahi);
    cudaGetSymbolAddress((void**)&Alo,    g_Alo);
    cudaGetSymbolAddress((void**)&A2hi,   g_A2hi);
    cudaGetSymbolAddress((void**)&A2lo,   g_A2lo);
    cudaGetSymbolAddress((void**)&H2hi,   g_H2hi);
    cudaGetSymbolAddress((void**)&H2lo,   g_H2lo);
    cudaGetSymbolAddress((void**)&Bh,     g_Bh);
    cudaGetSymbolAddress((void**)&W0hi,   g_W0hi);
    cudaGetSymbolAddress((void**)&W0lo,   g_W0lo);
    cudaGetSymbolAddress((void**)&W1hi,   g_W1hi);
    cudaGetSymbolAddress((void**)&W1lo,   g_W1lo);
    cudaGetSymbolAddress((void**)&Wqhi,   g_Wqhi);
    cudaGetSymbolAddress((void**)&Wqlo,   g_Wqlo);
    cudaGetSymbolAddress((void**)&Wohi,   g_Wohi);
    cudaGetSymbolAddress((void**)&Wolo,   g_Wolo);
    cudaGetSymbolAddress((void**)&Qhi,    g_Qhi);
    cudaGetSymbolAddress((void**)&Qlo,    g_Qlo);
    cudaGetSymbolAddress((void**)&Khi,    g_Khi);
    cudaGetSymbolAddress((void**)&Klo,    g_Klo);
    cudaGetSymbolAddress((void**)&Vth,    g_Vth);
    cudaGetSymbolAddress((void**)&Phi,    g_Phi);
    cudaGetSymbolAddress((void**)&Plo,    g_Plo);

    cudaFuncSetAttribute(gemm_pair_mma,
                         cudaFuncAttributeMaxDynamicSharedMemorySize, GP_SMEM);
    cudaFuncSetAttribute(gemm_f16_mma,
                         cudaFuncAttributeMaxDynamicSharedMemorySize, GF_SMEM);

    // weight preprocessing
    convert_f16_kernel<<<(VV*HH + 255)/256, 256>>>(out_w, Bh, VV*HH);
    split_bf16_kernel<<<(HH*EE + 255)/256, 256>>>(W0, W0hi, W0lo, HH*EE);
    split_bf16_kernel<<<(HH*HH + 255)/256, 256>>>(W1, W1hi, W1lo, HH*HH);
    split_bf16_kernel<<<(3*HH*HH + 255)/256, 256>>>(attn_in_w, Wqhi, Wqlo, 3*HH*HH);
    split_bf16_kernel<<<(HH*HH + 255)/256, 256>>>(attn_out_w, Wohi, Wolo, HH*HH);

    // 1. embedding + pos-enc -> bf16 splits
    embed_pe_split<<<(MM*EE)/256, 256>>>(x, emb, Ahi, Alo);

    // 2. liquid layer 0 (bf16 3-term)
    gemm_pair_mma<<<dim3(4, 32, 1), 256, GP_SMEM>>>(
        Ahi, Alo, W0hi, W0lo, b0, I, nullptr, nullptr,
        EE, EE, EE, HH, HH, 1.f, 1, 0,0,0,0,0,0);
    liquid_scan_par<<<dim3(BB, 32), 512>>>(I, tau0, log_dt, sbuf);
    layernorm_split<<<MM, 256>>>(sbuf, g0, be0, Ahi, Alo);

    // 3. liquid layer 1
    gemm_pair_mma<<<dim3(4, 32, 1), 256, GP_SMEM>>>(
        Ahi, Alo, W1hi, W1lo, b1, I, nullptr, nullptr,
        HH, HH, HH, HH, HH, 1.f, 1, 0,0,0,0,0,0);
    liquid_scan_par<<<dim3(BB, 32), 512>>>(I, tau1, log_dt, sbuf);
    layernorm_split<<<MM, 256>>>(sbuf, g1, be1, Ahi, Alo);

    // 4. MHA: qkv projection (bf16 3-term)
    gemm_pair_mma<<<dim3(12, 32, 1), 256, GP_SMEM>>>(
        Ahi, Alo, Wqhi, Wqlo, attn_in_b, qkv, nullptr, nullptr,
        HH, HH, HH, 3*HH, 3*HH, 1.f, 1, 0,0,0,0,0,0);
    qkv_split_kernel<<<(MM*1536 + 255)/256, 256>>>(qkv);

    // scores = Q @ K^T / 8 (bf16 3-term, batched)
    gemm_pair_mma<<<dim3(8, 8, 32), 256, GP_SMEM>>>(
        Qhi, Qlo, Khi, Klo, nullptr, scores, nullptr, nullptr,
        64, 64, 64, 1024, 1024, 0.125f,
        32, 65536LL, 0, 65536LL, 0, 1LL<<20, 0);
    softmax_split_kernel<<<32*1024, 256>>>(scores, Phi, Plo);

    // AV = P @ Vt^T (fp16 2-term) -> fused bf16 split into A2
    gemm_f16_mma<<<dim3(1, 8, 32), 256, GF_SMEM>>>(
        Phi, Plo, Vth, nullptr, nullptr, A2hi, A2lo,
        1024, 1024, 1024, 512, 64, 1.f,
        8, 1LL<<20, 8LL<<20, 131072LL, 8LL*131072, 64LL, 524288LL);

    // out-projection (bf16 3-term) -> fused fp16 split into H2
    gemm_pair_mma<<<dim3(4, 32, 1), 256, GP_SMEM>>>(
        A2hi, A2lo, Wohi, Wolo, attn_out_b, nullptr, H2hi, H2lo,
        HH, HH, HH, HH, HH, 1.f, 1, 0,0,0,0,0,0);

    // 5. vocab projection (fp16 2-term)
    gemm_f16_mma<<<dim3(VV/128, MM/128, 1), 256, GF_SMEM>>>(
        H2hi, H2lo, Bh, out_b, out, nullptr, nullptr,
        HH, HH, HH, VV, VV, 1.f, 1, 0,0,0,0,0,0);
}

// round 8
// speedup vs baseline: 4.7531x; 1.3286x over previous
#include <cuda_runtime.h>
#include <cuda_bf16.h>
#include <cuda_fp16.h>
#include <cstdint>
#include <math.h>

#define BB 4
#define SS 1024
#define EE 512
#define HH 512
#define VV 32000
#define MM (BB*SS)      // 4096
#define NH 8
#define DH 64

// ---------------- scratch (static device memory; no allocations) ----------------
__device__ float g_I[MM*HH];
__device__ float g_s[MM*HH];
__device__ float g_qkv[MM*3*HH];
__device__ float g_scores[32*1024*1024];          // [bh][q][k] fp32
__device__ __nv_bfloat16 g_Ahi[MM*HH],  g_Alo[MM*HH];
__device__ __nv_bfloat16 g_A2hi[MM*HH], g_A2lo[MM*HH];
__device__ __half        g_H2hi[MM*HH], g_H2lo[MM*HH];   // h2 fp16 (vocab A)
__device__ __nv_bfloat16 g_W0hi[HH*EE],  g_W0lo[HH*EE];
__device__ __nv_bfloat16 g_W1hi[HH*HH],  g_W1lo[HH*HH];
__device__ __nv_bfloat16 g_Wqhi[3*HH*HH], g_Wqlo[3*HH*HH];
__device__ __nv_bfloat16 g_Wohi[HH*HH],  g_Wolo[HH*HH];
__device__ __half        g_Bh[(size_t)VV*HH];            // vocab weights fp16
__device__ __nv_bfloat16 g_Qhi[32*1024*64], g_Qlo[32*1024*64];
__device__ __nv_bfloat16 g_Khi[32*1024*64], g_Klo[32*1024*64];
__device__ __half        g_Vth[32*128*1024];             // [bh][d pad128][k] fp16
__device__ __half        g_Phi[(size_t)32*1024*1024], g_Plo[(size_t)32*1024*1024];

__device__ __forceinline__ uint32_t smem_u32(const void* p) {
    uint32_t a;
    asm("{ .reg .u64 t; cvta.to.shared.u64 t, %1; cvt.u32.u64 %0, t; }" : "=r"(a) : "l"(p));
    return a;
}
__device__ __forceinline__ void cp_async16(uint32_t dst, const void* src) {
    asm volatile("cp.async.cg.shared.global [%0], [%1], 16;" :: "r"(dst), "l"(src));
}
__device__ __forceinline__ void ldsm_x4(uint32_t& r0, uint32_t& r1, uint32_t& r2, uint32_t& r3,
                                        uint32_t addr) {
    asm volatile("ldmatrix.sync.aligned.m8n8.x4.shared.b16 {%0,%1,%2,%3}, [%4];"
                 : "=r"(r0), "=r"(r1), "=r"(r2), "=r"(r3) : "r"(addr));
}
__device__ __forceinline__ void mma_bf16(float* c, const uint32_t* a, const uint32_t* b) {
    asm volatile("mma.sync.aligned.m16n8k16.row.col.f32.bf16.bf16.f32 "
                 "{%0,%1,%2,%3}, {%4,%5,%6,%7}, {%8,%9}, {%0,%1,%2,%3};"
                 : "+f"(c[0]), "+f"(c[1]), "+f"(c[2]), "+f"(c[3])
                 : "r"(a[0]), "r"(a[1]), "r"(a[2]), "r"(a[3]), "r"(b[0]), "r"(b[1]));
}
__device__ __forceinline__ void mma_f16(float* c, const uint32_t* a, const uint32_t* b) {
    asm volatile("mma.sync.aligned.m16n8k16.row.col.f32.f16.f16.f32 "
                 "{%0,%1,%2,%3}, {%4,%5,%6,%7}, {%8,%9}, {%0,%1,%2,%3};"
                 : "+f"(c[0]), "+f"(c[1]), "+f"(c[2]), "+f"(c[3])
                 : "r"(a[0]), "r"(a[1]), "r"(a[2]), "r"(a[3]), "r"(b[0]), "r"(b[1]));
}

// ---------------- embed + positional encoding -> bf16 hi/lo ----------------
__global__ void embed_pe_split(const int* __restrict__ x, const float* __restrict__ emb,
                               __nv_bfloat16* __restrict__ hi, __nv_bfloat16* __restrict__ lo) {
    int idx = blockIdx.x * blockDim.x + threadIdx.x;
    if (idx >= MM*EE) return;
    int m = idx >> 9;
    int e = idx & 511;
    int s = m & (SS - 1);
    int tok = x[m];
    int i2 = e & ~1;
    float freq = expf((float)i2 * (-9.210340371976184f / 512.0f));
    float ang = (float)s * freq;
    float pe = (e & 1) ? cosf(ang) : sinf(ang);
    float v = emb[(size_t)tok * EE + e] + pe;
    __nv_bfloat16 h = __float2bfloat16(v);
    hi[idx] = h;
    lo[idx] = __float2bfloat16(v - __bfloat162float(h));
}

__global__ void split_bf16_kernel(const float* __restrict__ in, __nv_bfloat16* __restrict__ hi,
                                  __nv_bfloat16* __restrict__ lo, int n) {
    int i = blockIdx.x * blockDim.x + threadIdx.x;
    if (i >= n) return;
    float x = in[i];
    __nv_bfloat16 h = __float2bfloat16(x);
    hi[i] = h;
    lo[i] = __float2bfloat16(x - __bfloat162float(h));
}

__global__ void convert_f16_kernel(const float* __restrict__ in, __half* __restrict__ out, int n) {
    int i = blockIdx.x * blockDim.x + threadIdx.x;
    if (i < n) out[i] = __float2half(in[i]);
}

// ============== bf16 3-term paired-operand NT GEMM ==============
#define SPAD 40
#define TILE_E (128*SPAD)
#define GP_SMEM (2*4*TILE_E*2)    // 81920 bytes

__global__ __launch_bounds__(256, 2) void gemm_pair_mma(
    const __nv_bfloat16* __restrict__ Ahi_, const __nv_bfloat16* __restrict__ Alo_,
    const __nv_bfloat16* __restrict__ Bhi_, const __nv_bfloat16* __restrict__ Blo_,
    const float* __restrict__ bias, float* __restrict__ C_,
    __half* __restrict__ Fhi_, __half* __restrict__ Flo_,
    int K, int lda, int ldb, int ldc, int nValid, float scale,
    int zmod, long long sA1, long long sA2, long long sB1, long long sB2,
    long long sC1, long long sC2)
{
    extern __shared__ __align__(16) __nv_bfloat16 sm[];
    const uint32_t smb = smem_u32(sm);

    const int tid = threadIdx.x;
    const int lane = tid & 31;
    const int wid = tid >> 5;
    const int warp_m = wid >> 2;
    const int warp_n = wid & 3;
    const int bm = blockIdx.y * 128;
    const int bn = blockIdx.x * 128;

    const int z = blockIdx.z;
    const int z1 = z % zmod, z2 = z / zmod;
    const long long offA = (long long)z1 * sA1 + (long long)z2 * sA2;
    const long long offB = (long long)z1 * sB1 + (long long)z2 * sB2;
    const long long offC = (long long)z1 * sC1 + (long long)z2 * sC2;

    const __nv_bfloat16* pA[2] = { Ahi_ + offA + (size_t)bm * lda,
                                   Alo_ + offA + (size_t)bm * lda };
    const __nv_bfloat16* pB[2] = { Bhi_ + offB + (size_t)bn * ldb,
                                   Blo_ + offB + (size_t)bn * ldb };

    float acc[4][4][4];
    #pragma unroll
    for (int i = 0; i < 4; i++)
        #pragma unroll
        for (int j = 0; j < 4; j++)
            #pragma unroll
            for (int r = 0; r < 4; r++) acc[i][j][r] = 0.f;

    const int lrow = tid >> 2;
    const int lcol = (tid & 3) * 8;
    const int nstages = K >> 5;

    auto prefetch = [&](int s) {
        const int gk = s * 32;
        const uint32_t base = smb + (uint32_t)((s & 1) * 4 * TILE_E) * 2;
        #pragma unroll
        for (int t = 0; t < 4; t++) {
            const __nv_bfloat16* src = (t < 2 ? pA[t] : pB[t-2]) + gk + lcol;
            const int ld = (t < 2) ? lda : ldb;
            #pragma unroll
            for (int c = 0; c < 2; c++) {
                int row = lrow + c * 64;
                cp_async16(base + (uint32_t)(t * TILE_E + row * SPAD + lcol) * 2,
                           src + (size_t)row * ld);
            }
        }
    };

    prefetch(0);
    asm volatile("cp.async.commit_group;");

    for (int s = 0; s < nstages; s++) {
        if (s < nstages - 1) {
            prefetch(s + 1);
            asm volatile("cp.async.commit_group;");
            asm volatile("cp.async.wait_group 1;");
        } else {
            asm volatile("cp.async.wait_group 0;");
        }
        __syncthreads();

        const uint32_t stg = smb + (uint32_t)((s & 1) * 4 * TILE_E) * 2;
        const uint32_t tAhi = stg;
        const uint32_t tAlo = stg + TILE_E * 2;
        const uint32_t tBhi = stg + 2 * TILE_E * 2;
        const uint32_t tBlo = stg + 3 * TILE_E * 2;
        const int q  = lane >> 3;
        const int rr = lane & 7;

        #pragma unroll
        for (int ko = 0; ko < 32; ko += 16) {
            const int arow = warp_m * 64 + (q & 1) * 8 + rr;
            const int acol = ko + (q >> 1) * 8;
            const int brow = warp_n * 32 + (q >> 1) * 8 + rr;
            const int bcol = ko + (q & 1) * 8;

            uint32_t aH[4][4];
            #pragma unroll
            for (int i = 0; i < 4; i++)
                ldsm_x4(aH[i][0], aH[i][1], aH[i][2], aH[i][3],
                        tAhi + (uint32_t)((arow + i * 16) * SPAD + acol) * 2);
            uint32_t bH[4][2], bL[4][2];
            #pragma unroll
            for (int j = 0; j < 2; j++) {
                ldsm_x4(bH[2*j][0], bH[2*j][1], bH[2*j+1][0], bH[2*j+1][1],
                        tBhi + (uint32_t)((brow + j * 16) * SPAD + bcol) * 2);
                ldsm_x4(bL[2*j][0], bL[2*j][1], bL[2*j+1][0], bL[2*j+1][1],
                        tBlo + (uint32_t)((brow + j * 16) * SPAD + bcol) * 2);
            }
            #pragma unroll
            for (int i = 0; i < 4; i++)
                #pragma unroll
                for (int j = 0; j < 4; j++)
                    mma_bf16(acc[i][j], aH[i], bH[j]);
            #pragma unroll
            for (int i = 0; i < 4; i++)
                #pragma unroll
                for (int j = 0; j < 4; j++)
                    mma_bf16(acc[i][j], aH[i], bL[j]);
            uint32_t aL[4][4];
            #pragma unroll
            for (int i = 0; i < 4; i++)
                ldsm_x4(aL[i][0], aL[i][1], aL[i][2], aL[i][3],
                        tAlo + (uint32_t)((arow + i * 16) * SPAD + acol) * 2);
            #pragma unroll
            for (int i = 0; i < 4; i++)
                #pragma unroll
                for (int j = 0; j < 4; j++)
                    mma_bf16(acc[i][j], aL[i], bH[j]);
        }
        __syncthreads();
    }

    const int gr = lane >> 2;
    const int gc = (lane & 3) * 2;
    float* C = C_ ? C_ + offC : nullptr;
    __half* Fhi = Fhi_ ? Fhi_ + offC : nullptr;
    __half* Flo = Flo_ ? Flo_ + offC : nullptr;

    #pragma unroll
    for (int j = 0; j < 4; j++) {
        int col = bn + warp_n * 32 + j * 8 + gc;
        if (col >= nValid) continue;
        float2 bv = make_float2(0.f, 0.f);
        if (bias) bv = *(const float2*)(bias + col);
        #pragma unroll
        for (int i = 0; i < 4; i++) {
            int row0 = bm + warp_m * 64 + i * 16 + gr;
            float v00 = acc[i][j][0]*scale + bv.x, v01 = acc[i][j][1]*scale + bv.y;
            float v10 = acc[i][j][2]*scale + bv.x, v11 = acc[i][j][3]*scale + bv.y;
            size_t o0 = (size_t)row0 * ldc + col;
            size_t o1 = (size_t)(row0 + 8) * ldc + col;
            if (Fhi) {
                __half h;
                h = __float2half(v00); Fhi[o0]   = h; Flo[o0]   = __float2half(v00 - __half2float(h));
                h = __float2half(v01); Fhi[o0+1] = h; Flo[o0+1] = __float2half(v01 - __half2float(h));
                h = __float2half(v10); Fhi[o1]   = h; Flo[o1]   = __float2half(v10 - __half2float(h));
                h = __float2half(v11); Fhi[o1+1] = h; Flo[o1+1] = __float2half(v11 - __half2float(h));
            } else {
                *(float2*)(C + o0) = make_float2(v00, v01);
                *(float2*)(C + o1) = make_float2(v10, v11);
            }
        }
    }
}

// ============== fp16 NT GEMM, 1- or 2-term A: C = scale*((Ahi[+Alo])@B^T) + bias ==============
#define GF_SMEM (2*3*TILE_E*2)    // 61440 bytes

__global__ __launch_bounds__(256, 2) void gemm_f16_mma(
    const __half* __restrict__ Ahi_, const __half* __restrict__ Alo_,
    const __half* __restrict__ B_,
    const float* __restrict__ bias, float* __restrict__ C_,
    __nv_bfloat16* __restrict__ Chi_, __nv_bfloat16* __restrict__ Clo_,
    int K, int lda, int ldb, int ldc, int nValid, float scale,
    int zmod, long long sA1, long long sA2, long long sB1, long long sB2,
    long long sC1, long long sC2)
{
    extern __shared__ __align__(16) __half smh[];
    const uint32_t smb = smem_u32(smh);

    const int tid = threadIdx.x;
    const int lane = tid & 31;
    const int wid = tid >> 5;
    const int warp_m = wid >> 2;
    const int warp_n = wid & 3;
    const int bm = blockIdx.y * 128;
    const int bn = blockIdx.x * 128;
    const bool two = (Alo_ != nullptr);

    const int z = blockIdx.z;
    const int z1 = z % zmod, z2 = z / zmod;
    const long long offA = (long long)z1 * sA1 + (long long)z2 * sA2;
    const long long offB = (long long)z1 * sB1 + (long long)z2 * sB2;
    const long long offC = (long long)z1 * sC1 + (long long)z2 * sC2;

    const __half* pT[3] = { Ahi_ + offA + (size_t)bm * lda,
                            two ? (Alo_ + offA + (size_t)bm * lda) : nullptr,
                            B_   + offB + (size_t)bn * ldb };

    float acc[4][4][4];
    #pragma unroll
    for (int i = 0; i < 4; i++)
        #pragma unroll
        for (int j = 0; j < 4; j++)
            #pragma unroll
            for (int r = 0; r < 4; r++) acc[i][j][r] = 0.f;

    const int lrow = tid >> 2;
    const int lcol = (tid & 3) * 8;
    const int nstages = K >> 5;

    auto prefetch = [&](int s) {
        const int gk = s * 32;
        const uint32_t base = smb + (uint32_t)((s & 1) * 3 * TILE_E) * 2;
        #pragma unroll
        for (int t = 0; t < 3; t++) {
            if (t == 1 && !two) continue;
            const __half* src = pT[t] + gk + lcol;
            const int ld = (t < 2) ? lda : ldb;
            #pragma unroll
            for (int c = 0; c < 2; c++) {
                int row = lrow + c * 64;
                cp_async16(base + (uint32_t)(t * TILE_E + row * SPAD + lcol) * 2,
                           src + (size_t)row * ld);
            }
        }
    };

    prefetch(0);
    asm volatile("cp.async.commit_group;");

    for (int s = 0; s < nstages; s++) {
        if (s < nstages - 1) {
            prefetch(s + 1);
            asm volatile("cp.async.commit_group;");
            asm volatile("cp.async.wait_group 1;");
        } else {
            asm volatile("cp.async.wait_group 0;");
        }
        __syncthreads();

        const uint32_t stg = smb + (uint32_t)((s & 1) * 3 * TILE_E) * 2;
        const uint32_t tAhi = stg;
        const uint32_t tAlo = stg + TILE_E * 2;
        const uint32_t tB   = stg + 2 * TILE_E * 2;
        const int q  = lane >> 3;
        const int rr = lane & 7;

        #pragma unroll
        for (int ko = 0; ko < 32; ko += 16) {
            const int arow = warp_m * 64 + (q & 1) * 8 + rr;
            const int acol = ko + (q >> 1) * 8;
            const int brow = warp_n * 32 + (q >> 1) * 8 + rr;
            const int bcol = ko + (q & 1) * 8;

            uint32_t b[4][2];
            #pragma unroll
            for (int j = 0; j < 2; j++)
                ldsm_x4(b[2*j][0], b[2*j][1], b[2*j+1][0], b[2*j+1][1],
                        tB + (uint32_t)((brow + j * 16) * SPAD + bcol) * 2);
            uint32_t aH[4][4];
            #pragma unroll
            for (int i = 0; i < 4; i++)
                ldsm_x4(aH[i][0], aH[i][1], aH[i][2], aH[i][3],
                        tAhi + (uint32_t)((arow + i * 16) * SPAD + acol) * 2);
            #pragma unroll
            for (int i = 0; i < 4; i++)
                #pragma unroll
                for (int j = 0; j < 4; j++)
                    mma_f16(acc[i][j], aH[i], b[j]);
            if (two) {
                uint32_t aL[4][4];
                #pragma unroll
                for (int i = 0; i < 4; i++)
                    ldsm_x4(aL[i][0], aL[i][1], aL[i][2], aL[i][3],
                            tAlo + (uint32_t)((arow + i * 16) * SPAD + acol) * 2);
                #pragma unroll
                for (int i = 0; i < 4; i++)
                    #pragma unroll
                    for (int j = 0; j < 4; j++)
                        mma_f16(acc[i][j], aL[i], b[j]);
            }
        }
        __syncthreads();
    }

    const int gr = lane >> 2;
    const int gc = (lane & 3) * 2;
    float* C = C_ ? C_ + offC : nullptr;
    __nv_bfloat16* Chi = Chi_ ? Chi_ + offC : nullptr;
    __nv_bfloat16* Clo = Clo_ ? Clo_ + offC : nullptr;

    #pragma unroll
    for (int j = 0; j < 4; j++) {
        int col = bn + warp_n * 32 + j * 8 + gc;
        if (col >= nValid) continue;
        float2 bv = make_float2(0.f, 0.f);
        if (bias) bv = *(const float2*)(bias + col);
        #pragma unroll
        for (int i = 0; i < 4; i++) {
            int row0 = bm + warp_m * 64 + i * 16 + gr;
            float v00 = acc[i][j][0]*scale + bv.x, v01 = acc[i][j][1]*scale + bv.y;
            float v10 = acc[i][j][2]*scale + bv.x, v11 = acc[i][j][3]*scale + bv.y;
            size_t o0 = (size_t)row0 * ldc + col;
            size_t o1 = (size_t)(row0 + 8) * ldc + col;
            if (Chi) {
                __nv_bfloat16 h;
                h = __float2bfloat16(v00); Chi[o0]   = h; Clo[o0]   = __float2bfloat16(v00 - __bfloat162float(h));
                h = __float2bfloat16(v01); Chi[o0+1] = h; Clo[o0+1] = __float2bfloat16(v01 - __bfloat162float(h));
                h = __float2bfloat16(v10); Chi[o1]   = h; Clo[o1]   = __float2bfloat16(v10 - __bfloat162float(h));
                h = __float2bfloat16(v11); Chi[o1+1] = h; Clo[o1+1] = __float2bfloat16(v11 - __bfloat162float(h));
            } else {
                *(float2*)(C + o0) = make_float2(v00, v01);
                *(float2*)(C + o1) = make_float2(v10, v11);
            }
        }
    }
}

// ---------------- parallel liquid scan (exact affine chunk decomposition) ----------------
__global__ __launch_bounds__(512) void liquid_scan_par(
    const float* __restrict__ I, const float* __restrict__ tau,
    const float* __restrict__ log_dt, float* __restrict__ out) {
    const int b = blockIdx.x;
    const int lg = blockIdx.y;
    const int lane16 = threadIdx.x & 15;
    const int chunk  = threadIdx.x >> 4;
    const int o = lg * 16 + lane16;
    const float dt = expf(log_dt[0]);
    const float r = dt / tau[o];
    const float a = 1.f - r;
    const float* Ib = I + (size_t)b * SS * HH + o;
    const int t0 = chunk * 32;

    float Iv[32];
    #pragma unroll
    for (int i = 0; i < 32; i++) Iv[i] = Ib[(size_t)(t0 + i) * HH];

    float u = 0.f, s = 0.f;
    #pragma unroll
    for (int i = 0; i < 32; i++) {
        float sn = s + r * (u - s);
        u = u + r * (Iv[i] - u);
        s = sn;
    }
    __shared__ float2 dloc[32][16];
    __shared__ float2 st[32][16];
    dloc[chunk][lane16] = make_float2(u, s);
    __syncthreads();

    if (chunk == 0) {
        float a2 = a*a, a4 = a2*a2, a8 = a4*a4, a16 = a8*a8;
        float a32v = a16*a16;
        float a31 = a16*a8*a4*a2*a;
        float c32 = 32.f * r * a31;
        float2 x = make_float2(0.f, 0.f);
        #pragma unroll
        for (int c = 0; c < 32; c++) {
            st[c][lane16] = x;
            float2 d = dloc[c][lane16];
            float nu = a32v * x.x + d.x;
            float ns = c32 * x.x + a32v * x.y + d.y;
            x = make_float2(nu, ns);
        }
    }
    __syncthreads();

    float2 x0 = st[chunk][lane16];
    u = x0.x; s = x0.y;
    float* Ob = out + (size_t)b * SS * HH + o;
    #pragma unroll
    for (int i = 0; i < 32; i++) {
        float sn = s + r * (u - s);
        u = u + r * (Iv[i] - u);
        s = sn;
        Ob[(size_t)(t0 + i) * HH] = tanhf(s);
    }
}

// ---------------- layernorm -> bf16 hi/lo ----------------
__global__ void layernorm_split(const float* __restrict__ in, const float* __restrict__ g,
                                const float* __restrict__ be,
                                __nv_bfloat16* __restrict__ hi, __nv_bfloat16* __restrict__ lo) {
    int row = blockIdx.x;
    int tid = threadIdx.x;
    const float* p = in + (size_t)row * HH;
    float a = p[tid], b = p[tid + 256];
    float sum = a + b, sq = a*a + b*b;
    __shared__ float s1[8], s2[8];
    #pragma unroll
    for (int o = 16; o; o >>= 1) {
        sum += __shfl_xor_sync(0xffffffffu, sum, o);
        sq  += __shfl_xor_sync(0xffffffffu, sq,  o);
    }
    if ((tid & 31) == 0) { s1[tid>>5] = sum; s2[tid>>5] = sq; }
    __syncthreads();
    sum = 0.f; sq = 0.f;
    #pragma unroll
    for (int i = 0; i < 8; i++) { sum += s1[i]; sq += s2[i]; }
    float mean = sum * (1.f/512.f);
    float var  = sq * (1.f/512.f) - mean*mean;
    float inv = rsqrtf(var + 1e-5f);
    float y0 = (a - mean) * inv * g[tid]       + be[tid];
    float y1 = (b - mean) * inv * g[tid + 256] + be[tid + 256];
    size_t base = (size_t)row * HH;
    __nv_bfloat16 h0 = __float2bfloat16(y0);
    __nv_bfloat16 h1 = __float2bfloat16(y1);
    hi[base + tid]       = h0;
    hi[base + tid + 256] = h1;
    lo[base + tid]       = __float2bfloat16(y0 - __bfloat162float(h0));
    lo[base + tid + 256] = __float2bfloat16(y1 - __bfloat162float(h1));
}

// ---------------- qkv split ----------------
__global__ void qkv_split_kernel(const float* __restrict__ qkv) {
    int idx = blockIdx.x * blockDim.x + threadIdx.x;
    if (idx >= MM * 1536) return;
    int row = idx / 1536;
    int col = idx - row * 1536;
    int b = row >> 10, s = row & 1023;
    float v = qkv[idx];
    if (col < 512) {
        int hd = col >> 6, d = col & 63;
        size_t o = ((size_t)(b*8 + hd) * 1024 + s) * 64 + d;
        __nv_bfloat16 h = __float2bfloat16(v);
        g_Qhi[o] = h; g_Qlo[o] = __float2bfloat16(v - __bfloat162float(h));
    } else if (col < 1024) {
        int c = col - 512;
        int hd = c >> 6, d = c & 63;
        size_t o = ((size_t)(b*8 + hd) * 1024 + s) * 64 + d;
        __nv_bfloat16 h = __float2bfloat16(v);
        g_Khi[o] = h; g_Klo[o] = __float2bfloat16(v - __bfloat162float(h));
    } else {
        int c = col - 1024;
        int hd = c >> 6, d = c & 63;
        size_t o = (size_t)(b*8 + hd) * 131072 + (size_t)d * 1024 + s;
        g_Vth[o] = __float2half(v);
    }
}

// ---------------- softmax over rows of 1024, fused fp16 P split ----------------
__global__ void softmax_split_kernel(const float* __restrict__ scores,
                                     __half* __restrict__ Phi,
                                     __half* __restrict__ Plo) {
    size_t row = blockIdx.x;
    const float* p = scores + row * 1024;
    int tid = threadIdx.x;
    float4 v = ((const float4*)p)[tid];
    float m = fmaxf(fmaxf(v.x, v.y), fmaxf(v.z, v.w));
    __shared__ float red[8];
    #pragma unroll
    for (int o = 16; o; o >>= 1) m = fmaxf(m, __shfl_xor_sync(0xffffffffu, m, o));
    if ((tid & 31) == 0) red[tid>>5] = m;
    __syncthreads();
    m = red[0];
    #pragma unroll
    for (int i = 1; i < 8; i++) m = fmaxf(m, red[i]);
    v.x = __expf(v.x - m); v.y = __expf(v.y - m);
    v.z = __expf(v.z - m); v.w = __expf(v.w - m);
    float sum = v.x + v.y + v.z + v.w;
    #pragma unroll
    for (int o = 16; o; o >>= 1) sum += __shfl_xor_sync(0xffffffffu, sum, o);
    __syncthreads();
    if ((tid & 31) == 0) red[tid>>5] = sum;
    __syncthreads();
    sum = 0.f;
    #pragma unroll
    for (int i = 0; i < 8; i++) sum += red[i];
    float inv = 1.f / sum;
    float pv[4] = { v.x*inv, v.y*inv, v.z*inv, v.w*inv };
    __half hb[4], lb[4];
    #pragma unroll
    for (int i = 0; i < 4; i++) {
        hb[i] = __float2half(pv[i]);
        lb[i] = __float2half(pv[i] - __half2float(hb[i]));
    }
    *(uint2*)(Phi + row*1024 + tid*4) = *(uint2*)hb;
    *(uint2*)(Plo + row*1024 + tid*4) = *(uint2*)lb;
}

// ---------------- host orchestration ----------------
extern "C" void kernel_launch(void* const* d_in, const int* in_sizes, int n_in,
                              void* d_out, int out_size) {
    const int*   x          = (const int*)  d_in[0];
    const float* emb        = (const float*)d_in[1];
    const float* W0         = (const float*)d_in[2];
    const float* b0         = (const float*)d_in[3];
    const float* tau0       = (const float*)d_in[4];
    const float* g0         = (const float*)d_in[5];
    const float* be0        = (const float*)d_in[6];
    const float* W1         = (const float*)d_in[7];
    const float* b1         = (const float*)d_in[8];
    const float* tau1       = (const float*)d_in[9];
    const float* g1         = (const float*)d_in[10];
    const float* be1        = (const float*)d_in[11];
    const float* attn_in_w  = (const float*)d_in[12];
    const float* attn_in_b  = (const float*)d_in[13];
    const float* attn_out_w = (const float*)d_in[14];
    const float* attn_out_b = (const float*)d_in[15];
    const float* out_w      = (const float*)d_in[16];
    const float* out_b      = (const float*)d_in[17];
    const float* log_dt     = (const float*)d_in[18];
    float* out = (float*)d_out;

    float *I, *sbuf, *qkv, *scores;
    __nv_bfloat16 *Ahi, *Alo, *A2hi, *A2lo;
    __nv_bfloat16 *W0hi, *W0lo, *W1hi, *W1lo, *Wqhi, *Wqlo, *Wohi, *Wolo;
    __nv_bfloat16 *Qhi, *Qlo, *Khi, *Klo;
    __half *H2hi, *H2lo, *Bh, *Vth, *Phi, *Plo;
    cudaGetSymbolAddress((void**)&I,      g_I);
    cudaGetSymbolAddress((void**)&sbuf,   g_s);
    cudaGetSymbolAddress((void**)&qkv,    g_qkv);
    cudaGetSymbolAddress((void**)&scores, g_scores);
    cudaGetSymbolAddress((void**)&Ahi,    g_Ahi);
    cudaGetSymbolAddress((void**)&Alo,    g_Alo);
    cudaGetSymbolAddress((void**)&A2hi,   g_A2hi);
    cudaGetSymbolAddress((void**)&A2lo,   g_A2lo);
    cudaGetSymbolAddress((void**)&H2hi,   g_H2hi);
    cudaGetSymbolAddress((void**)&H2lo,   g_H2lo);
    cudaGetSymbolAddress((void**)&Bh,     g_Bh);
    cudaGetSymbolAddress((void**)&W0hi,   g_W0hi);
    cudaGetSymbolAddress((void**)&W0lo,   g_W0lo);
    cudaGetSymbolAddress((void**)&W1hi,   g_W1hi);
    cudaGetSymbolAddress((void**)&W1lo,   g_W1lo);
    cudaGetSymbolAddress((void**)&Wqhi,   g_Wqhi);
    cudaGetSymbolAddress((void**)&Wqlo,   g_Wqlo);
    cudaGetSymbolAddress((void**)&Wohi,   g_Wohi);
    cudaGetSymbolAddress((void**)&Wolo,   g_Wolo);
    cudaGetSymbolAddress((void**)&Qhi,    g_Qhi);
    cudaGetSymbolAddress((void**)&Qlo,    g_Qlo);
    cudaGetSymbolAddress((void**)&Khi,    g_Khi);
    cudaGetSymbolAddress((void**)&Klo,    g_Klo);
    cudaGetSymbolAddress((void**)&Vth,    g_Vth);
    cudaGetSymbolAddress((void**)&Phi,    g_Phi);
    cudaGetSymbolAddress((void**)&Plo,    g_Plo);

    cudaFuncSetAttribute(gemm_pair_mma,
                         cudaFuncAttributeMaxDynamicSharedMemorySize, GP_SMEM);
    cudaFuncSetAttribute(gemm_f16_mma,
                         cudaFuncAttributeMaxDynamicSharedMemorySize, GF_SMEM);

    // weight preprocessing
    convert_f16_kernel<<<(VV*HH + 255)/256, 256>>>(out_w, Bh, VV*HH);
    split_bf16_kernel<<<(HH*EE + 255)/256, 256>>>(W0, W0hi, W0lo, HH*EE);
    split_bf16_kernel<<<(HH*HH + 255)/256, 256>>>(W1, W1hi, W1lo, HH*HH);
    split_bf16_kernel<<<(3*HH*HH + 255)/256, 256>>>(attn_in_w, Wqhi, Wqlo, 3*HH*HH);
    split_bf16_kernel<<<(HH*HH + 255)/256, 256>>>(attn_out_w, Wohi, Wolo, HH*HH);

    // 1. embedding + pos-enc -> bf16 splits
    embed_pe_split<<<(MM*EE)/256, 256>>>(x, emb, Ahi, Alo);

    // 2. liquid layer 0 (bf16 3-term)
    gemm_pair_mma<<<dim3(4, 32, 1), 256, GP_SMEM>>>(
        Ahi, Alo, W0hi, W0lo, b0, I, nullptr, nullptr,
        EE, EE, EE, HH, HH, 1.f, 1, 0,0,0,0,0,0);
    liquid_scan_par<<<dim3(BB, 32), 512>>>(I, tau0, log_dt, sbuf);
    layernorm_split<<<MM, 256>>>(sbuf, g0, be0, Ahi, Alo);

    // 3. liquid layer 1
    gemm_pair_mma<<<dim3(4, 32, 1), 256, GP_SMEM>>>(
        Ahi, Alo, W1hi, W1lo, b1, I, nullptr, nullptr,
        HH, HH, HH, HH, HH, 1.f, 1, 0,0,0,0,0,0);
    liquid_scan_par<<<dim3(BB, 32), 512>>>(I, tau1, log_dt, sbuf);
    layernorm_split<<<MM, 256>>>(sbuf, g1, be1, Ahi, Alo);

    // 4. MHA: qkv projection (bf16 3-term)
    gemm_pair_mma<<<dim3(12, 32, 1), 256, GP_SMEM>>>(
        Ahi, Alo, Wqhi, Wqlo, attn_in_b, qkv, nullptr, nullptr,
        HH, HH, HH, 3*HH, 3*HH, 1.f, 1, 0,0,0,0,0,0);
    qkv_split_kernel<<<(MM*1536 + 255)/256, 256>>>(qkv);

    // scores = Q @ K^T / 8 (bf16 3-term, batched)
    gemm_pair_mma<<<dim3(8, 8, 32), 256, GP_SMEM>>>(
        Qhi, Qlo, Khi, Klo, nullptr, scores, nullptr, nullptr,
        64, 64, 64, 1024, 1024, 0.125f,
        32, 65536LL, 0, 65536LL, 0, 1LL<<20, 0);
    softmax_split_kernel<<<32*1024, 256>>>(scores, Phi, Plo);

    // AV = P @ Vt^T (fp16 2-term) -> fused bf16 split into A2
    gemm_f16_mma<<<dim3(1, 8, 32), 256, GF_SMEM>>>(
        Phi, Plo, Vth, nullptr, nullptr, A2hi, A2lo,
        1024, 1024, 1024, 512, 64, 1.f,
        8, 1LL<<20, 8LL<<20, 131072LL, 8LL*131072, 64LL, 524288LL);

    // out-projection (bf16 3-term) -> fused fp16 split into H2
    gemm_pair_mma<<<dim3(4, 32, 1), 256, GP_SMEM>>>(
        A2hi, A2lo, Wohi, Wolo, attn_out_b, nullptr, H2hi, H2lo,
        HH, HH, HH, HH, HH, 1.f, 1, 0,0,0,0,0,0);

    // 5. vocab projection (fp16 1-term: A=h2 rounded to fp16)
    gemm_f16_mma<<<dim3(VV/128, MM/128, 1), 256, GF_SMEM>>>(
        H2hi, nullptr, Bh, out_b, out, nullptr, nullptr,
        HH, HH, HH, VV, VV, 1.f, 1, 0,0,0,0,0,0);
}

// round 9
// speedup vs baseline: 5.0069x; 1.0534x over previous
#include <cuda_runtime.h>
#include <cuda_bf16.h>
#include <cuda_fp16.h>
#include <cstdint>
#include <math.h>

#define BB 4
#define SS 1024
#define EE 512
#define HH 512
#define VV 32000
#define MM (BB*SS)      // 4096
#define NH 8
#define DH 64

// ---------------- scratch (static device memory; no allocations) ----------------
__device__ float g_I[MM*HH];
__device__ float g_s[MM*HH];
__device__ float g_qkv[MM*3*HH];
__device__ __nv_bfloat16 g_Ahi[MM*HH],  g_Alo[MM*HH];
__device__ __nv_bfloat16 g_A2hi[MM*HH], g_A2lo[MM*HH];
__device__ __half        g_H2hi[MM*HH], g_H2lo[MM*HH];   // h2 fp16 (vocab A)
__device__ __nv_bfloat16 g_W0hi[HH*EE],  g_W0lo[HH*EE];
__device__ __nv_bfloat16 g_W1hi[HH*HH],  g_W1lo[HH*HH];
__device__ __nv_bfloat16 g_Wqhi[3*HH*HH], g_Wqlo[3*HH*HH];
__device__ __nv_bfloat16 g_Wohi[HH*HH],  g_Wolo[HH*HH];
__device__ __half        g_Bh[(size_t)VV*HH];            // vocab weights fp16
__device__ __nv_bfloat16 g_Qhi[32*1024*64], g_Qlo[32*1024*64];
__device__ __nv_bfloat16 g_Khi[32*1024*64], g_Klo[32*1024*64];
__device__ __half        g_Vth[32*128*1024];             // [bh][d pad128][k] fp16
__device__ __half        g_Sh[(size_t)32*1024*1024];     // scores/P fp16 (in-place)

__device__ __forceinline__ uint32_t smem_u32(const void* p) {
    uint32_t a;
    asm("{ .reg .u64 t; cvta.to.shared.u64 t, %1; cvt.u32.u64 %0, t; }" : "=r"(a) : "l"(p));
    return a;
}
__device__ __forceinline__ void cp_async16(uint32_t dst, const void* src) {
    asm volatile("cp.async.cg.shared.global [%0], [%1], 16;" :: "r"(dst), "l"(src));
}
__device__ __forceinline__ void ldsm_x4(uint32_t& r0, uint32_t& r1, uint32_t& r2, uint32_t& r3,
                                        uint32_t addr) {
    asm volatile("ldmatrix.sync.aligned.m8n8.x4.shared.b16 {%0,%1,%2,%3}, [%4];"
                 : "=r"(r0), "=r"(r1), "=r"(r2), "=r"(r3) : "r"(addr));
}
__device__ __forceinline__ void mma_bf16(float* c, const uint32_t* a, const uint32_t* b) {
    asm volatile("mma.sync.aligned.m16n8k16.row.col.f32.bf16.bf16.f32 "
                 "{%0,%1,%2,%3}, {%4,%5,%6,%7}, {%8,%9}, {%0,%1,%2,%3};"
                 : "+f"(c[0]), "+f"(c[1]), "+f"(c[2]), "+f"(c[3])
                 : "r"(a[0]), "r"(a[1]), "r"(a[2]), "r"(a[3]), "r"(b[0]), "r"(b[1]));
}
__device__ __forceinline__ void mma_f16(float* c, const uint32_t* a, const uint32_t* b) {
    asm volatile("mma.sync.aligned.m16n8k16.row.col.f32.f16.f16.f32 "
                 "{%0,%1,%2,%3}, {%4,%5,%6,%7}, {%8,%9}, {%0,%1,%2,%3};"
                 : "+f"(c[0]), "+f"(c[1]), "+f"(c[2]), "+f"(c[3])
                 : "r"(a[0]), "r"(a[1]), "r"(a[2]), "r"(a[3]), "r"(b[0]), "r"(b[1]));
}

// ---------------- embed + positional encoding -> bf16 hi/lo ----------------
__global__ void embed_pe_split(const int* __restrict__ x, const float* __restrict__ emb,
                               __nv_bfloat16* __restrict__ hi, __nv_bfloat16* __restrict__ lo) {
    int idx = blockIdx.x * blockDim.x + threadIdx.x;
    if (idx >= MM*EE) return;
    int m = idx >> 9;
    int e = idx & 511;
    int s = m & (SS - 1);
    int tok = x[m];
    int i2 = e & ~1;
    float freq = expf((float)i2 * (-9.210340371976184f / 512.0f));
    float ang = (float)s * freq;
    float pe = (e & 1) ? cosf(ang) : sinf(ang);
    float v = emb[(size_t)tok * EE + e] + pe;
    __nv_bfloat16 h = __float2bfloat16(v);
    hi[idx] = h;
    lo[idx] = __float2bfloat16(v - __bfloat162float(h));
}

__global__ void split_bf16_kernel(const float* __restrict__ in, __nv_bfloat16* __restrict__ hi,
                                  __nv_bfloat16* __restrict__ lo, int n) {
    int i = blockIdx.x * blockDim.x + threadIdx.x;
    if (i >= n) return;
    float x = in[i];
    __nv_bfloat16 h = __float2bfloat16(x);
    hi[i] = h;
    lo[i] = __float2bfloat16(x - __bfloat162float(h));
}

__global__ void convert_f16_kernel(const float* __restrict__ in, __half* __restrict__ out, int n) {
    int i = blockIdx.x * blockDim.x + threadIdx.x;
    if (i < n) out[i] = __float2half(in[i]);
}

// ============== bf16 3-term paired-operand NT GEMM ==============
#define SPAD 40
#define TILE_E (128*SPAD)
#define GP_SMEM (2*4*TILE_E*2)    // 81920 bytes

__global__ __launch_bounds__(256, 2) void gemm_pair_mma(
    const __nv_bfloat16* __restrict__ Ahi_, const __nv_bfloat16* __restrict__ Alo_,
    const __nv_bfloat16* __restrict__ Bhi_, const __nv_bfloat16* __restrict__ Blo_,
    const float* __restrict__ bias, float* __restrict__ C_,
    __half* __restrict__ Fhi_, __half* __restrict__ Flo_,
    int K, int lda, int ldb, int ldc, int nValid, float scale,
    int zmod, long long sA1, long long sA2, long long sB1, long long sB2,
    long long sC1, long long sC2)
{
    extern __shared__ __align__(16) __nv_bfloat16 sm[];
    const uint32_t smb = smem_u32(sm);

    const int tid = threadIdx.x;
    const int lane = tid & 31;
    const int wid = tid >> 5;
    const int warp_m = wid >> 2;
    const int warp_n = wid & 3;
    const int bm = blockIdx.y * 128;
    const int bn = blockIdx.x * 128;

    const int z = blockIdx.z;
    const int z1 = z % zmod, z2 = z / zmod;
    const long long offA = (long long)z1 * sA1 + (long long)z2 * sA2;
    const long long offB = (long long)z1 * sB1 + (long long)z2 * sB2;
    const long long offC = (long long)z1 * sC1 + (long long)z2 * sC2;

    const __nv_bfloat16* pA[2] = { Ahi_ + offA + (size_t)bm * lda,
                                   Alo_ + offA + (size_t)bm * lda };
    const __nv_bfloat16* pB[2] = { Bhi_ + offB + (size_t)bn * ldb,
                                   Blo_ + offB + (size_t)bn * ldb };

    float acc[4][4][4];
    #pragma unroll
    for (int i = 0; i < 4; i++)
        #pragma unroll
        for (int j = 0; j < 4; j++)
            #pragma unroll
            for (int r = 0; r < 4; r++) acc[i][j][r] = 0.f;

    const int lrow = tid >> 2;
    const int lcol = (tid & 3) * 8;
    const int nstages = K >> 5;

    auto prefetch = [&](int s) {
        const int gk = s * 32;
        const uint32_t base = smb + (uint32_t)((s & 1) * 4 * TILE_E) * 2;
        #pragma unroll
        for (int t = 0; t < 4; t++) {
            const __nv_bfloat16* src = (t < 2 ? pA[t] : pB[t-2]) + gk + lcol;
            const int ld = (t < 2) ? lda : ldb;
            #pragma unroll
            for (int c = 0; c < 2; c++) {
                int row = lrow + c * 64;
                cp_async16(base + (uint32_t)(t * TILE_E + row * SPAD + lcol) * 2,
                           src + (size_t)row * ld);
            }
        }
    };

    prefetch(0);
    asm volatile("cp.async.commit_group;");

    for (int s = 0; s < nstages; s++) {
        if (s < nstages - 1) {
            prefetch(s + 1);
            asm volatile("cp.async.commit_group;");
            asm volatile("cp.async.wait_group 1;");
        } else {
            asm volatile("cp.async.wait_group 0;");
        }
        __syncthreads();

        const uint32_t stg = smb + (uint32_t)((s & 1) * 4 * TILE_E) * 2;
        const uint32_t tAhi = stg;
        const uint32_t tAlo = stg + TILE_E * 2;
        const uint32_t tBhi = stg + 2 * TILE_E * 2;
        const uint32_t tBlo = stg + 3 * TILE_E * 2;
        const int q  = lane >> 3;
        const int rr = lane & 7;

        #pragma unroll
        for (int ko = 0; ko < 32; ko += 16) {
            const int arow = warp_m * 64 + (q & 1) * 8 + rr;
            const int acol = ko + (q >> 1) * 8;
            const int brow = warp_n * 32 + (q >> 1) * 8 + rr;
            const int bcol = ko + (q & 1) * 8;

            uint32_t aH[4][4];
            #pragma unroll
            for (int i = 0; i < 4; i++)
                ldsm_x4(aH[i][0], aH[i][1], aH[i][2], aH[i][3],
                        tAhi + (uint32_t)((arow + i * 16) * SPAD + acol) * 2);
            uint32_t bH[4][2], bL[4][2];
            #pragma unroll
            for (int j = 0; j < 2; j++) {
                ldsm_x4(bH[2*j][0], bH[2*j][1], bH[2*j+1][0], bH[2*j+1][1],
                        tBhi + (uint32_t)((brow + j * 16) * SPAD + bcol) * 2);
                ldsm_x4(bL[2*j][0], bL[2*j][1], bL[2*j+1][0], bL[2*j+1][1],
                        tBlo + (uint32_t)((brow + j * 16) * SPAD + bcol) * 2);
            }
            #pragma unroll
            for (int i = 0; i < 4; i++)
                #pragma unroll
                for (int j = 0; j < 4; j++)
                    mma_bf16(acc[i][j], aH[i], bH[j]);
            #pragma unroll
            for (int i = 0; i < 4; i++)
                #pragma unroll
                for (int j = 0; j < 4; j++)
                    mma_bf16(acc[i][j], aH[i], bL[j]);
            uint32_t aL[4][4];
            #pragma unroll
            for (int i = 0; i < 4; i++)
                ldsm_x4(aL[i][0], aL[i][1], aL[i][2], aL[i][3],
                        tAlo + (uint32_t)((arow + i * 16) * SPAD + acol) * 2);
            #pragma unroll
            for (int i = 0; i < 4; i++)
                #pragma unroll
                for (int j = 0; j < 4; j++)
                    mma_bf16(acc[i][j], aL[i], bH[j]);
        }
        __syncthreads();
    }

    // epilogue: fp32, fp16 hi/lo split, or single fp16
    const int gr = lane >> 2;
    const int gc = (lane & 3) * 2;
    float* C = C_ ? C_ + offC : nullptr;
    __half* Fhi = Fhi_ ? Fhi_ + offC : nullptr;
    __half* Flo = Flo_ ? Flo_ + offC : nullptr;

    #pragma unroll
    for (int j = 0; j < 4; j++) {
        int col = bn + warp_n * 32 + j * 8 + gc;
        if (col >= nValid) continue;
        float2 bv = make_float2(0.f, 0.f);
        if (bias) bv = *(const float2*)(bias + col);
        #pragma unroll
        for (int i = 0; i < 4; i++) {
            int row0 = bm + warp_m * 64 + i * 16 + gr;
            float v00 = acc[i][j][0]*scale + bv.x, v01 = acc[i][j][1]*scale + bv.y;
            float v10 = acc[i][j][2]*scale + bv.x, v11 = acc[i][j][3]*scale + bv.y;
            size_t o0 = (size_t)row0 * ldc + col;
            size_t o1 = (size_t)(row0 + 8) * ldc + col;
            if (Fhi) {
                __half h;
                if (Flo) {
                    h = __float2half(v00); Fhi[o0]   = h; Flo[o0]   = __float2half(v00 - __half2float(h));
                    h = __float2half(v01); Fhi[o0+1] = h; Flo[o0+1] = __float2half(v01 - __half2float(h));
                    h = __float2half(v10); Fhi[o1]   = h; Flo[o1]   = __float2half(v10 - __half2float(h));
                    h = __float2half(v11); Fhi[o1+1] = h; Flo[o1+1] = __float2half(v11 - __half2float(h));
                } else {
                    *(__half2*)(Fhi + o0) = __floats2half2_rn(v00, v01);
                    *(__half2*)(Fhi + o1) = __floats2half2_rn(v10, v11);
                }
            } else {
                *(float2*)(C + o0) = make_float2(v00, v01);
                *(float2*)(C + o1) = make_float2(v10, v11);
            }
        }
    }
}

// ============== fp16 NT GEMM, 1- or 2-term A ==============
#define GF_SMEM (2*3*TILE_E*2)    // 61440 bytes

__global__ __launch_bounds__(256, 2) void gemm_f16_mma(
    const __half* __restrict__ Ahi_, const __half* __restrict__ Alo_,
    const __half* __restrict__ B_,
    const float* __restrict__ bias, float* __restrict__ C_,
    __nv_bfloat16* __restrict__ Chi_, __nv_bfloat16* __restrict__ Clo_,
    int K, int lda, int ldb, int ldc, int nValid, float scale,
    int zmod, long long sA1, long long sA2, long long sB1, long long sB2,
    long long sC1, long long sC2)
{
    extern __shared__ __align__(16) __half smh[];
    const uint32_t smb = smem_u32(smh);

    const int tid = threadIdx.x;
    const int lane = tid & 31;
    const int wid = tid >> 5;
    const int warp_m = wid >> 2;
    const int warp_n = wid & 3;
    const int bm = blockIdx.y * 128;
    const int bn = blockIdx.x * 128;
    const bool two = (Alo_ != nullptr);

    const int z = blockIdx.z;
    const int z1 = z % zmod, z2 = z / zmod;
    const long long offA = (long long)z1 * sA1 + (long long)z2 * sA2;
    const long long offB = (long long)z1 * sB1 + (long long)z2 * sB2;
    const long long offC = (long long)z1 * sC1 + (long long)z2 * sC2;

    const __half* pT[3] = { Ahi_ + offA + (size_t)bm * lda,
                            two ? (Alo_ + offA + (size_t)bm * lda) : nullptr,
                            B_   + offB + (size_t)bn * ldb };

    float acc[4][4][4];
    #pragma unroll
    for (int i = 0; i < 4; i++)
        #pragma unroll
        for (int j = 0; j < 4; j++)
            #pragma unroll
            for (int r = 0; r < 4; r++) acc[i][j][r] = 0.f;

    const int lrow = tid >> 2;
    const int lcol = (tid & 3) * 8;
    const int nstages = K >> 5;

    auto prefetch = [&](int s) {
        const int gk = s * 32;
        const uint32_t base = smb + (uint32_t)((s & 1) * 3 * TILE_E) * 2;
        #pragma unroll
        for (int t = 0; t < 3; t++) {
            if (t == 1 && !two) continue;
            const __half* src = pT[t] + gk + lcol;
            const int ld = (t < 2) ? lda : ldb;
            #pragma unroll
            for (int c = 0; c < 2; c++) {
                int row = lrow + c * 64;
                cp_async16(base + (uint32_t)(t * TILE_E + row * SPAD + lcol) * 2,
                           src + (size_t)row * ld);
            }
        }
    };

    prefetch(0);
    asm volatile("cp.async.commit_group;");

    for (int s = 0; s < nstages; s++) {
        if (s < nstages - 1) {
            prefetch(s + 1);
            asm volatile("cp.async.commit_group;");
            asm volatile("cp.async.wait_group 1;");
        } else {
            asm volatile("cp.async.wait_group 0;");
        }
        __syncthreads();

        const uint32_t stg = smb + (uint32_t)((s & 1) * 3 * TILE_E) * 2;
        const uint32_t tAhi = stg;
        const uint32_t tAlo = stg + TILE_E * 2;
        const uint32_t tB   = stg + 2 * TILE_E * 2;
        const int q  = lane >> 3;
        const int rr = lane & 7;

        #pragma unroll
        for (int ko = 0; ko < 32; ko += 16) {
            const int arow = warp_m * 64 + (q & 1) * 8 + rr;
            const int acol = ko + (q >> 1) * 8;
            const int brow = warp_n * 32 + (q >> 1) * 8 + rr;
            const int bcol = ko + (q & 1) * 8;

            uint32_t b[4][2];
            #pragma unroll
            for (int j = 0; j < 2; j++)
                ldsm_x4(b[2*j][0], b[2*j][1], b[2*j+1][0], b[2*j+1][1],
                        tB + (uint32_t)((brow + j * 16) * SPAD + bcol) * 2);
            uint32_t aH[4][4];
            #pragma unroll
            for (int i = 0; i < 4; i++)
                ldsm_x4(aH[i][0], aH[i][1], aH[i][2], aH[i][3],
                        tAhi + (uint32_t)((arow + i * 16) * SPAD + acol) * 2);
            #pragma unroll
            for (int i = 0; i < 4; i++)
                #pragma unroll
                for (int j = 0; j < 4; j++)
                    mma_f16(acc[i][j], aH[i], b[j]);
            if (two) {
                uint32_t aL[4][4];
                #pragma unroll
                for (int i = 0; i < 4; i++)
                    ldsm_x4(aL[i][0], aL[i][1], aL[i][2], aL[i][3],
                            tAlo + (uint32_t)((arow + i * 16) * SPAD + acol) * 2);
                #pragma unroll
                for (int i = 0; i < 4; i++)
                    #pragma unroll
                    for (int j = 0; j < 4; j++)
                        mma_f16(acc[i][j], aL[i], b[j]);
            }
        }
        __syncthreads();
    }

    const int gr = lane >> 2;
    const int gc = (lane & 3) * 2;
    float* C = C_ ? C_ + offC : nullptr;
    __nv_bfloat16* Chi = Chi_ ? Chi_ + offC : nullptr;
    __nv_bfloat16* Clo = Clo_ ? Clo_ + offC : nullptr;

    #pragma unroll
    for (int j = 0; j < 4; j++) {
        int col = bn + warp_n * 32 + j * 8 + gc;
        if (col >= nValid) continue;
        float2 bv = make_float2(0.f, 0.f);
        if (bias) bv = *(const float2*)(bias + col);
        #pragma unroll
        for (int i = 0; i < 4; i++) {
            int row0 = bm + warp_m * 64 + i * 16 + gr;
            float v00 = acc[i][j][0]*scale + bv.x, v01 = acc[i][j][1]*scale + bv.y;
            float v10 = acc[i][j][2]*scale + bv.x, v11 = acc[i][j][3]*scale + bv.y;
            size_t o0 = (size_t)row0 * ldc + col;
            size_t o1 = (size_t)(row0 + 8) * ldc + col;
            if (Chi) {
                __nv_bfloat16 h;
                h = __float2bfloat16(v00); Chi[o0]   = h; Clo[o0]   = __float2bfloat16(v00 - __bfloat162float(h));
                h = __float2bfloat16(v01); Chi[o0+1] = h; Clo[o0+1] = __float2bfloat16(v01 - __bfloat162float(h));
                h = __float2bfloat16(v10); Chi[o1]   = h; Clo[o1]   = __float2bfloat16(v10 - __bfloat162float(h));
                h = __float2bfloat16(v11); Chi[o1+1] = h; Clo[o1+1] = __float2bfloat16(v11 - __bfloat162float(h));
            } else {
                *(float2*)(C + o0) = make_float2(v00, v01);
                *(float2*)(C + o1) = make_float2(v10, v11);
            }
        }
    }
}

// ---------------- parallel liquid scan (exact affine chunk decomposition) ----------------
__global__ __launch_bounds__(512) void liquid_scan_par(
    const float* __restrict__ I, const float* __restrict__ tau,
    const float* __restrict__ log_dt, float* __restrict__ out) {
    const int b = blockIdx.x;
    const int lg = blockIdx.y;
    const int lane16 = threadIdx.x & 15;
    const int chunk  = threadIdx.x >> 4;
    const int o = lg * 16 + lane16;
    const float dt = expf(log_dt[0]);
    const float r = dt / tau[o];
    const float a = 1.f - r;
    const float* Ib = I + (size_t)b * SS * HH + o;
    const int t0 = chunk * 32;

    float Iv[32];
    #pragma unroll
    for (int i = 0; i < 32; i++) Iv[i] = Ib[(size_t)(t0 + i) * HH];

    float u = 0.f, s = 0.f;
    #pragma unroll
    for (int i = 0; i < 32; i++) {
        float sn = s + r * (u - s);
        u = u + r * (Iv[i] - u);
        s = sn;
    }
    __shared__ float2 dloc[32][16];
    __shared__ float2 st[32][16];
    dloc[chunk][lane16] = make_float2(u, s);
    __syncthreads();

    if (chunk == 0) {
        float a2 = a*a, a4 = a2*a2, a8 = a4*a4, a16 = a8*a8;
        float a32v = a16*a16;
        float a31 = a16*a8*a4*a2*a;
        float c32 = 32.f * r * a31;
        float2 x = make_float2(0.f, 0.f);
        #pragma unroll
        for (int c = 0; c < 32; c++) {
            st[c][lane16] = x;
            float2 d = dloc[c][lane16];
            float nu = a32v * x.x + d.x;
            float ns = c32 * x.x + a32v * x.y + d.y;
            x = make_float2(nu, ns);
        }
    }
    __syncthreads();

    float2 x0 = st[chunk][lane16];
    u = x0.x; s = x0.y;
    float* Ob = out + (size_t)b * SS * HH + o;
    #pragma unroll
    for (int i = 0; i < 32; i++) {
        float sn = s + r * (u - s);
        u = u + r * (Iv[i] - u);
        s = sn;
        Ob[(size_t)(t0 + i) * HH] = tanhf(s);
    }
}

// ---------------- layernorm -> bf16 hi/lo ----------------
__global__ void layernorm_split(const float* __restrict__ in, const float* __restrict__ g,
                                const float* __restrict__ be,
                                __nv_bfloat16* __restrict__ hi, __nv_bfloat16* __restrict__ lo) {
    int row = blockIdx.x;
    int tid = threadIdx.x;
    const float* p = in + (size_t)row * HH;
    float a = p[tid], b = p[tid + 256];
    float sum = a + b, sq = a*a + b*b;
    __shared__ float s1[8], s2[8];
    #pragma unroll
    for (int o = 16; o; o >>= 1) {
        sum += __shfl_xor_sync(0xffffffffu, sum, o);
        sq  += __shfl_xor_sync(0xffffffffu, sq,  o);
    }
    if ((tid & 31) == 0) { s1[tid>>5] = sum; s2[tid>>5] = sq; }
    __syncthreads();
    sum = 0.f; sq = 0.f;
    #pragma unroll
    for (int i = 0; i < 8; i++) { sum += s1[i]; sq += s2[i]; }
    float mean = sum * (1.f/512.f);
    float var  = sq * (1.f/512.f) - mean*mean;
    float inv = rsqrtf(var + 1e-5f);
    float y0 = (a - mean) * inv * g[tid]       + be[tid];
    float y1 = (b - mean) * inv * g[tid + 256] + be[tid + 256];
    size_t base = (size_t)row * HH;
    __nv_bfloat16 h0 = __float2bfloat16(y0);
    __nv_bfloat16 h1 = __float2bfloat16(y1);
    hi[base + tid]       = h0;
    hi[base + tid + 256] = h1;
    lo[base + tid]       = __float2bfloat16(y0 - __bfloat162float(h0));
    lo[base + tid + 256] = __float2bfloat16(y1 - __bfloat162float(h1));
}

// ---------------- qkv split ----------------
__global__ void qkv_split_kernel(const float* __restrict__ qkv) {
    int idx = blockIdx.x * blockDim.x + threadIdx.x;
    if (idx >= MM * 1536) return;
    int row = idx / 1536;
    int col = idx - row * 1536;
    int b = row >> 10, s = row & 1023;
    float v = qkv[idx];
    if (col < 512) {
        int hd = col >> 6, d = col & 63;
        size_t o = ((size_t)(b*8 + hd) * 1024 + s) * 64 + d;
        __nv_bfloat16 h = __float2bfloat16(v);
        g_Qhi[o] = h; g_Qlo[o] = __float2bfloat16(v - __bfloat162float(h));
    } else if (col < 1024) {
        int c = col - 512;
        int hd = c >> 6, d = c & 63;
        size_t o = ((size_t)(b*8 + hd) * 1024 + s) * 64 + d;
        __nv_bfloat16 h = __float2bfloat16(v);
        g_Khi[o] = h; g_Klo[o] = __float2bfloat16(v - __bfloat162float(h));
    } else {
        int c = col - 1024;
        int hd = c >> 6, d = c & 63;
        size_t o = (size_t)(b*8 + hd) * 131072 + (size_t)d * 1024 + s;
        g_Vth[o] = __float2half(v);
    }
}

// ---------------- in-place fp16 softmax over rows of 1024 ----------------
__global__ void softmax_f16_kernel(__half* __restrict__ S) {
    size_t row = blockIdx.x;
    __half* p = S + row * 1024;
    int tid = threadIdx.x;   // 256 threads x 4 halves
    uint2 raw = ((const uint2*)p)[tid];
    __half2 h01 = *(__half2*)&raw.x;
    __half2 h23 = *(__half2*)&raw.y;
    float v0 = __low2float(h01), v1 = __high2float(h01);
    float v2 = __low2float(h23), v3 = __high2float(h23);
    float m = fmaxf(fmaxf(v0, v1), fmaxf(v2, v3));
    __shared__ float red[8];
    #pragma unroll
    for (int o = 16; o; o >>= 1) m = fmaxf(m, __shfl_xor_sync(0xffffffffu, m, o));
    if ((tid & 31) == 0) red[tid>>5] = m;
    __syncthreads();
    m = red[0];
    #pragma unroll
    for (int i = 1; i < 8; i++) m = fmaxf(m, red[i]);
    v0 = __expf(v0 - m); v1 = __expf(v1 - m);
    v2 = __expf(v2 - m); v3 = __expf(v3 - m);
    float sum = v0 + v1 + v2 + v3;
    #pragma unroll
    for (int o = 16; o; o >>= 1) sum += __shfl_xor_sync(0xffffffffu, sum, o);
    __syncthreads();
    if ((tid & 31) == 0) red[tid>>5] = sum;
    __syncthreads();
    sum = 0.f;
    #pragma unroll
    for (int i = 0; i < 8; i++) sum += red[i];
    float inv = 1.f / sum;
    __half2 o01 = __floats2half2_rn(v0 * inv, v1 * inv);
    __half2 o23 = __floats2half2_rn(v2 * inv, v3 * inv);
    uint2 outw;
    outw.x = *(uint32_t*)&o01;
    outw.y = *(uint32_t*)&o23;
    ((uint2*)p)[tid] = outw;
}

// ---------------- host orchestration ----------------
extern "C" void kernel_launch(void* const* d_in, const int* in_sizes, int n_in,
                              void* d_out, int out_size) {
    const int*   x          = (const int*)  d_in[0];
    const float* emb        = (const float*)d_in[1];
    const float* W0         = (const float*)d_in[2];
    const float* b0         = (const float*)d_in[3];
    const float* tau0       = (const float*)d_in[4];
    const float* g0         = (const float*)d_in[5];
    const float* be0        = (const float*)d_in[6];
    const float* W1         = (const float*)d_in[7];
    const float* b1         = (const float*)d_in[8];
    const float* tau1       = (const float*)d_in[9];
    const float* g1         = (const float*)d_in[10];
    const float* be1        = (const float*)d_in[11];
    const float* attn_in_w  = (const float*)d_in[12];
    const float* attn_in_b  = (const float*)d_in[13];
    const float* attn_out_w = (const float*)d_in[14];
    const float* attn_out_b = (const float*)d_in[15];
    const float* out_w      = (const float*)d_in[16];
    const float* out_b      = (const float*)d_in[17];
    const float* log_dt     = (const float*)d_in[18];
    float* out = (float*)d_out;

    float *I, *sbuf, *qkv;
    __nv_bfloat16 *Ahi, *Alo, *A2hi, *A2lo;
    __nv_bfloat16 *W0hi, *W0lo, *W1hi, *W1lo, *Wqhi, *Wqlo, *Wohi, *Wolo;
    __nv_bfloat16 *Qhi, *Qlo, *Khi, *Klo;
    __half *H2hi, *H2lo, *Bh, *Vth, *Sh;
    cudaGetSymbolAddress((void**)&I,      g_I);
    cudaGetSymbolAddress((void**)&sbuf,   g_s);
    cudaGetSymbolAddress((void**)&qkv,    g_qkv);
    cudaGetSymbolAddress((void**)&Ahi,    g_Ahi);
    cudaGetSymbolAddress((void**)&Alo,    g_Alo);
    cudaGetSymbolAddress((void**)&A2hi,   g_A2hi);
    cudaGetSymbolAddress((void**)&A2lo,   g_A2lo);
    cudaGetSymbolAddress((void**)&H2hi,   g_H2hi);
    cudaGetSymbolAddress((void**)&H2lo,   g_H2lo);
    cudaGetSymbolAddress((void**)&Bh,     g_Bh);
    cudaGetSymbolAddress((void**)&W0hi,   g_W0hi);
    cudaGetSymbolAddress((void**)&W0lo,   g_W0lo);
    cudaGetSymbolAddress((void**)&W1hi,   g_W1hi);
    cudaGetSymbolAddress((void**)&W1lo,   g_W1lo);
    cudaGetSymbolAddress((void**)&Wqhi,   g_Wqhi);
    cudaGetSymbolAddress((void**)&Wqlo,   g_Wqlo);
    cudaGetSymbolAddress((void**)&Wohi,   g_Wohi);
    cudaGetSymbolAddress((void**)&Wolo,   g_Wolo);
    cudaGetSymbolAddress((void**)&Qhi,    g_Qhi);
    cudaGetSymbolAddress((void**)&Qlo,    g_Qlo);
    cudaGetSymbolAddress((void**)&Khi,    g_Khi);
    cudaGetSymbolAddress((void**)&Klo,    g_Klo);
    cudaGetSymbolAddress((void**)&Vth,    g_Vth);
    cudaGetSymbolAddress((void**)&Sh,     g_Sh);

    cudaFuncSetAttribute(gemm_pair_mma,
                         cudaFuncAttributeMaxDynamicSharedMemorySize, GP_SMEM);
    cudaFuncSetAttribute(gemm_f16_mma,
                         cudaFuncAttributeMaxDynamicSharedMemorySize, GF_SMEM);

    // weight preprocessing
    convert_f16_kernel<<<(VV*HH + 255)/256, 256>>>(out_w, Bh, VV*HH);
    split_bf16_kernel<<<(HH*EE + 255)/256, 256>>>(W0, W0hi, W0lo, HH*EE);
    split_bf16_kernel<<<(HH*HH + 255)/256, 256>>>(W1, W1hi, W1lo, HH*HH);
    split_bf16_kernel<<<(3*HH*HH + 255)/256, 256>>>(attn_in_w, Wqhi, Wqlo, 3*HH*HH);
    split_bf16_kernel<<<(HH*HH + 255)/256, 256>>>(attn_out_w, Wohi, Wolo, HH*HH);

    // 1. embedding + pos-enc -> bf16 splits
    embed_pe_split<<<(MM*EE)/256, 256>>>(x, emb, Ahi, Alo);

    // 2. liquid layer 0 (bf16 3-term)
    gemm_pair_mma<<<dim3(4, 32, 1), 256, GP_SMEM>>>(
        Ahi, Alo, W0hi, W0lo, b0, I, nullptr, nullptr,
        EE, EE, EE, HH, HH, 1.f, 1, 0,0,0,0,0,0);
    liquid_scan_par<<<dim3(BB, 32), 512>>>(I, tau0, log_dt, sbuf);
    layernorm_split<<<MM, 256>>>(sbuf, g0, be0, Ahi, Alo);

    // 3. liquid layer 1
    gemm_pair_mma<<<dim3(4, 32, 1), 256, GP_SMEM>>>(
        Ahi, Alo, W1hi, W1lo, b1, I, nullptr, nullptr,
        HH, HH, HH, HH, HH, 1.f, 1, 0,0,0,0,0,0);
    liquid_scan_par<<<dim3(BB, 32), 512>>>(I, tau1, log_dt, sbuf);
    layernorm_split<<<MM, 256>>>(sbuf, g1, be1, Ahi, Alo);

    // 4. MHA: qkv projection (bf16 3-term)
    gemm_pair_mma<<<dim3(12, 32, 1), 256, GP_SMEM>>>(
        Ahi, Alo, Wqhi, Wqlo, attn_in_b, qkv, nullptr, nullptr,
        HH, HH, HH, 3*HH, 3*HH, 1.f, 1, 0,0,0,0,0,0);
    qkv_split_kernel<<<(MM*1536 + 255)/256, 256>>>(qkv);

    // scores = Q @ K^T / 8 (bf16 3-term, batched) -> fp16 scores buffer
    gemm_pair_mma<<<dim3(8, 8, 32), 256, GP_SMEM>>>(
        Qhi, Qlo, Khi, Klo, nullptr, nullptr, Sh, nullptr,
        64, 64, 64, 1024, 1024, 0.125f,
        32, 65536LL, 0, 65536LL, 0, 1LL<<20, 0);

    // in-place fp16 softmax -> P
    softmax_f16_kernel<<<32*1024, 256>>>(Sh);

    // AV = P @ Vt^T (fp16 single product) -> fused bf16 split into A2
    gemm_f16_mma<<<dim3(1, 8, 32), 256, GF_SMEM>>>(
        Sh, nullptr, Vth, nullptr, nullptr, A2hi, A2lo,
        1024, 1024, 1024, 512, 64, 1.f,
        8, 1LL<<20, 8LL<<20, 131072LL, 8LL*131072, 64LL, 524288LL);

    // out-projection (bf16 3-term) -> fused fp16 split into H2
    gemm_pair_mma<<<dim3(4, 32, 1), 256, GP_SMEM>>>(
        A2hi, A2lo, Wohi, Wolo, attn_out_b, nullptr, H2hi, H2lo,
        HH, HH, HH, HH, HH, 1.f, 1, 0,0,0,0,0,0);

    // 5. vocab projection (fp16 1-term)
    gemm_f16_mma<<<dim3(VV/128, MM/128, 1), 256, GF_SMEM>>>(
        H2hi, nullptr, Bh, out_b, out, nullptr, nullptr,
        HH, HH, HH, VV, VV, 1.f, 1, 0,0,0,0,0,0);
}

// round 10
// speedup vs baseline: 5.0137x; 1.0014x over previous
#include <cuda_runtime.h>
#include <cuda_bf16.h>
#include <cuda_fp16.h>
#include <cstdint>
#include <math.h>

#define BB 4
#define SS 1024
#define EE 512
#define HH 512
#define VV 32000
#define MM (BB*SS)      // 4096
#define NH 8
#define DH 64

// ---------------- scratch (static device memory; no allocations) ----------------
__device__ float g_I[MM*HH];
__device__ float g_s[MM*HH];
__device__ float g_qkv[MM*3*HH];
__device__ __nv_bfloat16 g_Ahi[MM*HH],  g_Alo[MM*HH];
__device__ __nv_bfloat16 g_A2hi[MM*HH], g_A2lo[MM*HH];
__device__ __half        g_H2hi[MM*HH], g_H2lo[MM*HH];   // h2 fp16 (vocab A)
__device__ __nv_bfloat16 g_W0hi[HH*EE],  g_W0lo[HH*EE];
__device__ __nv_bfloat16 g_W1hi[HH*HH],  g_W1lo[HH*HH];
__device__ __nv_bfloat16 g_Wqhi[3*HH*HH], g_Wqlo[3*HH*HH];
__device__ __nv_bfloat16 g_Wohi[HH*HH],  g_Wolo[HH*HH];
__device__ __half        g_Bh[(size_t)VV*HH];            // vocab weights fp16
__device__ __nv_bfloat16 g_Qhi[32*1024*64], g_Qlo[32*1024*64];
__device__ __nv_bfloat16 g_Khi[32*1024*64], g_Klo[32*1024*64];
__device__ __half        g_Vth[32*128*1024];             // [bh][d pad128][k] fp16
__device__ __half        g_Sh[(size_t)32*1024*1024];     // scores/P fp16 (in-place)

__device__ __forceinline__ uint32_t smem_u32(const void* p) {
    uint32_t a;
    asm("{ .reg .u64 t; cvta.to.shared.u64 t, %1; cvt.u32.u64 %0, t; }" : "=r"(a) : "l"(p));
    return a;
}
__device__ __forceinline__ void cp_async16(uint32_t dst, const void* src) {
    asm volatile("cp.async.cg.shared.global [%0], [%1], 16;" :: "r"(dst), "l"(src));
}
__device__ __forceinline__ void ldsm_x4(uint32_t& r0, uint32_t& r1, uint32_t& r2, uint32_t& r3,
                                        uint32_t addr) {
    asm volatile("ldmatrix.sync.aligned.m8n8.x4.shared.b16 {%0,%1,%2,%3}, [%4];"
                 : "=r"(r0), "=r"(r1), "=r"(r2), "=r"(r3) : "r"(addr));
}
__device__ __forceinline__ void mma_bf16(float* c, const uint32_t* a, const uint32_t* b) {
    asm volatile("mma.sync.aligned.m16n8k16.row.col.f32.bf16.bf16.f32 "
                 "{%0,%1,%2,%3}, {%4,%5,%6,%7}, {%8,%9}, {%0,%1,%2,%3};"
                 : "+f"(c[0]), "+f"(c[1]), "+f"(c[2]), "+f"(c[3])
                 : "r"(a[0]), "r"(a[1]), "r"(a[2]), "r"(a[3]), "r"(b[0]), "r"(b[1]));
}
__device__ __forceinline__ void mma_f16(float* c, const uint32_t* a, const uint32_t* b) {
    asm volatile("mma.sync.aligned.m16n8k16.row.col.f32.f16.f16.f32 "
                 "{%0,%1,%2,%3}, {%4,%5,%6,%7}, {%8,%9}, {%0,%1,%2,%3};"
                 : "+f"(c[0]), "+f"(c[1]), "+f"(c[2]), "+f"(c[3])
                 : "r"(a[0]), "r"(a[1]), "r"(a[2]), "r"(a[3]), "r"(b[0]), "r"(b[1]));
}

// ---------------- embed + positional encoding -> bf16 hi/lo ----------------
__global__ void embed_pe_split(const int* __restrict__ x, const float* __restrict__ emb,
                               __nv_bfloat16* __restrict__ hi, __nv_bfloat16* __restrict__ lo) {
    int idx = blockIdx.x * blockDim.x + threadIdx.x;
    if (idx >= MM*EE) return;
    int m = idx >> 9;
    int e = idx & 511;
    int s = m & (SS - 1);
    int tok = x[m];
    int i2 = e & ~1;
    float freq = expf((float)i2 * (-9.210340371976184f / 512.0f));
    float ang = (float)s * freq;
    float pe = (e & 1) ? cosf(ang) : sinf(ang);
    float v = emb[(size_t)tok * EE + e] + pe;
    __nv_bfloat16 h = __float2bfloat16(v);
    hi[idx] = h;
    lo[idx] = __float2bfloat16(v - __bfloat162float(h));
}

__global__ void split_bf16_kernel(const float* __restrict__ in, __nv_bfloat16* __restrict__ hi,
                                  __nv_bfloat16* __restrict__ lo, int n) {
    int i = blockIdx.x * blockDim.x + threadIdx.x;
    if (i >= n) return;
    float x = in[i];
    __nv_bfloat16 h = __float2bfloat16(x);
    hi[i] = h;
    lo[i] = __float2bfloat16(x - __bfloat162float(h));
}

__global__ void convert_f16_kernel(const float* __restrict__ in, __half* __restrict__ out, int n) {
    int i = blockIdx.x * blockDim.x + threadIdx.x;
    if (i < n) out[i] = __float2half(in[i]);
}

// ============== bf16 3-term paired-operand NT GEMM ==============
#define SPAD 40
#define TILE_E (128*SPAD)
#define GP_SMEM (2*4*TILE_E*2)    // 81920 bytes

__global__ __launch_bounds__(256, 2) void gemm_pair_mma(
    const __nv_bfloat16* __restrict__ Ahi_, const __nv_bfloat16* __restrict__ Alo_,
    const __nv_bfloat16* __restrict__ Bhi_, const __nv_bfloat16* __restrict__ Blo_,
    const float* __restrict__ bias, float* __restrict__ C_,
    __half* __restrict__ Fhi_, __half* __restrict__ Flo_,
    int K, int lda, int ldb, int ldc, int nValid, float scale,
    int zmod, long long sA1, long long sA2, long long sB1, long long sB2,
    long long sC1, long long sC2)
{
    extern __shared__ __align__(16) __nv_bfloat16 sm[];
    const uint32_t smb = smem_u32(sm);

    const int tid = threadIdx.x;
    const int lane = tid & 31;
    const int wid = tid >> 5;
    const int warp_m = wid >> 2;
    const int warp_n = wid & 3;
    const int bm = blockIdx.y * 128;
    const int bn = blockIdx.x * 128;

    const int z = blockIdx.z;
    const int z1 = z % zmod, z2 = z / zmod;
    const long long offA = (long long)z1 * sA1 + (long long)z2 * sA2;
    const long long offB = (long long)z1 * sB1 + (long long)z2 * sB2;
    const long long offC = (long long)z1 * sC1 + (long long)z2 * sC2;

    const __nv_bfloat16* pA[2] = { Ahi_ + offA + (size_t)bm * lda,
                                   Alo_ + offA + (size_t)bm * lda };
    const __nv_bfloat16* pB[2] = { Bhi_ + offB + (size_t)bn * ldb,
                                   Blo_ + offB + (size_t)bn * ldb };

    float acc[4][4][4];
    #pragma unroll
    for (int i = 0; i < 4; i++)
        #pragma unroll
        for (int j = 0; j < 4; j++)
            #pragma unroll
            for (int r = 0; r < 4; r++) acc[i][j][r] = 0.f;

    const int lrow = tid >> 2;
    const int lcol = (tid & 3) * 8;
    const int nstages = K >> 5;

    auto prefetch = [&](int s) {
        const int gk = s * 32;
        const uint32_t base = smb + (uint32_t)((s & 1) * 4 * TILE_E) * 2;
        #pragma unroll
        for (int t = 0; t < 4; t++) {
            const __nv_bfloat16* src = (t < 2 ? pA[t] : pB[t-2]) + gk + lcol;
            const int ld = (t < 2) ? lda : ldb;
            #pragma unroll
            for (int c = 0; c < 2; c++) {
                int row = lrow + c * 64;
                cp_async16(base + (uint32_t)(t * TILE_E + row * SPAD + lcol) * 2,
                           src + (size_t)row * ld);
            }
        }
    };

    prefetch(0);
    asm volatile("cp.async.commit_group;");

    for (int s = 0; s < nstages; s++) {
        if (s < nstages - 1) {
            prefetch(s + 1);
            asm volatile("cp.async.commit_group;");
            asm volatile("cp.async.wait_group 1;");
        } else {
            asm volatile("cp.async.wait_group 0;");
        }
        __syncthreads();

        const uint32_t stg = smb + (uint32_t)((s & 1) * 4 * TILE_E) * 2;
        const uint32_t tAhi = stg;
        const uint32_t tAlo = stg + TILE_E * 2;
        const uint32_t tBhi = stg + 2 * TILE_E * 2;
        const uint32_t tBlo = stg + 3 * TILE_E * 2;
        const int q  = lane >> 3;
        const int rr = lane & 7;

        #pragma unroll
        for (int ko = 0; ko < 32; ko += 16) {
            const int arow = warp_m * 64 + (q & 1) * 8 + rr;
            const int acol = ko + (q >> 1) * 8;
            const int brow = warp_n * 32 + (q >> 1) * 8 + rr;
            const int bcol = ko + (q & 1) * 8;

            uint32_t aH[4][4];
            #pragma unroll
            for (int i = 0; i < 4; i++)
                ldsm_x4(aH[i][0], aH[i][1], aH[i][2], aH[i][3],
                        tAhi + (uint32_t)((arow + i * 16) * SPAD + acol) * 2);
            uint32_t bH[4][2], bL[4][2];
            #pragma unroll
            for (int j = 0; j < 2; j++) {
                ldsm_x4(bH[2*j][0], bH[2*j][1], bH[2*j+1][0], bH[2*j+1][1],
                        tBhi + (uint32_t)((brow + j * 16) * SPAD + bcol) * 2);
                ldsm_x4(bL[2*j][0], bL[2*j][1], bL[2*j+1][0], bL[2*j+1][1],
                        tBlo + (uint32_t)((brow + j * 16) * SPAD + bcol) * 2);
            }
            #pragma unroll
            for (int i = 0; i < 4; i++)
                #pragma unroll
                for (int j = 0; j < 4; j++)
                    mma_bf16(acc[i][j], aH[i], bH[j]);
            #pragma unroll
            for (int i = 0; i < 4; i++)
                #pragma unroll
                for (int j = 0; j < 4; j++)
                    mma_bf16(acc[i][j], aH[i], bL[j]);
            uint32_t aL[4][4];
            #pragma unroll
            for (int i = 0; i < 4; i++)
                ldsm_x4(aL[i][0], aL[i][1], aL[i][2], aL[i][3],
                        tAlo + (uint32_t)((arow + i * 16) * SPAD + acol) * 2);
            #pragma unroll
            for (int i = 0; i < 4; i++)
                #pragma unroll
                for (int j = 0; j < 4; j++)
                    mma_bf16(acc[i][j], aL[i], bH[j]);
        }
        __syncthreads();
    }

    // epilogue: fp32, fp16 hi/lo split, or single fp16
    const int gr = lane >> 2;
    const int gc = (lane & 3) * 2;
    float* C = C_ ? C_ + offC : nullptr;
    __half* Fhi = Fhi_ ? Fhi_ + offC : nullptr;
    __half* Flo = Flo_ ? Flo_ + offC : nullptr;

    #pragma unroll
    for (int j = 0; j < 4; j++) {
        int col = bn + warp_n * 32 + j * 8 + gc;
        if (col >= nValid) continue;
        float2 bv = make_float2(0.f, 0.f);
        if (bias) bv = *(const float2*)(bias + col);
        #pragma unroll
        for (int i = 0; i < 4; i++) {
            int row0 = bm + warp_m * 64 + i * 16 + gr;
            float v00 = acc[i][j][0]*scale + bv.x, v01 = acc[i][j][1]*scale + bv.y;
            float v10 = acc[i][j][2]*scale + bv.x, v11 = acc[i][j][3]*scale + bv.y;
            size_t o0 = (size_t)row0 * ldc + col;
            size_t o1 = (size_t)(row0 + 8) * ldc + col;
            if (Fhi) {
                __half h;
                if (Flo) {
                    h = __float2half(v00); Fhi[o0]   = h; Flo[o0]   = __float2half(v00 - __half2float(h));
                    h = __float2half(v01); Fhi[o0+1] = h; Flo[o0+1] = __float2half(v01 - __half2float(h));
                    h = __float2half(v10); Fhi[o1]   = h; Flo[o1]   = __float2half(v10 - __half2float(h));
                    h = __float2half(v11); Fhi[o1+1] = h; Flo[o1+1] = __float2half(v11 - __half2float(h));
                } else {
                    *(__half2*)(Fhi + o0) = __floats2half2_rn(v00, v01);
                    *(__half2*)(Fhi + o1) = __floats2half2_rn(v10, v11);
                }
            } else {
                *(float2*)(C + o0) = make_float2(v00, v01);
                *(float2*)(C + o1) = make_float2(v10, v11);
            }
        }
    }
}

// ============== fp16 NT GEMM, 1- or 2-term A ==============
#define GF_SMEM (2*3*TILE_E*2)    // 61440 bytes

__global__ __launch_bounds__(256, 2) void gemm_f16_mma(
    const __half* __restrict__ Ahi_, const __half* __restrict__ Alo_,
    const __half* __restrict__ B_,
    const float* __restrict__ bias, float* __restrict__ C_,
    __nv_bfloat16* __restrict__ Chi_, __nv_bfloat16* __restrict__ Clo_,
    int K, int lda, int ldb, int ldc, int nValid, float scale,
    int zmod, long long sA1, long long sA2, long long sB1, long long sB2,
    long long sC1, long long sC2)
{
    extern __shared__ __align__(16) __half smh[];
    const uint32_t smb = smem_u32(smh);

    const int tid = threadIdx.x;
    const int lane = tid & 31;
    const int wid = tid >> 5;
    const int warp_m = wid >> 2;
    const int warp_n = wid & 3;
    const int bm = blockIdx.y * 128;
    const int bn = blockIdx.x * 128;
    const bool two = (Alo_ != nullptr);

    const int z = blockIdx.z;
    const int z1 = z % zmod, z2 = z / zmod;
    const long long offA = (long long)z1 * sA1 + (long long)z2 * sA2;
    const long long offB = (long long)z1 * sB1 + (long long)z2 * sB2;
    const long long offC = (long long)z1 * sC1 + (long long)z2 * sC2;

    const __half* pT[3] = { Ahi_ + offA + (size_t)bm * lda,
                            two ? (Alo_ + offA + (size_t)bm * lda) : nullptr,
                            B_   + offB + (size_t)bn * ldb };

    float acc[4][4][4];
    #pragma unroll
    for (int i = 0; i < 4; i++)
        #pragma unroll
        for (int j = 0; j < 4; j++)
            #pragma unroll
            for (int r = 0; r < 4; r++) acc[i][j][r] = 0.f;

    const int lrow = tid >> 2;
    const int lcol = (tid & 3) * 8;
    const int nstages = K >> 5;

    auto prefetch = [&](int s) {
        const int gk = s * 32;
        const uint32_t base = smb + (uint32_t)((s & 1) * 3 * TILE_E) * 2;
        #pragma unroll
        for (int t = 0; t < 3; t++) {
            if (t == 1 && !two) continue;
            const __half* src = pT[t] + gk + lcol;
            const int ld = (t < 2) ? lda : ldb;
            #pragma unroll
            for (int c = 0; c < 2; c++) {
                int row = lrow + c * 64;
                cp_async16(base + (uint32_t)(t * TILE_E + row * SPAD + lcol) * 2,
                           src + (size_t)row * ld);
            }
        }
    };

    prefetch(0);
    asm volatile("cp.async.commit_group;");

    for (int s = 0; s < nstages; s++) {
        if (s < nstages - 1) {
            prefetch(s + 1);
            asm volatile("cp.async.commit_group;");
            asm volatile("cp.async.wait_group 1;");
        } else {
            asm volatile("cp.async.wait_group 0;");
        }
        __syncthreads();

        const uint32_t stg = smb + (uint32_t)((s & 1) * 3 * TILE_E) * 2;
        const uint32_t tAhi = stg;
        const uint32_t tAlo = stg + TILE_E * 2;
        const uint32_t tB   = stg + 2 * TILE_E * 2;
        const int q  = lane >> 3;
        const int rr = lane & 7;

        #pragma unroll
        for (int ko = 0; ko < 32; ko += 16) {
            const int arow = warp_m * 64 + (q & 1) * 8 + rr;
            const int acol = ko + (q >> 1) * 8;
            const int brow = warp_n * 32 + (q >> 1) * 8 + rr;
            const int bcol = ko + (q & 1) * 8;

            uint32_t b[4][2];
            #pragma unroll
            for (int j = 0; j < 2; j++)
                ldsm_x4(b[2*j][0], b[2*j][1], b[2*j+1][0], b[2*j+1][1],
                        tB + (uint32_t)((brow + j * 16) * SPAD + bcol) * 2);
            uint32_t aH[4][4];
            #pragma unroll
            for (int i = 0; i < 4; i++)
                ldsm_x4(aH[i][0], aH[i][1], aH[i][2], aH[i][3],
                        tAhi + (uint32_t)((arow + i * 16) * SPAD + acol) * 2);
            #pragma unroll
            for (int i = 0; i < 4; i++)
                #pragma unroll
                for (int j = 0; j < 4; j++)
                    mma_f16(acc[i][j], aH[i], b[j]);
            if (two) {
                uint32_t aL[4][4];
                #pragma unroll
                for (int i = 0; i < 4; i++)
                    ldsm_x4(aL[i][0], aL[i][1], aL[i][2], aL[i][3],
                            tAlo + (uint32_t)((arow + i * 16) * SPAD + acol) * 2);
                #pragma unroll
                for (int i = 0; i < 4; i++)
                    #pragma unroll
                    for (int j = 0; j < 4; j++)
                        mma_f16(acc[i][j], aL[i], b[j]);
            }
        }
        __syncthreads();
    }

    const int gr = lane >> 2;
    const int gc = (lane & 3) * 2;
    float* C = C_ ? C_ + offC : nullptr;
    __nv_bfloat16* Chi = Chi_ ? Chi_ + offC : nullptr;
    __nv_bfloat16* Clo = Clo_ ? Clo_ + offC : nullptr;

    #pragma unroll
    for (int j = 0; j < 4; j++) {
        int col = bn + warp_n * 32 + j * 8 + gc;
        if (col >= nValid) continue;
        float2 bv = make_float2(0.f, 0.f);
        if (bias) bv = *(const float2*)(bias + col);
        #pragma unroll
        for (int i = 0; i < 4; i++) {
            int row0 = bm + warp_m * 64 + i * 16 + gr;
            float v00 = acc[i][j][0]*scale + bv.x, v01 = acc[i][j][1]*scale + bv.y;
            float v10 = acc[i][j][2]*scale + bv.x, v11 = acc[i][j][3]*scale + bv.y;
            size_t o0 = (size_t)row0 * ldc + col;
            size_t o1 = (size_t)(row0 + 8) * ldc + col;
            if (Chi) {
                __nv_bfloat16 h;
                h = __float2bfloat16(v00); Chi[o0]   = h; Clo[o0]   = __float2bfloat16(v00 - __bfloat162float(h));
                h = __float2bfloat16(v01); Chi[o0+1] = h; Clo[o0+1] = __float2bfloat16(v01 - __bfloat162float(h));
                h = __float2bfloat16(v10); Chi[o1]   = h; Clo[o1]   = __float2bfloat16(v10 - __bfloat162float(h));
                h = __float2bfloat16(v11); Chi[o1+1] = h; Clo[o1+1] = __float2bfloat16(v11 - __bfloat162float(h));
            } else {
                *(float2*)(C + o0) = make_float2(v00, v01);
                *(float2*)(C + o1) = make_float2(v10, v11);
            }
        }
    }
}

// ---------------- parallel liquid scan (exact affine chunk decomposition) ----------------
__global__ __launch_bounds__(512) void liquid_scan_par(
    const float* __restrict__ I, const float* __restrict__ tau,
    const float* __restrict__ log_dt, float* __restrict__ out) {
    const int b = blockIdx.x;
    const int lg = blockIdx.y;
    const int lane16 = threadIdx.x & 15;
    const int chunk  = threadIdx.x >> 4;
    const int o = lg * 16 + lane16;
    const float dt = expf(log_dt[0]);
    const float r = dt / tau[o];
    const float a = 1.f - r;
    const float* Ib = I + (size_t)b * SS * HH + o;
    const int t0 = chunk * 32;

    float Iv[32];
    #pragma unroll
    for (int i = 0; i < 32; i++) Iv[i] = Ib[(size_t)(t0 + i) * HH];

    float u = 0.f, s = 0.f;
    #pragma unroll
    for (int i = 0; i < 32; i++) {
        float sn = s + r * (u - s);
        u = u + r * (Iv[i] - u);
        s = sn;
    }
    __shared__ float2 dloc[32][16];
    __shared__ float2 st[32][16];
    dloc[chunk][lane16] = make_float2(u, s);
    __syncthreads();

    if (chunk == 0) {
        float a2 = a*a, a4 = a2*a2, a8 = a4*a4, a16 = a8*a8;
        float a32v = a16*a16;
        float a31 = a16*a8*a4*a2*a;
        float c32 = 32.f * r * a31;
        float2 x = make_float2(0.f, 0.f);
        #pragma unroll
        for (int c = 0; c < 32; c++) {
            st[c][lane16] = x;
            float2 d = dloc[c][lane16];
            float nu = a32v * x.x + d.x;
            float ns = c32 * x.x + a32v * x.y + d.y;
            x = make_float2(nu, ns);
        }
    }
    __syncthreads();

    float2 x0 = st[chunk][lane16];
    u = x0.x; s = x0.y;
    float* Ob = out + (size_t)b * SS * HH + o;
    #pragma unroll
    for (int i = 0; i < 32; i++) {
        float sn = s + r * (u - s);
        u = u + r * (Iv[i] - u);
        s = sn;
        Ob[(size_t)(t0 + i) * HH] = tanhf(s);
    }
}

// ---------------- layernorm -> bf16 hi/lo ----------------
__global__ void layernorm_split(const float* __restrict__ in, const float* __restrict__ g,
                                const float* __restrict__ be,
                                __nv_bfloat16* __restrict__ hi, __nv_bfloat16* __restrict__ lo) {
    int row = blockIdx.x;
    int tid = threadIdx.x;
    const float* p = in + (size_t)row * HH;
    float a = p[tid], b = p[tid + 256];
    float sum = a + b, sq = a*a + b*b;
    __shared__ float s1[8], s2[8];
    #pragma unroll
    for (int o = 16; o; o >>= 1) {
        sum += __shfl_xor_sync(0xffffffffu, sum, o);
        sq  += __shfl_xor_sync(0xffffffffu, sq,  o);
    }
    if ((tid & 31) == 0) { s1[tid>>5] = sum; s2[tid>>5] = sq; }
    __syncthreads();
    sum = 0.f; sq = 0.f;
    #pragma unroll
    for (int i = 0; i < 8; i++) { sum += s1[i]; sq += s2[i]; }
    float mean = sum * (1.f/512.f);
    float var  = sq * (1.f/512.f) - mean*mean;
    float inv = rsqrtf(var + 1e-5f);
    float y0 = (a - mean) * inv * g[tid]       + be[tid];
    float y1 = (b - mean) * inv * g[tid + 256] + be[tid + 256];
    size_t base = (size_t)row * HH;
    __nv_bfloat16 h0 = __float2bfloat16(y0);
    __nv_bfloat16 h1 = __float2bfloat16(y1);
    hi[base + tid]       = h0;
    hi[base + tid + 256] = h1;
    lo[base + tid]       = __float2bfloat16(y0 - __bfloat162float(h0));
    lo[base + tid + 256] = __float2bfloat16(y1 - __bfloat162float(h1));
}

// ---------------- qkv split ----------------
__global__ void qkv_split_kernel(const float* __restrict__ qkv) {
    int idx = blockIdx.x * blockDim.x + threadIdx.x;
    if (idx >= MM * 1536) return;
    int row = idx / 1536;
    int col = idx - row * 1536;
    int b = row >> 10, s = row & 1023;
    float v = qkv[idx];
    if (col < 512) {
        int hd = col >> 6, d = col & 63;
        size_t o = ((size_t)(b*8 + hd) * 1024 + s) * 64 + d;
        __nv_bfloat16 h = __float2bfloat16(v);
        g_Qhi[o] = h; g_Qlo[o] = __float2bfloat16(v - __bfloat162float(h));
    } else if (col < 1024) {
        int c = col - 512;
        int hd = c >> 6, d = c & 63;
        size_t o = ((size_t)(b*8 + hd) * 1024 + s) * 64 + d;
        __nv_bfloat16 h = __float2bfloat16(v);
        g_Khi[o] = h; g_Klo[o] = __float2bfloat16(v - __bfloat162float(h));
    } else {
        int c = col - 1024;
        int hd = c >> 6, d = c & 63;
        size_t o = (size_t)(b*8 + hd) * 131072 + (size_t)d * 1024 + s;
        g_Vth[o] = __float2half(v);
    }
}

// ---------------- in-place fp16 softmax over rows of 1024 ----------------
__global__ void softmax_f16_kernel(__half* __restrict__ S) {
    size_t row = blockIdx.x;
    __half* p = S + row * 1024;
    int tid = threadIdx.x;   // 256 threads x 4 halves
    uint2 raw = ((const uint2*)p)[tid];
    __half2 h01 = *(__half2*)&raw.x;
    __half2 h23 = *(__half2*)&raw.y;
    float v0 = __low2float(h01), v1 = __high2float(h01);
    float v2 = __low2float(h23), v3 = __high2float(h23);
    float m = fmaxf(fmaxf(v0, v1), fmaxf(v2, v3));
    __shared__ float red[8];
    #pragma unroll
    for (int o = 16; o; o >>= 1) m = fmaxf(m, __shfl_xor_sync(0xffffffffu, m, o));
    if ((tid & 31) == 0) red[tid>>5] = m;
    __syncthreads();
    m = red[0];
    #pragma unroll
    for (int i = 1; i < 8; i++) m = fmaxf(m, red[i]);
    v0 = __expf(v0 - m); v1 = __expf(v1 - m);
    v2 = __expf(v2 - m); v3 = __expf(v3 - m);
    float sum = v0 + v1 + v2 + v3;
    #pragma unroll
    for (int o = 16; o; o >>= 1) sum += __shfl_xor_sync(0xffffffffu, sum, o);
    __syncthreads();
    if ((tid & 31) == 0) red[tid>>5] = sum;
    __syncthreads();
    sum = 0.f;
    #pragma unroll
    for (int i = 0; i < 8; i++) sum += red[i];
    float inv = 1.f / sum;
    __half2 o01 = __floats2half2_rn(v0 * inv, v1 * inv);
    __half2 o23 = __floats2half2_rn(v2 * inv, v3 * inv);
    uint2 outw;
    outw.x = *(uint32_t*)&o01;
    outw.y = *(uint32_t*)&o23;
    ((uint2*)p)[tid] = outw;
}

// ---------------- host orchestration ----------------
extern "C" void kernel_launch(void* const* d_in, const int* in_sizes, int n_in,
                              void* d_out, int out_size) {
    const int*   x          = (const int*)  d_in[0];
    const float* emb        = (const float*)d_in[1];
    const float* W0         = (const float*)d_in[2];
    const float* b0         = (const float*)d_in[3];
    const float* tau0       = (const float*)d_in[4];
    const float* g0         = (const float*)d_in[5];
    const float* be0        = (const float*)d_in[6];
    const float* W1         = (const float*)d_in[7];
    const float* b1         = (const float*)d_in[8];
    const float* tau1       = (const float*)d_in[9];
    const float* g1         = (const float*)d_in[10];
    const float* be1        = (const float*)d_in[11];
    const float* attn_in_w  = (const float*)d_in[12];
    const float* attn_in_b  = (const float*)d_in[13];
    const float* attn_out_w = (const float*)d_in[14];
    const float* attn_out_b = (const float*)d_in[15];
    const float* out_w      = (const float*)d_in[16];
    const float* out_b      = (const float*)d_in[17];
    const float* log_dt     = (const float*)d_in[18];
    float* out = (float*)d_out;

    float *I, *sbuf, *qkv;
    __nv_bfloat16 *Ahi, *Alo, *A2hi, *A2lo;
    __nv_bfloat16 *W0hi, *W0lo, *W1hi, *W1lo, *Wqhi, *Wqlo, *Wohi, *Wolo;
    __nv_bfloat16 *Qhi, *Qlo, *Khi, *Klo;
    __half *H2hi, *H2lo, *Bh, *Vth, *Sh;
    cudaGetSymbolAddress((void**)&I,      g_I);
    cudaGetSymbolAddress((void**)&sbuf,   g_s);
    cudaGetSymbolAddress((void**)&qkv,    g_qkv);
    cudaGetSymbolAddress((void**)&Ahi,    g_Ahi);
    cudaGetSymbolAddress((void**)&Alo,    g_Alo);
    cudaGetSymbolAddress((void**)&A2hi,   g_A2hi);
    cudaGetSymbolAddress((void**)&A2lo,   g_A2lo);
    cudaGetSymbolAddress((void**)&H2hi,   g_H2hi);
    cudaGetSymbolAddress((void**)&H2lo,   g_H2lo);
    cudaGetSymbolAddress((void**)&Bh,     g_Bh);
    cudaGetSymbolAddress((void**)&W0hi,   g_W0hi);
    cudaGetSymbolAddress((void**)&W0lo,   g_W0lo);
    cudaGetSymbolAddress((void**)&W1hi,   g_W1hi);
    cudaGetSymbolAddress((void**)&W1lo,   g_W1lo);
    cudaGetSymbolAddress((void**)&Wqhi,   g_Wqhi);
    cudaGetSymbolAddress((void**)&Wqlo,   g_Wqlo);
    cudaGetSymbolAddress((void**)&Wohi,   g_Wohi);
    cudaGetSymbolAddress((void**)&Wolo,   g_Wolo);
    cudaGetSymbolAddress((void**)&Qhi,    g_Qhi);
    cudaGetSymbolAddress((void**)&Qlo,    g_Qlo);
    cudaGetSymbolAddress((void**)&Khi,    g_Khi);
    cudaGetSymbolAddress((void**)&Klo,    g_Klo);
    cudaGetSymbolAddress((void**)&Vth,    g_Vth);
    cudaGetSymbolAddress((void**)&Sh,     g_Sh);

    cudaFuncSetAttribute(gemm_pair_mma,
                         cudaFuncAttributeMaxDynamicSharedMemorySize, GP_SMEM);
    cudaFuncSetAttribute(gemm_f16_mma,
                         cudaFuncAttributeMaxDynamicSharedMemorySize, GF_SMEM);

    // weight preprocessing
    convert_f16_kernel<<<(VV*HH + 255)/256, 256>>>(out_w, Bh, VV*HH);
    split_bf16_kernel<<<(HH*EE + 255)/256, 256>>>(W0, W0hi, W0lo, HH*EE);
    split_bf16_kernel<<<(HH*HH + 255)/256, 256>>>(W1, W1hi, W1lo, HH*HH);
    split_bf16_kernel<<<(3*HH*HH + 255)/256, 256>>>(attn_in_w, Wqhi, Wqlo, 3*HH*HH);
    split_bf16_kernel<<<(HH*HH + 255)/256, 256>>>(attn_out_w, Wohi, Wolo, HH*HH);

    // 1. embedding + pos-enc -> bf16 splits
    embed_pe_split<<<(MM*EE)/256, 256>>>(x, emb, Ahi, Alo);

    // 2. liquid layer 0 (bf16 3-term)
    gemm_pair_mma<<<dim3(4, 32, 1), 256, GP_SMEM>>>(
        Ahi, Alo, W0hi, W0lo, b0, I, nullptr, nullptr,
        EE, EE, EE, HH, HH, 1.f, 1, 0,0,0,0,0,0);
    liquid_scan_par<<<dim3(BB, 32), 512>>>(I, tau0, log_dt, sbuf);
    layernorm_split<<<MM, 256>>>(sbuf, g0, be0, Ahi, Alo);

    // 3. liquid layer 1
    gemm_pair_mma<<<dim3(4, 32, 1), 256, GP_SMEM>>>(
        Ahi, Alo, W1hi, W1lo, b1, I, nullptr, nullptr,
        HH, HH, HH, HH, HH, 1.f, 1, 0,0,0,0,0,0);
    liquid_scan_par<<<dim3(BB, 32), 512>>>(I, tau1, log_dt, sbuf);
    layernorm_split<<<MM, 256>>>(sbuf, g1, be1, Ahi, Alo);

    // 4. MHA: qkv projection (bf16 3-term)
    gemm_pair_mma<<<dim3(12, 32, 1), 256, GP_SMEM>>>(
        Ahi, Alo, Wqhi, Wqlo, attn_in_b, qkv, nullptr, nullptr,
        HH, HH, HH, 3*HH, 3*HH, 1.f, 1, 0,0,0,0,0,0);
    qkv_split_kernel<<<(MM*1536 + 255)/256, 256>>>(qkv);

    // scores = Q @ K^T / 8 (bf16 3-term, batched) -> fp16 scores buffer
    gemm_pair_mma<<<dim3(8, 8, 32), 256, GP_SMEM>>>(
        Qhi, Qlo, Khi, Klo, nullptr, nullptr, Sh, nullptr,
        64, 64, 64, 1024, 1024, 0.125f,
        32, 65536LL, 0, 65536LL, 0, 1LL<<20, 0);

    // in-place fp16 softmax -> P
    softmax_f16_kernel<<<32*1024, 256>>>(Sh);

    // AV = P @ Vt^T (fp16 single product) -> fused bf16 split into A2
    gemm_f16_mma<<<dim3(1, 8, 32), 256, GF_SMEM>>>(
        Sh, nullptr, Vth, nullptr, nullptr, A2hi, A2lo,
        1024, 1024, 1024, 512, 64, 1.f,
        8, 1LL<<20, 8LL<<20, 131072LL, 8LL*131072, 64LL, 524288LL);

    // out-projection (bf16 3-term) -> fused fp16 split into H2
    gemm_pair_mma<<<dim3(4, 32, 1), 256, GP_SMEM>>>(
        A2hi, A2lo, Wohi, Wolo, attn_out_b, nullptr, H2hi, H2lo,
        HH, HH, HH, HH, HH, 1.f, 1, 0,0,0,0,0,0);

    // 5. vocab projection (fp16 1-term)
    gemm_f16_mma<<<dim3(VV/128, MM/128, 1), 256, GF_SMEM>>>(
        H2hi, nullptr, Bh, out_b, out, nullptr, nullptr,
        HH, HH, HH, VV, VV, 1.f, 1, 0,0,0,0,0,0);
}